// round 1
// baseline (speedup 1.0000x reference)
#include <cuda_runtime.h>

// Problem constants
constexpr int BATCH   = 2;
constexpr int SEQ     = 2048;
constexpr int HIDDEN  = 2048;
constexpr int HEADS   = 16;
constexpr int HEAD_DIM = 128;   // HIDDEN / HEADS

// ---------------------------------------------------------------------------
// Scratch (device globals — no allocations allowed in kernel_launch)
// ---------------------------------------------------------------------------
__device__ float g_q[BATCH * HEADS * SEQ * HEAD_DIM];      // [b][h][s][d]  32 MB
__device__ float g_k[BATCH * HEADS * SEQ * HEAD_DIM];      // [b][h][s][d]  32 MB
__device__ float g_v[BATCH * HEADS * SEQ * HEAD_DIM];      // [b][h][s][d]  32 MB
__device__ float g_scores[(size_t)BATCH * HEADS * SEQ * SEQ]; // [bh][q][k] 512 MB
__device__ float g_attn[BATCH * SEQ * HIDDEN];             // [b][s][h*D+d] 32 MB

// ---------------------------------------------------------------------------
// Tiled GEMM: 128x128 block tile, BK=8, 8x8 per thread, 256 threads.
// MODE 0: QKV projection   C = A @ W^T + bias  -> scatter to [b][h][s][d]
// MODE 1: scores           C = Q @ K^T * scale -> [bh][q][k]
// MODE 2: PV (NN)          C = P @ V           -> scatter to [b][s][h*D+d]
// MODE 3: out projection   C = A @ Wo^T + bo   -> [m][n] row-major
// A is always row-major with K contiguous.
// B: modes 0/1/3 are NT (rows = n, K contiguous); mode 2 is NN (rows = k).
// ---------------------------------------------------------------------------
constexpr int BM = 128, BN = 128, BK = 8;

template <int MODE>
__global__ __launch_bounds__(256)
void gemm_kernel(const float* __restrict__ A,
                 const float* __restrict__ B,
                 float* __restrict__ C,
                 const float* __restrict__ bias,
                 int K, int lda, int ldb,
                 long aStrideZ, long bStrideZ,
                 float alpha)
{
    __shared__ float As[BK][BM + 4];
    __shared__ float Bs[BK][BN + 4];

    const int tid = threadIdx.x;
    const int tx = tid & 15;       // 0..15 -> column group (8 cols each)
    const int ty = tid >> 4;       // 0..15 -> row group (8 rows each)
    const int bx = blockIdx.x;     // column tile
    const int by = blockIdx.y;     // row tile
    const int bz = blockIdx.z;

    const float* Ab = A + (size_t)bz * aStrideZ + (size_t)by * BM * lda;
    const float* Bb = B + (size_t)bz * bStrideZ;

    // Loader indices (NT path: same pattern for A and B)
    const int lrow = tid >> 1;            // 0..127
    const int lk4  = (tid & 1) * 4;       // 0 or 4
    // NN B loader
    const int bkrow = tid >> 5;           // 0..7
    const int bn4   = (tid & 31) * 4;     // 0..124

    float acc[8][8];
    #pragma unroll
    for (int i = 0; i < 8; i++)
        #pragma unroll
        for (int j = 0; j < 8; j++) acc[i][j] = 0.0f;

    for (int k0 = 0; k0 < K; k0 += BK) {
        // --- load A tile (transpose into As[k][m]) ---
        {
            float4 a4 = *reinterpret_cast<const float4*>(
                Ab + (size_t)lrow * lda + k0 + lk4);
            As[lk4 + 0][lrow] = a4.x;
            As[lk4 + 1][lrow] = a4.y;
            As[lk4 + 2][lrow] = a4.z;
            As[lk4 + 3][lrow] = a4.w;
        }
        // --- load B tile ---
        if (MODE != 2) {
            // NT: B rows are n, K contiguous
            float4 b4 = *reinterpret_cast<const float4*>(
                Bb + (size_t)(bx * BN + lrow) * ldb + k0 + lk4);
            Bs[lk4 + 0][lrow] = b4.x;
            Bs[lk4 + 1][lrow] = b4.y;
            Bs[lk4 + 2][lrow] = b4.z;
            Bs[lk4 + 3][lrow] = b4.w;
        } else {
            // NN: B rows are k, n contiguous
            float4 b4 = *reinterpret_cast<const float4*>(
                Bb + (size_t)(k0 + bkrow) * ldb + bx * BN + bn4);
            *reinterpret_cast<float4*>(&Bs[bkrow][bn4]) = b4;
        }
        __syncthreads();

        #pragma unroll
        for (int k = 0; k < BK; k++) {
            float4 a0 = *reinterpret_cast<const float4*>(&As[k][ty * 8]);
            float4 a1 = *reinterpret_cast<const float4*>(&As[k][ty * 8 + 4]);
            float4 b0 = *reinterpret_cast<const float4*>(&Bs[k][tx * 8]);
            float4 b1 = *reinterpret_cast<const float4*>(&Bs[k][tx * 8 + 4]);
            float a[8] = {a0.x, a0.y, a0.z, a0.w, a1.x, a1.y, a1.z, a1.w};
            float b[8] = {b0.x, b0.y, b0.z, b0.w, b1.x, b1.y, b1.z, b1.w};
            #pragma unroll
            for (int i = 0; i < 8; i++)
                #pragma unroll
                for (int j = 0; j < 8; j++)
                    acc[i][j] = fmaf(a[i], b[j], acc[i][j]);
        }
        __syncthreads();
    }

    // ------------------------- epilogue -------------------------
    size_t base;
    int ldc, colbase;
    if (MODE == 0) {
        // C[b][h][s][d]; bz = b, bx = head (BN == HEAD_DIM)
        base = (size_t)bz * (HEADS * SEQ * HEAD_DIM) + (size_t)bx * (SEQ * HEAD_DIM);
        ldc = HEAD_DIM;
        colbase = tx * 8;
    } else if (MODE == 1) {
        base = (size_t)bz * SEQ * SEQ;
        ldc = SEQ;
        colbase = bx * BN + tx * 8;
    } else if (MODE == 2) {
        const int b = bz >> 4, h = bz & 15;
        base = (size_t)b * SEQ * HIDDEN + (size_t)h * HEAD_DIM;
        ldc = HIDDEN;
        colbase = tx * 8;  // grid.x == 1
    } else {
        base = 0;
        ldc = HIDDEN;
        colbase = bx * BN + tx * 8;
    }

    float bvals[8];
    if (MODE == 0 || MODE == 3) {
        const int bn = bx * BN + tx * 8;
        #pragma unroll
        for (int j = 0; j < 8; j++) bvals[j] = bias[bn + j];
    } else {
        #pragma unroll
        for (int j = 0; j < 8; j++) bvals[j] = 0.0f;
    }

    const int row0 = by * BM + ty * 8;
    #pragma unroll
    for (int i = 0; i < 8; i++) {
        float4 o0, o1;
        o0.x = fmaf(acc[i][0], alpha, bvals[0]);
        o0.y = fmaf(acc[i][1], alpha, bvals[1]);
        o0.z = fmaf(acc[i][2], alpha, bvals[2]);
        o0.w = fmaf(acc[i][3], alpha, bvals[3]);
        o1.x = fmaf(acc[i][4], alpha, bvals[4]);
        o1.y = fmaf(acc[i][5], alpha, bvals[5]);
        o1.z = fmaf(acc[i][6], alpha, bvals[6]);
        o1.w = fmaf(acc[i][7], alpha, bvals[7]);
        float* cp = C + base + (size_t)(row0 + i) * ldc + colbase;
        *reinterpret_cast<float4*>(cp)     = o0;
        *reinterpret_cast<float4*>(cp + 4) = o1;
    }
}

// ---------------------------------------------------------------------------
// Row softmax over 2048 elements, in place. One block (256 threads) per row.
// ---------------------------------------------------------------------------
__global__ __launch_bounds__(256)
void softmax2048_kernel(float* __restrict__ S)
{
    float4* r4 = reinterpret_cast<float4*>(S + (size_t)blockIdx.x * SEQ);
    const int tid = threadIdx.x;
    float4 v0 = r4[tid * 2];
    float4 v1 = r4[tid * 2 + 1];

    float m = fmaxf(fmaxf(fmaxf(v0.x, v0.y), fmaxf(v0.z, v0.w)),
                    fmaxf(fmaxf(v1.x, v1.y), fmaxf(v1.z, v1.w)));
    #pragma unroll
    for (int o = 16; o > 0; o >>= 1)
        m = fmaxf(m, __shfl_xor_sync(0xffffffffu, m, o));

    __shared__ float red[8];
    const int warp = tid >> 5, lane = tid & 31;
    if (lane == 0) red[warp] = m;
    __syncthreads();
    const float bm = fmaxf(fmaxf(fmaxf(red[0], red[1]), fmaxf(red[2], red[3])),
                           fmaxf(fmaxf(red[4], red[5]), fmaxf(red[6], red[7])));

    v0.x = __expf(v0.x - bm); v0.y = __expf(v0.y - bm);
    v0.z = __expf(v0.z - bm); v0.w = __expf(v0.w - bm);
    v1.x = __expf(v1.x - bm); v1.y = __expf(v1.y - bm);
    v1.z = __expf(v1.z - bm); v1.w = __expf(v1.w - bm);

    float s = v0.x + v0.y + v0.z + v0.w + v1.x + v1.y + v1.z + v1.w;
    #pragma unroll
    for (int o = 16; o > 0; o >>= 1)
        s += __shfl_xor_sync(0xffffffffu, s, o);
    __syncthreads();
    if (lane == 0) red[warp] = s;
    __syncthreads();
    const float bs = ((red[0] + red[1]) + (red[2] + red[3])) +
                     ((red[4] + red[5]) + (red[6] + red[7]));
    const float inv = 1.0f / bs;

    v0.x *= inv; v0.y *= inv; v0.z *= inv; v0.w *= inv;
    v1.x *= inv; v1.y *= inv; v1.z *= inv; v1.w *= inv;
    r4[tid * 2]     = v0;
    r4[tid * 2 + 1] = v1;
}

// ---------------------------------------------------------------------------
// kernel_launch
// Inputs: hidden_state, Wq, bq, Wk, bk, Wv, bv, Wo, bo  (all float32)
// ---------------------------------------------------------------------------
extern "C" void kernel_launch(void* const* d_in, const int* in_sizes, int n_in,
                              void* d_out, int out_size)
{
    const float* x  = (const float*)d_in[0];
    const float* Wq = (const float*)d_in[1];
    const float* bq = (const float*)d_in[2];
    const float* Wk = (const float*)d_in[3];
    const float* bk = (const float*)d_in[4];
    const float* Wv = (const float*)d_in[5];
    const float* bv = (const float*)d_in[6];
    const float* Wo = (const float*)d_in[7];
    const float* bo = (const float*)d_in[8];
    float* out = (float*)d_out;

    float *q, *k, *v, *sc, *at;
    cudaGetSymbolAddress((void**)&q,  g_q);
    cudaGetSymbolAddress((void**)&k,  g_k);
    cudaGetSymbolAddress((void**)&v,  g_v);
    cudaGetSymbolAddress((void**)&sc, g_scores);
    cudaGetSymbolAddress((void**)&at, g_attn);

    const float scale = 0.08838834764831845f;  // 1/sqrt(128)

    // 1) QKV projections: per batch z, M=2048, N=2048, K=2048 (NT)
    dim3 gridQKV(HIDDEN / BN, SEQ / BM, BATCH);
    gemm_kernel<0><<<gridQKV, 256>>>(x, Wq, q, bq, HIDDEN, HIDDEN, HIDDEN,
                                     (long)SEQ * HIDDEN, 0L, 1.0f);
    gemm_kernel<0><<<gridQKV, 256>>>(x, Wk, k, bk, HIDDEN, HIDDEN, HIDDEN,
                                     (long)SEQ * HIDDEN, 0L, 1.0f);
    gemm_kernel<0><<<gridQKV, 256>>>(x, Wv, v, bv, HIDDEN, HIDDEN, HIDDEN,
                                     (long)SEQ * HIDDEN, 0L, 1.0f);

    // 2) scores = Q @ K^T * scale : per (b,h), M=N=2048, K=128 (NT)
    dim3 gridS(SEQ / BN, SEQ / BM, BATCH * HEADS);
    gemm_kernel<1><<<gridS, 256>>>(q, k, sc, nullptr, HEAD_DIM, HEAD_DIM, HEAD_DIM,
                                   (long)SEQ * HEAD_DIM, (long)SEQ * HEAD_DIM, scale);

    // 3) softmax over last dim: one block per row
    softmax2048_kernel<<<BATCH * HEADS * SEQ, 256>>>(sc);

    // 4) attn = P @ V : per (b,h), M=2048, N=128, K=2048 (NN)
    dim3 gridPV(HEAD_DIM / BN, SEQ / BM, BATCH * HEADS);
    gemm_kernel<2><<<gridPV, 256>>>(sc, v, at, nullptr, SEQ, SEQ, HEAD_DIM,
                                    (long)SEQ * SEQ, (long)SEQ * HEAD_DIM, 1.0f);

    // 5) output projection: M=4096, N=2048, K=2048 (NT) + bias
    dim3 gridO(HIDDEN / BN, (BATCH * SEQ) / BM, 1);
    gemm_kernel<3><<<gridO, 256>>>(at, Wo, out, bo, HIDDEN, HIDDEN, HIDDEN,
                                   0L, 0L, 1.0f);
}

// round 2
// speedup vs baseline: 1.0004x; 1.0004x over previous
#include <cuda_runtime.h>

// Problem constants
constexpr int BATCH   = 2;
constexpr int SEQ     = 2048;
constexpr int HIDDEN  = 2048;
constexpr int HEADS   = 16;
constexpr int HEAD_DIM = 128;   // HIDDEN / HEADS

// ---------------------------------------------------------------------------
// Scratch (device globals — no allocations allowed in kernel_launch)
// ---------------------------------------------------------------------------
__device__ float g_q[BATCH * HEADS * SEQ * HEAD_DIM];      // [b][h][s][d]  32 MB
__device__ float g_k[BATCH * HEADS * SEQ * HEAD_DIM];      // [b][h][s][d]  32 MB
__device__ float g_v[BATCH * HEADS * SEQ * HEAD_DIM];      // [b][h][s][d]  32 MB
__device__ float g_scores[(size_t)BATCH * HEADS * SEQ * SEQ]; // [bh][q][k] 512 MB
__device__ float g_attn[BATCH * SEQ * HIDDEN];             // [b][s][h*D+d] 32 MB

// ---------------------------------------------------------------------------
// Tiled GEMM: 128x128 block tile, BK=8, 8x8 per thread, 256 threads.
// MODE 0: QKV projection   C = A @ W^T + bias  -> scatter to [b][h][s][d]
// MODE 1: scores           C = Q @ K^T * scale -> [bh][q][k]
// MODE 2: PV (NN)          C = P @ V           -> scatter to [b][s][h*D+d]
// MODE 3: out projection   C = A @ Wo^T + bo   -> [m][n] row-major
// A is always row-major with K contiguous.
// B: modes 0/1/3 are NT (rows = n, K contiguous); mode 2 is NN (rows = k).
// ---------------------------------------------------------------------------
constexpr int BM = 128, BN = 128, BK = 8;

template <int MODE>
__global__ __launch_bounds__(256)
void gemm_kernel(const float* __restrict__ A,
                 const float* __restrict__ B,
                 float* __restrict__ C,
                 const float* __restrict__ bias,
                 int K, int lda, int ldb,
                 long aStrideZ, long bStrideZ,
                 float alpha)
{
    __shared__ float As[BK][BM + 4];
    __shared__ float Bs[BK][BN + 4];

    const int tid = threadIdx.x;
    const int tx = tid & 15;       // 0..15 -> column group (8 cols each)
    const int ty = tid >> 4;       // 0..15 -> row group (8 rows each)
    const int bx = blockIdx.x;     // column tile
    const int by = blockIdx.y;     // row tile
    const int bz = blockIdx.z;

    const float* Ab = A + (size_t)bz * aStrideZ + (size_t)by * BM * lda;
    const float* Bb = B + (size_t)bz * bStrideZ;

    // Loader indices (NT path: same pattern for A and B)
    const int lrow = tid >> 1;            // 0..127
    const int lk4  = (tid & 1) * 4;       // 0 or 4
    // NN B loader
    const int bkrow = tid >> 5;           // 0..7
    const int bn4   = (tid & 31) * 4;     // 0..124

    float acc[8][8];
    #pragma unroll
    for (int i = 0; i < 8; i++)
        #pragma unroll
        for (int j = 0; j < 8; j++) acc[i][j] = 0.0f;

    for (int k0 = 0; k0 < K; k0 += BK) {
        // --- load A tile (transpose into As[k][m]) ---
        {
            float4 a4 = *reinterpret_cast<const float4*>(
                Ab + (size_t)lrow * lda + k0 + lk4);
            As[lk4 + 0][lrow] = a4.x;
            As[lk4 + 1][lrow] = a4.y;
            As[lk4 + 2][lrow] = a4.z;
            As[lk4 + 3][lrow] = a4.w;
        }
        // --- load B tile ---
        if (MODE != 2) {
            // NT: B rows are n, K contiguous
            float4 b4 = *reinterpret_cast<const float4*>(
                Bb + (size_t)(bx * BN + lrow) * ldb + k0 + lk4);
            Bs[lk4 + 0][lrow] = b4.x;
            Bs[lk4 + 1][lrow] = b4.y;
            Bs[lk4 + 2][lrow] = b4.z;
            Bs[lk4 + 3][lrow] = b4.w;
        } else {
            // NN: B rows are k, n contiguous
            float4 b4 = *reinterpret_cast<const float4*>(
                Bb + (size_t)(k0 + bkrow) * ldb + bx * BN + bn4);
            *reinterpret_cast<float4*>(&Bs[bkrow][bn4]) = b4;
        }
        __syncthreads();

        #pragma unroll
        for (int k = 0; k < BK; k++) {
            float4 a0 = *reinterpret_cast<const float4*>(&As[k][ty * 8]);
            float4 a1 = *reinterpret_cast<const float4*>(&As[k][ty * 8 + 4]);
            float4 b0 = *reinterpret_cast<const float4*>(&Bs[k][tx * 8]);
            float4 b1 = *reinterpret_cast<const float4*>(&Bs[k][tx * 8 + 4]);
            float a[8] = {a0.x, a0.y, a0.z, a0.w, a1.x, a1.y, a1.z, a1.w};
            float b[8] = {b0.x, b0.y, b0.z, b0.w, b1.x, b1.y, b1.z, b1.w};
            #pragma unroll
            for (int i = 0; i < 8; i++)
                #pragma unroll
                for (int j = 0; j < 8; j++)
                    acc[i][j] = fmaf(a[i], b[j], acc[i][j]);
        }
        __syncthreads();
    }

    // ------------------------- epilogue -------------------------
    size_t base;
    int ldc, colbase;
    if (MODE == 0) {
        // C[b][h][s][d]; bz = b, bx = head (BN == HEAD_DIM)
        base = (size_t)bz * (HEADS * SEQ * HEAD_DIM) + (size_t)bx * (SEQ * HEAD_DIM);
        ldc = HEAD_DIM;
        colbase = tx * 8;
    } else if (MODE == 1) {
        base = (size_t)bz * SEQ * SEQ;
        ldc = SEQ;
        colbase = bx * BN + tx * 8;
    } else if (MODE == 2) {
        const int b = bz >> 4, h = bz & 15;
        base = (size_t)b * SEQ * HIDDEN + (size_t)h * HEAD_DIM;
        ldc = HIDDEN;
        colbase = tx * 8;  // grid.x == 1
    } else {
        base = 0;
        ldc = HIDDEN;
        colbase = bx * BN + tx * 8;
    }

    float bvals[8];
    if (MODE == 0 || MODE == 3) {
        const int bn = bx * BN + tx * 8;
        #pragma unroll
        for (int j = 0; j < 8; j++) bvals[j] = bias[bn + j];
    } else {
        #pragma unroll
        for (int j = 0; j < 8; j++) bvals[j] = 0.0f;
    }

    const int row0 = by * BM + ty * 8;
    #pragma unroll
    for (int i = 0; i < 8; i++) {
        float4 o0, o1;
        o0.x = fmaf(acc[i][0], alpha, bvals[0]);
        o0.y = fmaf(acc[i][1], alpha, bvals[1]);
        o0.z = fmaf(acc[i][2], alpha, bvals[2]);
        o0.w = fmaf(acc[i][3], alpha, bvals[3]);
        o1.x = fmaf(acc[i][4], alpha, bvals[4]);
        o1.y = fmaf(acc[i][5], alpha, bvals[5]);
        o1.z = fmaf(acc[i][6], alpha, bvals[6]);
        o1.w = fmaf(acc[i][7], alpha, bvals[7]);
        float* cp = C + base + (size_t)(row0 + i) * ldc + colbase;
        *reinterpret_cast<float4*>(cp)     = o0;
        *reinterpret_cast<float4*>(cp + 4) = o1;
    }
}

// ---------------------------------------------------------------------------
// Row softmax over 2048 elements, in place. One block (256 threads) per row.
// ---------------------------------------------------------------------------
__global__ __launch_bounds__(256)
void softmax2048_kernel(float* __restrict__ S)
{
    float4* r4 = reinterpret_cast<float4*>(S + (size_t)blockIdx.x * SEQ);
    const int tid = threadIdx.x;
    float4 v0 = r4[tid * 2];
    float4 v1 = r4[tid * 2 + 1];

    float m = fmaxf(fmaxf(fmaxf(v0.x, v0.y), fmaxf(v0.z, v0.w)),
                    fmaxf(fmaxf(v1.x, v1.y), fmaxf(v1.z, v1.w)));
    #pragma unroll
    for (int o = 16; o > 0; o >>= 1)
        m = fmaxf(m, __shfl_xor_sync(0xffffffffu, m, o));

    __shared__ float red[8];
    const int warp = tid >> 5, lane = tid & 31;
    if (lane == 0) red[warp] = m;
    __syncthreads();
    const float bm = fmaxf(fmaxf(fmaxf(red[0], red[1]), fmaxf(red[2], red[3])),
                           fmaxf(fmaxf(red[4], red[5]), fmaxf(red[6], red[7])));

    v0.x = __expf(v0.x - bm); v0.y = __expf(v0.y - bm);
    v0.z = __expf(v0.z - bm); v0.w = __expf(v0.w - bm);
    v1.x = __expf(v1.x - bm); v1.y = __expf(v1.y - bm);
    v1.z = __expf(v1.z - bm); v1.w = __expf(v1.w - bm);

    float s = v0.x + v0.y + v0.z + v0.w + v1.x + v1.y + v1.z + v1.w;
    #pragma unroll
    for (int o = 16; o > 0; o >>= 1)
        s += __shfl_xor_sync(0xffffffffu, s, o);
    __syncthreads();
    if (lane == 0) red[warp] = s;
    __syncthreads();
    const float bs = ((red[0] + red[1]) + (red[2] + red[3])) +
                     ((red[4] + red[5]) + (red[6] + red[7]));
    const float inv = 1.0f / bs;

    v0.x *= inv; v0.y *= inv; v0.z *= inv; v0.w *= inv;
    v1.x *= inv; v1.y *= inv; v1.z *= inv; v1.w *= inv;
    r4[tid * 2]     = v0;
    r4[tid * 2 + 1] = v1;
}

// ---------------------------------------------------------------------------
// kernel_launch
// Inputs: hidden_state, Wq, bq, Wk, bk, Wv, bv, Wo, bo  (all float32)
// ---------------------------------------------------------------------------
extern "C" void kernel_launch(void* const* d_in, const int* in_sizes, int n_in,
                              void* d_out, int out_size)
{
    const float* x  = (const float*)d_in[0];
    const float* Wq = (const float*)d_in[1];
    const float* bq = (const float*)d_in[2];
    const float* Wk = (const float*)d_in[3];
    const float* bk = (const float*)d_in[4];
    const float* Wv = (const float*)d_in[5];
    const float* bv = (const float*)d_in[6];
    const float* Wo = (const float*)d_in[7];
    const float* bo = (const float*)d_in[8];
    float* out = (float*)d_out;

    float *q, *k, *v, *sc, *at;
    cudaGetSymbolAddress((void**)&q,  g_q);
    cudaGetSymbolAddress((void**)&k,  g_k);
    cudaGetSymbolAddress((void**)&v,  g_v);
    cudaGetSymbolAddress((void**)&sc, g_scores);
    cudaGetSymbolAddress((void**)&at, g_attn);

    const float scale = 0.08838834764831845f;  // 1/sqrt(128)

    // 1) QKV projections: per batch z, M=2048, N=2048, K=2048 (NT)
    dim3 gridQKV(HIDDEN / BN, SEQ / BM, BATCH);
    gemm_kernel<0><<<gridQKV, 256>>>(x, Wq, q, bq, HIDDEN, HIDDEN, HIDDEN,
                                     (long)SEQ * HIDDEN, 0L, 1.0f);
    gemm_kernel<0><<<gridQKV, 256>>>(x, Wk, k, bk, HIDDEN, HIDDEN, HIDDEN,
                                     (long)SEQ * HIDDEN, 0L, 1.0f);
    gemm_kernel<0><<<gridQKV, 256>>>(x, Wv, v, bv, HIDDEN, HIDDEN, HIDDEN,
                                     (long)SEQ * HIDDEN, 0L, 1.0f);

    // 2) scores = Q @ K^T * scale : per (b,h), M=N=2048, K=128 (NT)
    dim3 gridS(SEQ / BN, SEQ / BM, BATCH * HEADS);
    gemm_kernel<1><<<gridS, 256>>>(q, k, sc, nullptr, HEAD_DIM, HEAD_DIM, HEAD_DIM,
                                   (long)SEQ * HEAD_DIM, (long)SEQ * HEAD_DIM, scale);

    // 3) softmax over last dim: one block per row
    softmax2048_kernel<<<BATCH * HEADS * SEQ, 256>>>(sc);

    // 4) attn = P @ V : per (b,h), M=2048, N=128, K=2048 (NN)
    dim3 gridPV(HEAD_DIM / BN, SEQ / BM, BATCH * HEADS);
    gemm_kernel<2><<<gridPV, 256>>>(sc, v, at, nullptr, SEQ, SEQ, HEAD_DIM,
                                    (long)SEQ * SEQ, (long)SEQ * HEAD_DIM, 1.0f);

    // 5) output projection: M=4096, N=2048, K=2048 (NT) + bias
    dim3 gridO(HIDDEN / BN, (BATCH * SEQ) / BM, 1);
    gemm_kernel<3><<<gridO, 256>>>(at, Wo, out, bo, HIDDEN, HIDDEN, HIDDEN,
                                   0L, 0L, 1.0f);
}

// round 4
// speedup vs baseline: 2.1783x; 2.1774x over previous
#include <cuda_runtime.h>
#include <cuda_bf16.h>
#include <cstdint>
#include <cstddef>

// ============================================================================
// Problem constants
// ============================================================================
constexpr int SEQ = 2048, HID = 2048, HEADS = 16, HD = 128, BATCH = 2;
constexpr int NS = 4;                    // pipeline stages
constexpr int TILEB  = 128 * 80;         // one 128x32-bf16 tile, 80B padded rows
constexpr int STAGEB = 4 * TILEB;        // Ah, Al, Bh, Bl
constexpr int SMEM_BYTES = NS * STAGEB;  // 163840

// ============================================================================
// Device scratch pool (static — no runtime allocation allowed)
// ============================================================================
constexpr size_t MB = 1048576ull;
constexpr size_t OFF_XH  = 0,        OFF_XL  = 16*MB;
constexpr size_t OFF_WQH = 32*MB,    OFF_WQL = 40*MB;
constexpr size_t OFF_WKH = 48*MB,    OFF_WKL = 56*MB;
constexpr size_t OFF_WVH = 64*MB,    OFF_WVL = 72*MB;
constexpr size_t OFF_WOH = 80*MB,    OFF_WOL = 88*MB;
constexpr size_t OFF_QH  = 96*MB,    OFF_QL  = 112*MB;
constexpr size_t OFF_KH  = 128*MB,   OFF_KL  = 144*MB;
constexpr size_t OFF_VTH = 160*MB,   OFF_VTL = 176*MB;   // V^T [b][h][d][s]
constexpr size_t OFF_AH  = 192*MB,   OFF_AL  = 208*MB;   // attn [b*s][hid]
constexpr size_t OFF_SC  = 224*MB;                        // scores fp32 512MB
constexpr size_t OFF_PH  = 736*MB,   OFF_PL  = 992*MB;   // probs bf16 hi/lo
constexpr size_t POOL_SZ = 1248*MB;

__device__ __align__(1024) unsigned char g_pool[POOL_SZ];

// ============================================================================
// Helpers
// ============================================================================
__device__ __forceinline__ uint32_t smem_u32(const void* p) {
    uint32_t a;
    asm("{ .reg .u64 t; cvta.to.shared.u64 t, %1; cvt.u32.u64 %0, t; }"
        : "=r"(a) : "l"(p));
    return a;
}
__device__ __forceinline__ void cp_async16(uint32_t dst, const void* src) {
    asm volatile("cp.async.cg.shared.global [%0], [%1], 16;"
                 :: "r"(dst), "l"(src) : "memory");
}
#define CP_COMMIT() asm volatile("cp.async.commit_group;" ::: "memory")
#define CP_WAIT(n)  asm volatile("cp.async.wait_group %0;" :: "n"(n) : "memory")

__device__ __forceinline__ void ldsm4(uint32_t r[4], uint32_t a) {
    asm volatile("ldmatrix.sync.aligned.m8n8.x4.shared.b16 {%0,%1,%2,%3}, [%4];"
                 : "=r"(r[0]), "=r"(r[1]), "=r"(r[2]), "=r"(r[3]) : "r"(a));
}
__device__ __forceinline__ void mma16816(float c[4], const uint32_t a[4],
                                         const uint32_t b[2]) {
    asm volatile(
        "mma.sync.aligned.m16n8k16.row.col.f32.bf16.bf16.f32 "
        "{%0,%1,%2,%3}, {%4,%5,%6,%7}, {%8,%9}, {%0,%1,%2,%3};"
        : "+f"(c[0]), "+f"(c[1]), "+f"(c[2]), "+f"(c[3])
        : "r"(a[0]), "r"(a[1]), "r"(a[2]), "r"(a[3]), "r"(b[0]), "r"(b[1]));
}
__device__ __forceinline__ uint32_t bf2pack(float a, float b) {
    __nv_bfloat162 t;
    t.x = __float2bfloat16(a);
    t.y = __float2bfloat16(b);
    return *reinterpret_cast<uint32_t*>(&t);
}
__device__ __forceinline__ void split2(__nv_bfloat16* Ch, __nv_bfloat16* Cl,
                                       size_t idx, float v0, float v1) {
    float h0 = __bfloat162float(__float2bfloat16(v0));
    float h1 = __bfloat162float(__float2bfloat16(v1));
    *(uint32_t*)(Ch + idx) = bf2pack(h0, h1);
    *(uint32_t*)(Cl + idx) = bf2pack(v0 - h0, v1 - h1);
}

// ============================================================================
// bf16x3 mma.sync GEMM.  acc[m,n] = sum_k (Ah+Al)[m,k]*(Bh+Bl)[n,k]   (NT)
// 128x128 tile, BK=32, 256 threads (8 warps, each 32x64), NS-stage cp.async.
// MODE 0: v=(acc+bias[n])*alpha -> bf16 hi/lo q/k [b][h][s][d]   (grid.x=heads)
// MODE 1: v= acc+bias[n]        -> bf16 hi/lo TRANSPOSED vt [b][h][d][s]
// MODE 2: v= acc                -> fp32 scores [bh][q][k]
// MODE 3: v= acc                -> bf16 hi/lo attn [b][s][hid]
// MODE 4: v= acc+bias[n]        -> fp32 out [m][n]
// ============================================================================
template <int MODE>
__global__ void __launch_bounds__(256, 1)
gemm_mma(const __nv_bfloat16* __restrict__ Ah, const __nv_bfloat16* __restrict__ Al,
         const __nv_bfloat16* __restrict__ Bh, const __nv_bfloat16* __restrict__ Bl,
         float* __restrict__ Cf,
         __nv_bfloat16* __restrict__ Ch, __nv_bfloat16* __restrict__ Cl,
         const float* __restrict__ bias, float alpha,
         int K, int lda, int ldb, long aZ, long bZ)
{
    extern __shared__ __align__(128) unsigned char smem[];
    const uint32_t sb = smem_u32(smem);
    const int tid = threadIdx.x, lane = tid & 31, wid = tid >> 5;
    const int wm = wid & 3;   // warp row: 32 rows each
    const int wn = wid >> 2;  // warp col: 64 cols each
    const int bx = blockIdx.x, by = blockIdx.y, bz = blockIdx.z;

    const __nv_bfloat16* pAh = Ah + (size_t)bz * aZ + (size_t)by * 128 * lda;
    const __nv_bfloat16* pAl = Al + (size_t)bz * aZ + (size_t)by * 128 * lda;
    const __nv_bfloat16* pBh = Bh + (size_t)bz * bZ + (size_t)bx * 128 * ldb;
    const __nv_bfloat16* pBl = Bl + (size_t)bz * bZ + (size_t)bx * 128 * ldb;

    // cp.async per-thread chunk: rows (tid>>2) and (tid>>2)+64, 16B chunk tid&3
    const int frow = tid >> 2;
    const int fch  = tid & 3;
    const uint32_t fdst = (uint32_t)frow * 80 + (uint32_t)fch * 16;

    #define FILL_TILE(dstBase, g, ld) do {                                      \
        const char* _g = (const char*)(g) + ((size_t)_k0 + fch * 8) * 2;        \
        cp_async16((dstBase) + fdst, _g + (size_t)frow * (ld) * 2);             \
        cp_async16((dstBase) + fdst + 64 * 80, _g + (size_t)(frow + 64) * (ld) * 2); \
    } while (0)

    #define FILL_STAGE(IT) do {                                                 \
        const uint32_t _st = sb + (uint32_t)((IT) % NS) * STAGEB;               \
        const int _k0 = (IT) * 32;                                              \
        FILL_TILE(_st,             pAh, lda);                                   \
        FILL_TILE(_st + TILEB,     pAl, lda);                                   \
        FILL_TILE(_st + 2 * TILEB, pBh, ldb);                                   \
        FILL_TILE(_st + 3 * TILEB, pBl, ldb);                                   \
        CP_COMMIT();                                                            \
    } while (0)

    // ldmatrix per-lane offsets
    const uint32_t aOff = (uint32_t)(wm * 32 + (lane & 15)) * 80
                        + (uint32_t)((lane >> 4) & 1) * 16;
    const int nl = (lane & 7) + ((lane >> 4) & 1) * 8;
    const int kh = (lane >> 3) & 1;
    const uint32_t bOff = (uint32_t)(wn * 64 + nl) * 80 + (uint32_t)kh * 16;

    float acc[2][8][4];
    #pragma unroll
    for (int i = 0; i < 2; i++)
        #pragma unroll
        for (int j = 0; j < 8; j++)
            #pragma unroll
            for (int q = 0; q < 4; q++) acc[i][j][q] = 0.0f;

    const int NIT = K >> 5;
    for (int p = 0; p < NS - 1 && p < NIT; p++) FILL_STAGE(p);

    for (int it = 0; it < NIT; ++it) {
        if (it + NS - 1 < NIT) FILL_STAGE(it + NS - 1);
        int pend = NIT - 1 - it;
        if (pend > NS - 1) pend = NS - 1;
        switch (pend) {
            case 0: CP_WAIT(0); break;
            case 1: CP_WAIT(1); break;
            case 2: CP_WAIT(2); break;
            default: CP_WAIT(3); break;
        }
        __syncthreads();
        const uint32_t st = sb + (uint32_t)(it % NS) * STAGEB;
        #pragma unroll
        for (int ks = 0; ks < 2; ks++) {
            uint32_t ahf[2][4], alf[2][4], bhf[8][2], blf[8][2];
            #pragma unroll
            for (int mf = 0; mf < 2; mf++) {
                ldsm4(ahf[mf], st + aOff + mf * (16 * 80) + ks * 32);
                ldsm4(alf[mf], st + TILEB + aOff + mf * (16 * 80) + ks * 32);
            }
            #pragma unroll
            for (int nq = 0; nq < 4; nq++) {
                uint32_t t[4];
                ldsm4(t, st + 2 * TILEB + bOff + nq * (16 * 80) + ks * 32);
                bhf[2 * nq][0] = t[0]; bhf[2 * nq][1] = t[1];
                bhf[2 * nq + 1][0] = t[2]; bhf[2 * nq + 1][1] = t[3];
                ldsm4(t, st + 3 * TILEB + bOff + nq * (16 * 80) + ks * 32);
                blf[2 * nq][0] = t[0]; blf[2 * nq][1] = t[1];
                blf[2 * nq + 1][0] = t[2]; blf[2 * nq + 1][1] = t[3];
            }
            #pragma unroll
            for (int mf = 0; mf < 2; mf++)
                #pragma unroll
                for (int nf = 0; nf < 8; nf++) {
                    mma16816(acc[mf][nf], ahf[mf], bhf[nf]);
                    mma16816(acc[mf][nf], ahf[mf], blf[nf]);
                    mma16816(acc[mf][nf], alf[mf], bhf[nf]);
                }
        }
        __syncthreads();
    }
    #undef FILL_STAGE
    #undef FILL_TILE

    // ------------------------- epilogue -------------------------
    const int mrow0 = wm * 32 + (lane >> 2);       // tile-local row of c0/c1
    const int ncol0 = wn * 64 + (lane & 3) * 2;    // tile-local col

    if (MODE == 1) {
        // stage fp32 tile in smem, then transposed split-bf16 write
        float* tb = (float*)smem;  // [128][132]
        #pragma unroll
        for (int mf = 0; mf < 2; mf++)
            #pragma unroll
            for (int nf = 0; nf < 8; nf++) {
                const int r = mrow0 + mf * 16;
                const int c = ncol0 + nf * 8;
                tb[r * 132 + c]       = acc[mf][nf][0];
                tb[r * 132 + c + 1]   = acc[mf][nf][1];
                tb[(r + 8) * 132 + c] = acc[mf][nf][2];
                tb[(r + 8) * 132 + c + 1] = acc[mf][nf][3];
            }
        __syncthreads();
        const int d = tid & 127, sh = tid >> 7;  // sh: 0/1 -> s halves of 64
        const float bv = bias[bx * 128 + d];
        const int b = by >> 4;
        const size_t base = (((size_t)(b * HEADS + bx)) * HD + d) * SEQ
                          + (size_t)(by & 15) * 128 + sh * 64;
        #pragma unroll 8
        for (int s = 0; s < 64; s += 2) {
            float v0 = tb[(sh * 64 + s) * 132 + d] + bv;
            float v1 = tb[(sh * 64 + s + 1) * 132 + d] + bv;
            split2(Ch, Cl, base + s, v0, v1);
        }
        return;
    }

    #pragma unroll
    for (int mf = 0; mf < 2; mf++)
        #pragma unroll
        for (int nf = 0; nf < 8; nf++) {
            const int r = by * 128 + mrow0 + mf * 16;   // global row (c0/c1)
            const int c = ncol0 + nf * 8;               // tile-local col
            const float* a = acc[mf][nf];

            if (MODE == 2) {
                float* p0 = Cf + ((size_t)bz * SEQ + r) * SEQ + (size_t)bx * 128 + c;
                float2 w0; w0.x = a[0]; w0.y = a[1];
                float2 w1; w1.x = a[2]; w1.y = a[3];
                *(float2*)p0 = w0;
                *(float2*)(p0 + (size_t)8 * SEQ) = w1;
            } else if (MODE == 4) {
                const float b0 = bias[bx * 128 + c], b1 = bias[bx * 128 + c + 1];
                float* p0 = Cf + (size_t)r * HID + (size_t)bx * 128 + c;
                float2 w0; w0.x = a[0] + b0; w0.y = a[1] + b1;
                float2 w1; w1.x = a[2] + b0; w1.y = a[3] + b1;
                *(float2*)p0 = w0;
                *(float2*)(p0 + (size_t)8 * HID) = w1;
            } else if (MODE == 0) {
                const int b = r >> 11, s = r & 2047;
                const float b0 = bias[bx * 128 + c], b1 = bias[bx * 128 + c + 1];
                const size_t base = (((size_t)(b * HEADS + bx)) * SEQ + s) * HD + c;
                split2(Ch, Cl, base, (a[0] + b0) * alpha, (a[1] + b1) * alpha);
                split2(Ch, Cl, base + (size_t)8 * HD,
                       (a[2] + b0) * alpha, (a[3] + b1) * alpha);
            } else {  // MODE 3
                const int b = bz >> 4, h = bz & 15;
                const size_t base = ((size_t)b * SEQ + r) * HID + h * 128 + c;
                split2(Ch, Cl, base, a[0], a[1]);
                split2(Ch, Cl, base + (size_t)8 * HID, a[2], a[3]);
            }
        }
}

// ============================================================================
// fp32 -> bf16 hi/lo split conversion (4 elems/thread)
// ============================================================================
__global__ __launch_bounds__(256)
void conv_split(const float4* __restrict__ in, uint32_t* __restrict__ hi,
                uint32_t* __restrict__ lo, int n4)
{
    int i = blockIdx.x * blockDim.x + threadIdx.x;
    if (i >= n4) return;
    float4 v = in[i];
    float hx = __bfloat162float(__float2bfloat16(v.x));
    float hy = __bfloat162float(__float2bfloat16(v.y));
    float hz = __bfloat162float(__float2bfloat16(v.z));
    float hw = __bfloat162float(__float2bfloat16(v.w));
    hi[2 * i]     = bf2pack(hx, hy);
    hi[2 * i + 1] = bf2pack(hz, hw);
    lo[2 * i]     = bf2pack(v.x - hx, v.y - hy);
    lo[2 * i + 1] = bf2pack(v.z - hz, v.w - hw);
}

// ============================================================================
// Row softmax over 2048 fp32 + split-convert probs to bf16 hi/lo
// ============================================================================
__global__ __launch_bounds__(256)
void softmax_split(const float* __restrict__ S, uint32_t* __restrict__ PH,
                   uint32_t* __restrict__ PL)
{
    const float4* r4 = (const float4*)(S + (size_t)blockIdx.x * SEQ);
    const int tid = threadIdx.x;
    float4 v0 = r4[tid * 2];
    float4 v1 = r4[tid * 2 + 1];

    float m = fmaxf(fmaxf(fmaxf(v0.x, v0.y), fmaxf(v0.z, v0.w)),
                    fmaxf(fmaxf(v1.x, v1.y), fmaxf(v1.z, v1.w)));
    #pragma unroll
    for (int o = 16; o > 0; o >>= 1)
        m = fmaxf(m, __shfl_xor_sync(0xffffffffu, m, o));

    __shared__ float red[8];
    const int warp = tid >> 5, lane = tid & 31;
    if (lane == 0) red[warp] = m;
    __syncthreads();
    const float bm = fmaxf(fmaxf(fmaxf(red[0], red[1]), fmaxf(red[2], red[3])),
                           fmaxf(fmaxf(red[4], red[5]), fmaxf(red[6], red[7])));

    v0.x = __expf(v0.x - bm); v0.y = __expf(v0.y - bm);
    v0.z = __expf(v0.z - bm); v0.w = __expf(v0.w - bm);
    v1.x = __expf(v1.x - bm); v1.y = __expf(v1.y - bm);
    v1.z = __expf(v1.z - bm); v1.w = __expf(v1.w - bm);

    float s = v0.x + v0.y + v0.z + v0.w + v1.x + v1.y + v1.z + v1.w;
    #pragma unroll
    for (int o = 16; o > 0; o >>= 1)
        s += __shfl_xor_sync(0xffffffffu, s, o);
    __syncthreads();
    if (lane == 0) red[warp] = s;
    __syncthreads();
    const float bs = ((red[0] + red[1]) + (red[2] + red[3])) +
                     ((red[4] + red[5]) + (red[6] + red[7]));
    const float inv = 1.0f / bs;

    float p[8] = {v0.x * inv, v0.y * inv, v0.z * inv, v0.w * inv,
                  v1.x * inv, v1.y * inv, v1.z * inv, v1.w * inv};
    uint32_t* oh = PH + ((size_t)blockIdx.x * SEQ + tid * 8) / 2;
    uint32_t* ol = PL + ((size_t)blockIdx.x * SEQ + tid * 8) / 2;
    #pragma unroll
    for (int q = 0; q < 4; q++) {
        float a = p[2 * q], b = p[2 * q + 1];
        float ha = __bfloat162float(__float2bfloat16(a));
        float hb = __bfloat162float(__float2bfloat16(b));
        oh[q] = bf2pack(ha, hb);
        ol[q] = bf2pack(a - ha, b - hb);
    }
}

// ============================================================================
// kernel_launch
// ============================================================================
extern "C" void kernel_launch(void* const* d_in, const int* in_sizes, int n_in,
                              void* d_out, int out_size)
{
    const float* x  = (const float*)d_in[0];
    const float* Wq = (const float*)d_in[1];
    const float* bq = (const float*)d_in[2];
    const float* Wk = (const float*)d_in[3];
    const float* bk = (const float*)d_in[4];
    const float* Wv = (const float*)d_in[5];
    const float* bv = (const float*)d_in[6];
    const float* Wo = (const float*)d_in[7];
    const float* bo = (const float*)d_in[8];
    float* out = (float*)d_out;

    unsigned char* pool;
    cudaGetSymbolAddress((void**)&pool, g_pool);
    auto bfp = [&](size_t off) { return (__nv_bfloat16*)(pool + off); };
    auto u32 = [&](size_t off) { return (uint32_t*)(pool + off); };
    float* sc = (float*)(pool + OFF_SC);

    cudaFuncSetAttribute(gemm_mma<0>, cudaFuncAttributeMaxDynamicSharedMemorySize, SMEM_BYTES);
    cudaFuncSetAttribute(gemm_mma<1>, cudaFuncAttributeMaxDynamicSharedMemorySize, SMEM_BYTES);
    cudaFuncSetAttribute(gemm_mma<2>, cudaFuncAttributeMaxDynamicSharedMemorySize, SMEM_BYTES);
    cudaFuncSetAttribute(gemm_mma<3>, cudaFuncAttributeMaxDynamicSharedMemorySize, SMEM_BYTES);
    cudaFuncSetAttribute(gemm_mma<4>, cudaFuncAttributeMaxDynamicSharedMemorySize, SMEM_BYTES);

    const float scale = 0.08838834764831845f;  // 1/sqrt(128)

    // 1) split-convert inputs & weights to bf16 hi/lo
    conv_split<<<8192, 256>>>((const float4*)x,  u32(OFF_XH),  u32(OFF_XL), 2097152);
    conv_split<<<4096, 256>>>((const float4*)Wq, u32(OFF_WQH), u32(OFF_WQL), 1048576);
    conv_split<<<4096, 256>>>((const float4*)Wk, u32(OFF_WKH), u32(OFF_WKL), 1048576);
    conv_split<<<4096, 256>>>((const float4*)Wv, u32(OFF_WVH), u32(OFF_WVL), 1048576);
    conv_split<<<4096, 256>>>((const float4*)Wo, u32(OFF_WOH), u32(OFF_WOL), 1048576);

    // 2) projections: M=4096 (both batches), N=2048, K=2048
    dim3 gP(16, 32, 1);
    gemm_mma<0><<<gP, 256, SMEM_BYTES>>>(bfp(OFF_XH), bfp(OFF_XL), bfp(OFF_WQH), bfp(OFF_WQL),
                                         nullptr, bfp(OFF_QH), bfp(OFF_QL), bq, scale,
                                         HID, HID, HID, 0, 0);
    gemm_mma<0><<<gP, 256, SMEM_BYTES>>>(bfp(OFF_XH), bfp(OFF_XL), bfp(OFF_WKH), bfp(OFF_WKL),
                                         nullptr, bfp(OFF_KH), bfp(OFF_KL), bk, 1.0f,
                                         HID, HID, HID, 0, 0);
    gemm_mma<1><<<gP, 256, SMEM_BYTES>>>(bfp(OFF_XH), bfp(OFF_XL), bfp(OFF_WVH), bfp(OFF_WVL),
                                         nullptr, bfp(OFF_VTH), bfp(OFF_VTL), bv, 1.0f,
                                         HID, HID, HID, 0, 0);

    // 3) scores = Q K^T (scale folded into Q): per (b,h), M=N=2048, K=128
    dim3 gS(16, 16, BATCH * HEADS);
    gemm_mma<2><<<gS, 256, SMEM_BYTES>>>(bfp(OFF_QH), bfp(OFF_QL), bfp(OFF_KH), bfp(OFF_KL),
                                         sc, nullptr, nullptr, nullptr, 1.0f,
                                         HD, HD, HD, (long)SEQ * HD, (long)SEQ * HD);

    // 4) softmax + split to bf16 hi/lo probs
    softmax_split<<<BATCH * HEADS * SEQ, 256>>>(sc, u32(OFF_PH), u32(OFF_PL));

    // 5) PV: per (b,h), M=2048, N=128, K=2048 (NT against V^T)
    dim3 gPV(1, 16, BATCH * HEADS);
    gemm_mma<3><<<gPV, 256, SMEM_BYTES>>>(bfp(OFF_PH), bfp(OFF_PL), bfp(OFF_VTH), bfp(OFF_VTL),
                                          nullptr, bfp(OFF_AH), bfp(OFF_AL), nullptr, 1.0f,
                                          SEQ, SEQ, SEQ, (long)SEQ * SEQ, (long)HD * SEQ);

    // 6) out projection: M=4096, N=2048, K=2048 + bias -> fp32
    gemm_mma<4><<<gP, 256, SMEM_BYTES>>>(bfp(OFF_AH), bfp(OFF_AL), bfp(OFF_WOH), bfp(OFF_WOL),
                                         out, nullptr, nullptr, bo, 1.0f,
                                         HID, HID, HID, 0, 0);
}

// round 5
// speedup vs baseline: 2.5280x; 1.1605x over previous
#include <cuda_runtime.h>
#include <cuda_bf16.h>
#include <cstdint>
#include <cstddef>

// ============================================================================
// Problem constants
// ============================================================================
constexpr int SEQ = 2048, HID = 2048, HEADS = 16, HD = 128, BATCH = 2;
constexpr int NS = 2;                    // pipeline stages (2 => 2 CTAs/SM)
constexpr int TILEB  = 128 * 80;         // one 128x32-bf16 tile, 80B padded rows
constexpr int STAGEB = 4 * TILEB;        // Ah, Al, Bh, Bl
constexpr int SMEM_BYTES = NS * STAGEB;  // 81920

// ============================================================================
// Device scratch pool (static — no runtime allocation allowed)
// ============================================================================
constexpr size_t MB = 1048576ull;
constexpr size_t OFF_XH  = 0,        OFF_XL  = 16*MB;
constexpr size_t OFF_WQH = 32*MB,    OFF_WQL = 40*MB;
constexpr size_t OFF_WKH = 48*MB,    OFF_WKL = 56*MB;
constexpr size_t OFF_WVH = 64*MB,    OFF_WVL = 72*MB;
constexpr size_t OFF_WOH = 80*MB,    OFF_WOL = 88*MB;
constexpr size_t OFF_QH  = 96*MB,    OFF_QL  = 112*MB;
constexpr size_t OFF_KH  = 128*MB,   OFF_KL  = 144*MB;
constexpr size_t OFF_VTH = 160*MB,   OFF_VTL = 176*MB;   // V^T [b][h][d][s]
constexpr size_t OFF_AH  = 192*MB,   OFF_AL  = 208*MB;   // attn [b*s][hid]
constexpr size_t OFF_SC  = 224*MB;                        // scores fp32 512MB
constexpr size_t OFF_PH  = 736*MB,   OFF_PL  = 992*MB;   // probs bf16 hi/lo
constexpr size_t POOL_SZ = 1248*MB;

__device__ __align__(1024) unsigned char g_pool[POOL_SZ];

// ============================================================================
// Helpers
// ============================================================================
__device__ __forceinline__ uint32_t smem_u32(const void* p) {
    uint32_t a;
    asm("{ .reg .u64 t; cvta.to.shared.u64 t, %1; cvt.u32.u64 %0, t; }"
        : "=r"(a) : "l"(p));
    return a;
}
__device__ __forceinline__ void cp_async16(uint32_t dst, const void* src) {
    asm volatile("cp.async.cg.shared.global [%0], [%1], 16;"
                 :: "r"(dst), "l"(src) : "memory");
}
#define CP_COMMIT() asm volatile("cp.async.commit_group;" ::: "memory")
#define CP_WAIT(n)  asm volatile("cp.async.wait_group %0;" :: "n"(n) : "memory")

__device__ __forceinline__ void ldsm4(uint32_t r[4], uint32_t a) {
    asm volatile("ldmatrix.sync.aligned.m8n8.x4.shared.b16 {%0,%1,%2,%3}, [%4];"
                 : "=r"(r[0]), "=r"(r[1]), "=r"(r[2]), "=r"(r[3]) : "r"(a));
}
__device__ __forceinline__ void mma16816(float c[4], const uint32_t a[4],
                                         const uint32_t b0, const uint32_t b1) {
    asm volatile(
        "mma.sync.aligned.m16n8k16.row.col.f32.bf16.bf16.f32 "
        "{%0,%1,%2,%3}, {%4,%5,%6,%7}, {%8,%9}, {%0,%1,%2,%3};"
        : "+f"(c[0]), "+f"(c[1]), "+f"(c[2]), "+f"(c[3])
        : "r"(a[0]), "r"(a[1]), "r"(a[2]), "r"(a[3]), "r"(b0), "r"(b1));
}
__device__ __forceinline__ uint32_t bf2pack(float a, float b) {
    __nv_bfloat162 t;
    t.x = __float2bfloat16(a);
    t.y = __float2bfloat16(b);
    return *reinterpret_cast<uint32_t*>(&t);
}
__device__ __forceinline__ void split2(__nv_bfloat16* Ch, __nv_bfloat16* Cl,
                                       size_t idx, float v0, float v1) {
    float h0 = __bfloat162float(__float2bfloat16(v0));
    float h1 = __bfloat162float(__float2bfloat16(v1));
    *(uint32_t*)(Ch + idx) = bf2pack(h0, h1);
    *(uint32_t*)(Cl + idx) = bf2pack(v0 - h0, v1 - h1);
}

// ============================================================================
// bf16x3 mma.sync GEMM.  acc[m,n] = sum_k (Ah+Al)[m,k]*(Bh+Bl)[n,k]   (NT)
// 128x128 tile, BK=32, 256 threads (8 warps, each 32x64), 2-stage cp.async,
// 2 CTAs/SM.
// MODE 0: v=(acc+bias[n])*alpha -> bf16 hi/lo q/k [b][h][s][d]   (grid.x=heads)
// MODE 1: v= acc+bias[n]        -> bf16 hi/lo TRANSPOSED vt [b][h][d][s]
// MODE 2: v= acc                -> fp32 scores [bh][q][k]
// MODE 3: v= acc                -> bf16 hi/lo attn [b][s][hid]
// MODE 4: v= acc+bias[n]        -> fp32 out [m][n]
// ============================================================================
template <int MODE>
__global__ void __launch_bounds__(256, 2)
gemm_mma(const __nv_bfloat16* __restrict__ Ah, const __nv_bfloat16* __restrict__ Al,
         const __nv_bfloat16* __restrict__ Bh, const __nv_bfloat16* __restrict__ Bl,
         float* __restrict__ Cf,
         __nv_bfloat16* __restrict__ Ch, __nv_bfloat16* __restrict__ Cl,
         const float* __restrict__ bias, float alpha,
         int K, int lda, int ldb, long aZ, long bZ)
{
    extern __shared__ __align__(128) unsigned char smem[];
    const uint32_t sb = smem_u32(smem);
    const int tid = threadIdx.x, lane = tid & 31, wid = tid >> 5;
    const int wm = wid & 3;   // warp row: 32 rows each
    const int wn = wid >> 2;  // warp col: 64 cols each
    const int bx = blockIdx.x, by = blockIdx.y, bz = blockIdx.z;

    const __nv_bfloat16* pAh = Ah + (size_t)bz * aZ + (size_t)by * 128 * lda;
    const __nv_bfloat16* pAl = Al + (size_t)bz * aZ + (size_t)by * 128 * lda;
    const __nv_bfloat16* pBh = Bh + (size_t)bz * bZ + (size_t)bx * 128 * ldb;
    const __nv_bfloat16* pBl = Bl + (size_t)bz * bZ + (size_t)bx * 128 * ldb;

    // cp.async per-thread chunk: rows (tid>>2) and (tid>>2)+64, 16B chunk tid&3
    const int frow = tid >> 2;
    const int fch  = tid & 3;
    const uint32_t fdst = (uint32_t)frow * 80 + (uint32_t)fch * 16;

    #define FILL_TILE(dstBase, g, ld) do {                                      \
        const char* _g = (const char*)(g) + ((size_t)_k0 + fch * 8) * 2;        \
        cp_async16((dstBase) + fdst, _g + (size_t)frow * (ld) * 2);             \
        cp_async16((dstBase) + fdst + 64 * 80, _g + (size_t)(frow + 64) * (ld) * 2); \
    } while (0)

    #define FILL_STAGE(IT) do {                                                 \
        const uint32_t _st = sb + (uint32_t)((IT) & 1) * STAGEB;                \
        const int _k0 = (IT) * 32;                                              \
        FILL_TILE(_st,             pAh, lda);                                   \
        FILL_TILE(_st + TILEB,     pAl, lda);                                   \
        FILL_TILE(_st + 2 * TILEB, pBh, ldb);                                   \
        FILL_TILE(_st + 3 * TILEB, pBl, ldb);                                   \
        CP_COMMIT();                                                            \
    } while (0)

    // ldmatrix per-lane offsets
    const uint32_t aOff = (uint32_t)(wm * 32 + (lane & 15)) * 80
                        + (uint32_t)((lane >> 4) & 1) * 16;
    const int nl = (lane & 7) + ((lane >> 4) & 1) * 8;
    const int kh = (lane >> 3) & 1;
    const uint32_t bOff = (uint32_t)(wn * 64 + nl) * 80 + (uint32_t)kh * 16;

    float acc[2][8][4];
    #pragma unroll
    for (int i = 0; i < 2; i++)
        #pragma unroll
        for (int j = 0; j < 8; j++)
            #pragma unroll
            for (int q = 0; q < 4; q++) acc[i][j][q] = 0.0f;

    const int NIT = K >> 5;
    FILL_STAGE(0);

    for (int it = 0; it < NIT; ++it) {
        if (it + 1 < NIT) { FILL_STAGE(it + 1); CP_WAIT(1); }
        else              { CP_WAIT(0); }
        __syncthreads();
        const uint32_t st = sb + (uint32_t)(it & 1) * STAGEB;
        #pragma unroll
        for (int ks = 0; ks < 2; ks++) {
            uint32_t ahf[2][4], alf[2][4];
            #pragma unroll
            for (int mf = 0; mf < 2; mf++) {
                ldsm4(ahf[mf], st + aOff + mf * (16 * 80) + ks * 32);
                ldsm4(alf[mf], st + TILEB + aOff + mf * (16 * 80) + ks * 32);
            }
            #pragma unroll
            for (int nq = 0; nq < 4; nq++) {
                uint32_t th[4], tl[4];
                ldsm4(th, st + 2 * TILEB + bOff + nq * (16 * 80) + ks * 32);
                ldsm4(tl, st + 3 * TILEB + bOff + nq * (16 * 80) + ks * 32);
                #pragma unroll
                for (int mf = 0; mf < 2; mf++) {
                    mma16816(acc[mf][2 * nq],     ahf[mf], th[0], th[1]);
                    mma16816(acc[mf][2 * nq],     ahf[mf], tl[0], tl[1]);
                    mma16816(acc[mf][2 * nq],     alf[mf], th[0], th[1]);
                    mma16816(acc[mf][2 * nq + 1], ahf[mf], th[2], th[3]);
                    mma16816(acc[mf][2 * nq + 1], ahf[mf], tl[2], tl[3]);
                    mma16816(acc[mf][2 * nq + 1], alf[mf], th[2], th[3]);
                }
            }
        }
        __syncthreads();
    }
    #undef FILL_STAGE
    #undef FILL_TILE

    // ------------------------- epilogue -------------------------
    const int mrow0 = wm * 32 + (lane >> 2);       // tile-local row of c0/c1
    const int ncol0 = wn * 64 + (lane & 3) * 2;    // tile-local col

    if (MODE == 1) {
        // stage fp32 tile in smem, then transposed split-bf16 write
        float* tb = (float*)smem;  // [128][132]
        #pragma unroll
        for (int mf = 0; mf < 2; mf++)
            #pragma unroll
            for (int nf = 0; nf < 8; nf++) {
                const int r = mrow0 + mf * 16;
                const int c = ncol0 + nf * 8;
                tb[r * 132 + c]       = acc[mf][nf][0];
                tb[r * 132 + c + 1]   = acc[mf][nf][1];
                tb[(r + 8) * 132 + c] = acc[mf][nf][2];
                tb[(r + 8) * 132 + c + 1] = acc[mf][nf][3];
            }
        __syncthreads();
        const int d = tid & 127, sh = tid >> 7;  // sh: 0/1 -> s halves of 64
        const float bv = bias[bx * 128 + d];
        const int b = by >> 4;
        const size_t base = (((size_t)(b * HEADS + bx)) * HD + d) * SEQ
                          + (size_t)(by & 15) * 128 + sh * 64;
        #pragma unroll 8
        for (int s = 0; s < 64; s += 2) {
            float v0 = tb[(sh * 64 + s) * 132 + d] + bv;
            float v1 = tb[(sh * 64 + s + 1) * 132 + d] + bv;
            split2(Ch, Cl, base + s, v0, v1);
        }
        return;
    }

    #pragma unroll
    for (int mf = 0; mf < 2; mf++)
        #pragma unroll
        for (int nf = 0; nf < 8; nf++) {
            const int r = by * 128 + mrow0 + mf * 16;   // global row (c0/c1)
            const int c = ncol0 + nf * 8;               // tile-local col
            const float* a = acc[mf][nf];

            if (MODE == 2) {
                float* p0 = Cf + ((size_t)bz * SEQ + r) * SEQ + (size_t)bx * 128 + c;
                float2 w0; w0.x = a[0]; w0.y = a[1];
                float2 w1; w1.x = a[2]; w1.y = a[3];
                *(float2*)p0 = w0;
                *(float2*)(p0 + (size_t)8 * SEQ) = w1;
            } else if (MODE == 4) {
                const float b0 = bias[bx * 128 + c], b1 = bias[bx * 128 + c + 1];
                float* p0 = Cf + (size_t)r * HID + (size_t)bx * 128 + c;
                float2 w0; w0.x = a[0] + b0; w0.y = a[1] + b1;
                float2 w1; w1.x = a[2] + b0; w1.y = a[3] + b1;
                *(float2*)p0 = w0;
                *(float2*)(p0 + (size_t)8 * HID) = w1;
            } else if (MODE == 0) {
                const int b = r >> 11, s = r & 2047;
                const float b0 = bias[bx * 128 + c], b1 = bias[bx * 128 + c + 1];
                const size_t base = (((size_t)(b * HEADS + bx)) * SEQ + s) * HD + c;
                split2(Ch, Cl, base, (a[0] + b0) * alpha, (a[1] + b1) * alpha);
                split2(Ch, Cl, base + (size_t)8 * HD,
                       (a[2] + b0) * alpha, (a[3] + b1) * alpha);
            } else {  // MODE 3
                const int b = bz >> 4, h = bz & 15;
                const size_t base = ((size_t)b * SEQ + r) * HID + h * 128 + c;
                split2(Ch, Cl, base, a[0], a[1]);
                split2(Ch, Cl, base + (size_t)8 * HID, a[2], a[3]);
            }
        }
}

// ============================================================================
// fp32 -> bf16 hi/lo split conversion (4 elems/thread)
// ============================================================================
__global__ __launch_bounds__(256)
void conv_split(const float4* __restrict__ in, uint32_t* __restrict__ hi,
                uint32_t* __restrict__ lo, int n4)
{
    int i = blockIdx.x * blockDim.x + threadIdx.x;
    if (i >= n4) return;
    float4 v = in[i];
    float hx = __bfloat162float(__float2bfloat16(v.x));
    float hy = __bfloat162float(__float2bfloat16(v.y));
    float hz = __bfloat162float(__float2bfloat16(v.z));
    float hw = __bfloat162float(__float2bfloat16(v.w));
    hi[2 * i]     = bf2pack(hx, hy);
    hi[2 * i + 1] = bf2pack(hz, hw);
    lo[2 * i]     = bf2pack(v.x - hx, v.y - hy);
    lo[2 * i + 1] = bf2pack(v.z - hz, v.w - hw);
}

// ============================================================================
// Row softmax over 2048 fp32 + split-convert probs to bf16 hi/lo
// ============================================================================
__global__ __launch_bounds__(256)
void softmax_split(const float* __restrict__ S, uint32_t* __restrict__ PH,
                   uint32_t* __restrict__ PL)
{
    const float4* r4 = (const float4*)(S + (size_t)blockIdx.x * SEQ);
    const int tid = threadIdx.x;
    float4 v0 = r4[tid * 2];
    float4 v1 = r4[tid * 2 + 1];

    float m = fmaxf(fmaxf(fmaxf(v0.x, v0.y), fmaxf(v0.z, v0.w)),
                    fmaxf(fmaxf(v1.x, v1.y), fmaxf(v1.z, v1.w)));
    #pragma unroll
    for (int o = 16; o > 0; o >>= 1)
        m = fmaxf(m, __shfl_xor_sync(0xffffffffu, m, o));

    __shared__ float red[8];
    const int warp = tid >> 5, lane = tid & 31;
    if (lane == 0) red[warp] = m;
    __syncthreads();
    const float bm = fmaxf(fmaxf(fmaxf(red[0], red[1]), fmaxf(red[2], red[3])),
                           fmaxf(fmaxf(red[4], red[5]), fmaxf(red[6], red[7])));

    v0.x = __expf(v0.x - bm); v0.y = __expf(v0.y - bm);
    v0.z = __expf(v0.z - bm); v0.w = __expf(v0.w - bm);
    v1.x = __expf(v1.x - bm); v1.y = __expf(v1.y - bm);
    v1.z = __expf(v1.z - bm); v1.w = __expf(v1.w - bm);

    float s = v0.x + v0.y + v0.z + v0.w + v1.x + v1.y + v1.z + v1.w;
    #pragma unroll
    for (int o = 16; o > 0; o >>= 1)
        s += __shfl_xor_sync(0xffffffffu, s, o);
    __syncthreads();
    if (lane == 0) red[warp] = s;
    __syncthreads();
    const float bs = ((red[0] + red[1]) + (red[2] + red[3])) +
                     ((red[4] + red[5]) + (red[6] + red[7]));
    const float inv = 1.0f / bs;

    float p[8] = {v0.x * inv, v0.y * inv, v0.z * inv, v0.w * inv,
                  v1.x * inv, v1.y * inv, v1.z * inv, v1.w * inv};
    uint32_t* oh = PH + ((size_t)blockIdx.x * SEQ + tid * 8) / 2;
    uint32_t* ol = PL + ((size_t)blockIdx.x * SEQ + tid * 8) / 2;
    #pragma unroll
    for (int q = 0; q < 4; q++) {
        float a = p[2 * q], b = p[2 * q + 1];
        float ha = __bfloat162float(__float2bfloat16(a));
        float hb = __bfloat162float(__float2bfloat16(b));
        oh[q] = bf2pack(ha, hb);
        ol[q] = bf2pack(a - ha, b - hb);
    }
}

// ============================================================================
// kernel_launch
// ============================================================================
extern "C" void kernel_launch(void* const* d_in, const int* in_sizes, int n_in,
                              void* d_out, int out_size)
{
    const float* x  = (const float*)d_in[0];
    const float* Wq = (const float*)d_in[1];
    const float* bq = (const float*)d_in[2];
    const float* Wk = (const float*)d_in[3];
    const float* bk = (const float*)d_in[4];
    const float* Wv = (const float*)d_in[5];
    const float* bv = (const float*)d_in[6];
    const float* Wo = (const float*)d_in[7];
    const float* bo = (const float*)d_in[8];
    float* out = (float*)d_out;

    unsigned char* pool;
    cudaGetSymbolAddress((void**)&pool, g_pool);
    auto bfp = [&](size_t off) { return (__nv_bfloat16*)(pool + off); };
    auto u32 = [&](size_t off) { return (uint32_t*)(pool + off); };
    float* sc = (float*)(pool + OFF_SC);

    cudaFuncSetAttribute(gemm_mma<0>, cudaFuncAttributeMaxDynamicSharedMemorySize, SMEM_BYTES);
    cudaFuncSetAttribute(gemm_mma<1>, cudaFuncAttributeMaxDynamicSharedMemorySize, SMEM_BYTES);
    cudaFuncSetAttribute(gemm_mma<2>, cudaFuncAttributeMaxDynamicSharedMemorySize, SMEM_BYTES);
    cudaFuncSetAttribute(gemm_mma<3>, cudaFuncAttributeMaxDynamicSharedMemorySize, SMEM_BYTES);
    cudaFuncSetAttribute(gemm_mma<4>, cudaFuncAttributeMaxDynamicSharedMemorySize, SMEM_BYTES);

    const float scale = 0.08838834764831845f;  // 1/sqrt(128)

    // 1) split-convert inputs & weights to bf16 hi/lo
    conv_split<<<8192, 256>>>((const float4*)x,  u32(OFF_XH),  u32(OFF_XL), 2097152);
    conv_split<<<4096, 256>>>((const float4*)Wq, u32(OFF_WQH), u32(OFF_WQL), 1048576);
    conv_split<<<4096, 256>>>((const float4*)Wk, u32(OFF_WKH), u32(OFF_WKL), 1048576);
    conv_split<<<4096, 256>>>((const float4*)Wv, u32(OFF_WVH), u32(OFF_WVL), 1048576);
    conv_split<<<4096, 256>>>((const float4*)Wo, u32(OFF_WOH), u32(OFF_WOL), 1048576);

    // 2) projections: M=4096 (both batches), N=2048, K=2048
    dim3 gP(16, 32, 1);
    gemm_mma<0><<<gP, 256, SMEM_BYTES>>>(bfp(OFF_XH), bfp(OFF_XL), bfp(OFF_WQH), bfp(OFF_WQL),
                                         nullptr, bfp(OFF_QH), bfp(OFF_QL), bq, scale,
                                         HID, HID, HID, 0, 0);
    gemm_mma<0><<<gP, 256, SMEM_BYTES>>>(bfp(OFF_XH), bfp(OFF_XL), bfp(OFF_WKH), bfp(OFF_WKL),
                                         nullptr, bfp(OFF_KH), bfp(OFF_KL), bk, 1.0f,
                                         HID, HID, HID, 0, 0);
    gemm_mma<1><<<gP, 256, SMEM_BYTES>>>(bfp(OFF_XH), bfp(OFF_XL), bfp(OFF_WVH), bfp(OFF_WVL),
                                         nullptr, bfp(OFF_VTH), bfp(OFF_VTL), bv, 1.0f,
                                         HID, HID, HID, 0, 0);

    // 3) scores = Q K^T (scale folded into Q): per (b,h), M=N=2048, K=128
    dim3 gS(16, 16, BATCH * HEADS);
    gemm_mma<2><<<gS, 256, SMEM_BYTES>>>(bfp(OFF_QH), bfp(OFF_QL), bfp(OFF_KH), bfp(OFF_KL),
                                         sc, nullptr, nullptr, nullptr, 1.0f,
                                         HD, HD, HD, (long)SEQ * HD, (long)SEQ * HD);

    // 4) softmax + split to bf16 hi/lo probs
    softmax_split<<<BATCH * HEADS * SEQ, 256>>>(sc, u32(OFF_PH), u32(OFF_PL));

    // 5) PV: per (b,h), M=2048, N=128, K=2048 (NT against V^T)
    dim3 gPV(1, 16, BATCH * HEADS);
    gemm_mma<3><<<gPV, 256, SMEM_BYTES>>>(bfp(OFF_PH), bfp(OFF_PL), bfp(OFF_VTH), bfp(OFF_VTL),
                                          nullptr, bfp(OFF_AH), bfp(OFF_AL), nullptr, 1.0f,
                                          SEQ, SEQ, SEQ, (long)SEQ * SEQ, (long)HD * SEQ);

    // 6) out projection: M=4096, N=2048, K=2048 + bias -> fp32
    gemm_mma<4><<<gP, 256, SMEM_BYTES>>>(bfp(OFF_AH), bfp(OFF_AL), bfp(OFF_WOH), bfp(OFF_WOL),
                                         out, nullptr, nullptr, bo, 1.0f,
                                         HID, HID, HID, 0, 0);
}

// round 6
// speedup vs baseline: 2.8183x; 1.1148x over previous
#include <cuda_runtime.h>
#include <cuda_bf16.h>
#include <cstdint>
#include <cstddef>

// ============================================================================
// Problem constants
// ============================================================================
constexpr int SEQ = 2048, HID = 2048, HEADS = 16, HD = 128, BATCH = 2;
constexpr int NS = 2;                    // GEMM pipeline stages (2 CTAs/SM)
constexpr int TILEB  = 128 * 80;         // 128x32-bf16 tile, 80B padded rows
constexpr int STAGEB = 4 * TILEB;
constexpr int SMEM_BYTES = NS * STAGEB;  // 81920

// ============================================================================
// Device scratch pool
// ============================================================================
constexpr size_t MB = 1048576ull;
constexpr size_t OFF_XH  = 0,        OFF_XL  = 16*MB;
constexpr size_t OFF_WQH = 32*MB,    OFF_WQL = 40*MB;
constexpr size_t OFF_WKH = 48*MB,    OFF_WKL = 56*MB;
constexpr size_t OFF_WVH = 64*MB,    OFF_WVL = 72*MB;
constexpr size_t OFF_WOH = 80*MB,    OFF_WOL = 88*MB;
constexpr size_t OFF_QH  = 96*MB,    OFF_QL  = 112*MB;
constexpr size_t OFF_KH  = 128*MB,   OFF_KL  = 144*MB;
constexpr size_t OFF_VTH = 160*MB,   OFF_VTL = 176*MB;   // V^T [b][h][d][s]
constexpr size_t OFF_AH  = 192*MB,   OFF_AL  = 208*MB;   // attn [b*s][hid]
constexpr size_t POOL_SZ = 224*MB;

__device__ __align__(1024) unsigned char g_pool[POOL_SZ];

// ============================================================================
// Helpers
// ============================================================================
__device__ __forceinline__ uint32_t smem_u32(const void* p) {
    uint32_t a;
    asm("{ .reg .u64 t; cvta.to.shared.u64 t, %1; cvt.u32.u64 %0, t; }"
        : "=r"(a) : "l"(p));
    return a;
}
__device__ __forceinline__ void cp_async16(uint32_t dst, const void* src) {
    asm volatile("cp.async.cg.shared.global [%0], [%1], 16;"
                 :: "r"(dst), "l"(src) : "memory");
}
#define CP_COMMIT() asm volatile("cp.async.commit_group;" ::: "memory")
#define CP_WAIT(n)  asm volatile("cp.async.wait_group %0;" :: "n"(n) : "memory")

__device__ __forceinline__ void ldsm4(uint32_t r[4], uint32_t a) {
    asm volatile("ldmatrix.sync.aligned.m8n8.x4.shared.b16 {%0,%1,%2,%3}, [%4];"
                 : "=r"(r[0]), "=r"(r[1]), "=r"(r[2]), "=r"(r[3]) : "r"(a));
}
__device__ __forceinline__ void mma16816(float c[4], const uint32_t a[4],
                                         const uint32_t b0, const uint32_t b1) {
    asm volatile(
        "mma.sync.aligned.m16n8k16.row.col.f32.bf16.bf16.f32 "
        "{%0,%1,%2,%3}, {%4,%5,%6,%7}, {%8,%9}, {%0,%1,%2,%3};"
        : "+f"(c[0]), "+f"(c[1]), "+f"(c[2]), "+f"(c[3])
        : "r"(a[0]), "r"(a[1]), "r"(a[2]), "r"(a[3]), "r"(b0), "r"(b1));
}
__device__ __forceinline__ uint32_t bf2pack(float a, float b) {
    __nv_bfloat162 t;
    t.x = __float2bfloat16(a);
    t.y = __float2bfloat16(b);
    return *reinterpret_cast<uint32_t*>(&t);
}
__device__ __forceinline__ void split2(__nv_bfloat16* Ch, __nv_bfloat16* Cl,
                                       size_t idx, float v0, float v1) {
    float h0 = __bfloat162float(__float2bfloat16(v0));
    float h1 = __bfloat162float(__float2bfloat16(v1));
    *(uint32_t*)(Ch + idx) = bf2pack(h0, h1);
    *(uint32_t*)(Cl + idx) = bf2pack(v0 - h0, v1 - h1);
}
__device__ __forceinline__ uint32_t swz(uint32_t o) { return o ^ ((o >> 3) & 0x70); }

// ============================================================================
// bf16x3 mma.sync GEMM (same proven structure as R5).
// MODE 0: (acc+bias)*alpha -> bf16 h/l at q/k [b][h][s][d]
// MODE 1:  acc+bias        -> bf16 h/l TRANSPOSED vt [b][h][d][s]
// MODE 4:  acc+bias        -> fp32 out [m][n]
// ============================================================================
template <int MODE>
__global__ void __launch_bounds__(256, 2)
gemm_mma(const __nv_bfloat16* __restrict__ Ah, const __nv_bfloat16* __restrict__ Al,
         const __nv_bfloat16* __restrict__ Bh, const __nv_bfloat16* __restrict__ Bl,
         float* __restrict__ Cf,
         __nv_bfloat16* __restrict__ Ch, __nv_bfloat16* __restrict__ Cl,
         const float* __restrict__ bias, float alpha,
         int K, int lda, int ldb, long aZ, long bZ)
{
    extern __shared__ __align__(128) unsigned char smem[];
    const uint32_t sb = smem_u32(smem);
    const int tid = threadIdx.x, lane = tid & 31, wid = tid >> 5;
    const int wm = wid & 3;
    const int wn = wid >> 2;
    const int bx = blockIdx.x, by = blockIdx.y, bz = blockIdx.z;

    const __nv_bfloat16* pAh = Ah + (size_t)bz * aZ + (size_t)by * 128 * lda;
    const __nv_bfloat16* pAl = Al + (size_t)bz * aZ + (size_t)by * 128 * lda;
    const __nv_bfloat16* pBh = Bh + (size_t)bz * bZ + (size_t)bx * 128 * ldb;
    const __nv_bfloat16* pBl = Bl + (size_t)bz * bZ + (size_t)bx * 128 * ldb;

    const int frow = tid >> 2;
    const int fch  = tid & 3;
    const uint32_t fdst = (uint32_t)frow * 80 + (uint32_t)fch * 16;

    #define FILL_TILE(dstBase, g, ld) do {                                      \
        const char* _g = (const char*)(g) + ((size_t)_k0 + fch * 8) * 2;        \
        cp_async16((dstBase) + fdst, _g + (size_t)frow * (ld) * 2);             \
        cp_async16((dstBase) + fdst + 64 * 80, _g + (size_t)(frow + 64) * (ld) * 2); \
    } while (0)

    #define FILL_STAGE(IT) do {                                                 \
        const uint32_t _st = sb + (uint32_t)((IT) & 1) * STAGEB;                \
        const int _k0 = (IT) * 32;                                              \
        FILL_TILE(_st,             pAh, lda);                                   \
        FILL_TILE(_st + TILEB,     pAl, lda);                                   \
        FILL_TILE(_st + 2 * TILEB, pBh, ldb);                                   \
        FILL_TILE(_st + 3 * TILEB, pBl, ldb);                                   \
        CP_COMMIT();                                                            \
    } while (0)

    const uint32_t aOff = (uint32_t)(wm * 32 + (lane & 15)) * 80
                        + (uint32_t)((lane >> 4) & 1) * 16;
    const int nl = (lane & 7) + ((lane >> 4) & 1) * 8;
    const int kh = (lane >> 3) & 1;
    const uint32_t bOff = (uint32_t)(wn * 64 + nl) * 80 + (uint32_t)kh * 16;

    float acc[2][8][4];
    #pragma unroll
    for (int i = 0; i < 2; i++)
        #pragma unroll
        for (int j = 0; j < 8; j++)
            #pragma unroll
            for (int q = 0; q < 4; q++) acc[i][j][q] = 0.0f;

    const int NIT = K >> 5;
    FILL_STAGE(0);

    for (int it = 0; it < NIT; ++it) {
        if (it + 1 < NIT) { FILL_STAGE(it + 1); CP_WAIT(1); }
        else              { CP_WAIT(0); }
        __syncthreads();
        const uint32_t st = sb + (uint32_t)(it & 1) * STAGEB;
        #pragma unroll
        for (int ks = 0; ks < 2; ks++) {
            uint32_t ahf[2][4], alf[2][4];
            #pragma unroll
            for (int mf = 0; mf < 2; mf++) {
                ldsm4(ahf[mf], st + aOff + mf * (16 * 80) + ks * 32);
                ldsm4(alf[mf], st + TILEB + aOff + mf * (16 * 80) + ks * 32);
            }
            #pragma unroll
            for (int nq = 0; nq < 4; nq++) {
                uint32_t th[4], tl[4];
                ldsm4(th, st + 2 * TILEB + bOff + nq * (16 * 80) + ks * 32);
                ldsm4(tl, st + 3 * TILEB + bOff + nq * (16 * 80) + ks * 32);
                #pragma unroll
                for (int mf = 0; mf < 2; mf++) {
                    mma16816(acc[mf][2 * nq],     ahf[mf], th[0], th[1]);
                    mma16816(acc[mf][2 * nq],     ahf[mf], tl[0], tl[1]);
                    mma16816(acc[mf][2 * nq],     alf[mf], th[0], th[1]);
                    mma16816(acc[mf][2 * nq + 1], ahf[mf], th[2], th[3]);
                    mma16816(acc[mf][2 * nq + 1], ahf[mf], tl[2], tl[3]);
                    mma16816(acc[mf][2 * nq + 1], alf[mf], th[2], th[3]);
                }
            }
        }
        __syncthreads();
    }
    #undef FILL_STAGE
    #undef FILL_TILE

    const int mrow0 = wm * 32 + (lane >> 2);
    const int ncol0 = wn * 64 + (lane & 3) * 2;

    if (MODE == 1) {
        float* tb = (float*)smem;  // [128][132]
        #pragma unroll
        for (int mf = 0; mf < 2; mf++)
            #pragma unroll
            for (int nf = 0; nf < 8; nf++) {
                const int r = mrow0 + mf * 16;
                const int c = ncol0 + nf * 8;
                tb[r * 132 + c]           = acc[mf][nf][0];
                tb[r * 132 + c + 1]       = acc[mf][nf][1];
                tb[(r + 8) * 132 + c]     = acc[mf][nf][2];
                tb[(r + 8) * 132 + c + 1] = acc[mf][nf][3];
            }
        __syncthreads();
        const int d = tid & 127, sh = tid >> 7;
        const float bv = bias[bx * 128 + d];
        const int b = by >> 4;
        const size_t base = (((size_t)(b * HEADS + bx)) * HD + d) * SEQ
                          + (size_t)(by & 15) * 128 + sh * 64;
        #pragma unroll 8
        for (int s = 0; s < 64; s += 2) {
            float v0 = tb[(sh * 64 + s) * 132 + d] + bv;
            float v1 = tb[(sh * 64 + s + 1) * 132 + d] + bv;
            split2(Ch, Cl, base + s, v0, v1);
        }
        return;
    }

    #pragma unroll
    for (int mf = 0; mf < 2; mf++)
        #pragma unroll
        for (int nf = 0; nf < 8; nf++) {
            const int r = by * 128 + mrow0 + mf * 16;
            const int c = ncol0 + nf * 8;
            const float* a = acc[mf][nf];
            if (MODE == 4) {
                const float b0 = bias[bx * 128 + c], b1 = bias[bx * 128 + c + 1];
                float* p0 = Cf + (size_t)r * HID + (size_t)bx * 128 + c;
                float2 w0; w0.x = a[0] + b0; w0.y = a[1] + b1;
                float2 w1; w1.x = a[2] + b0; w1.y = a[3] + b1;
                *(float2*)p0 = w0;
                *(float2*)(p0 + (size_t)8 * HID) = w1;
            } else {  // MODE 0
                const int b = r >> 11, s = r & 2047;
                const float b0 = bias[bx * 128 + c], b1 = bias[bx * 128 + c + 1];
                const size_t base = (((size_t)(b * HEADS + bx)) * SEQ + s) * HD + c;
                split2(Ch, Cl, base, (a[0] + b0) * alpha, (a[1] + b1) * alpha);
                split2(Ch, Cl, base + (size_t)8 * HD,
                       (a[2] + b0) * alpha, (a[3] + b1) * alpha);
            }
        }
}

// ============================================================================
// Fused flash attention: per CTA one (q-tile 128) x (b,h); loop over 32
// kv-tiles of 64. Q/K/V/P in SW128-swizzled smem panels, bf16x3 MMAs,
// online softmax, O accumulated in registers.
// smem map: Q 0..64K (Qh p0/p1, Ql p0/p1, 16K each)
//           KV buf b @ 64K + b*64K: Kh p0/p1 (8K), Kl p0/p1 (8K), Vh 16K, Vl 16K
//           P @ 192K: Ph 16K, Pl 16K ; red @ 224K (128x2 fp32)
// ============================================================================
constexpr int FL_KV0  = 65536;
constexpr int FL_P    = 196608;
constexpr int FL_RED  = 229376;
constexpr int FL_SMEM = 230400;

__global__ void __launch_bounds__(256, 1)
flash_attn(const __nv_bfloat16* __restrict__ Qh_, const __nv_bfloat16* __restrict__ Ql_,
           const __nv_bfloat16* __restrict__ Kh_, const __nv_bfloat16* __restrict__ Kl_,
           const __nv_bfloat16* __restrict__ Vh_, const __nv_bfloat16* __restrict__ Vl_,
           __nv_bfloat16* __restrict__ Ah_, __nv_bfloat16* __restrict__ Al_)
{
    extern __shared__ __align__(128) unsigned char smem[];
    const uint32_t sb = smem_u32(smem);
    const int tid = threadIdx.x, lane = tid & 31, wid = tid >> 5;
    const int wm = wid & 3, wn = wid >> 2;
    const int qt = blockIdx.x, bh = blockIdx.y;

    const size_t qoff = ((size_t)bh * SEQ + (size_t)qt * 128) * HD;
    const size_t koff = (size_t)bh * SEQ * HD;
    const size_t voff = (size_t)bh * HD * SEQ;

    // ---- load Q tile (4 panels x 16KB) ----
    {
        const int r = tid >> 1;
        const size_t gq = qoff + (size_t)r * HD;
        #pragma unroll
        for (int j = 0; j < 4; j++) {
            const uint32_t cb = (uint32_t)(tid & 1) * 64 + j * 16;
            const uint32_t off = swz((uint32_t)r * 128 + cb);
            cp_async16(sb + off,         (const char*)(Qh_ + gq)      + cb);
            cp_async16(sb + 16384 + off, (const char*)(Qh_ + gq + 64) + cb);
            cp_async16(sb + 32768 + off, (const char*)(Ql_ + gq)      + cb);
            cp_async16(sb + 49152 + off, (const char*)(Ql_ + gq + 64) + cb);
        }
    }

    auto fill_kv = [&](int it) {
        const uint32_t bufb = sb + FL_KV0 + (uint32_t)(it & 1) * 65536;
        {   // K: 64 rows x 128 d (2 panels) h/l
            const int r = tid >> 2;
            const size_t gk = koff + ((size_t)it * 64 + r) * HD;
            #pragma unroll
            for (int j = 0; j < 2; j++) {
                const uint32_t cb = (uint32_t)(tid & 3) * 32 + j * 16;
                const uint32_t off = swz((uint32_t)r * 128 + cb);
                cp_async16(bufb + off,         (const char*)(Kh_ + gk)      + cb);
                cp_async16(bufb + 8192 + off,  (const char*)(Kh_ + gk + 64) + cb);
                cp_async16(bufb + 16384 + off, (const char*)(Kl_ + gk)      + cb);
                cp_async16(bufb + 24576 + off, (const char*)(Kl_ + gk + 64) + cb);
            }
        }
        {   // V^T: 128 d-rows x 64 kv cols, h/l
            const int r = tid >> 1;
            const size_t gv = voff + (size_t)r * SEQ + (size_t)it * 64;
            #pragma unroll
            for (int j = 0; j < 4; j++) {
                const uint32_t cb = (uint32_t)(tid & 1) * 64 + j * 16;
                const uint32_t off = swz((uint32_t)r * 128 + cb);
                cp_async16(bufb + 32768 + off, (const char*)(Vh_ + gv) + cb);
                cp_async16(bufb + 49152 + off, (const char*)(Vl_ + gv) + cb);
            }
        }
        CP_COMMIT();
    };

    fill_kv(0);  // group also covers the Q loads above

    const int nl = (lane & 7) + ((lane >> 4) & 1) * 8;
    const int kh = (lane >> 3) & 1;
    const uint32_t arow = (uint32_t)(wm * 32 + (lane & 15));
    const uint32_t acol16 = (uint32_t)(((lane >> 4) & 1) * 16);

    float O[2][8][4];
    #pragma unroll
    for (int i = 0; i < 2; i++)
        #pragma unroll
        for (int j = 0; j < 8; j++)
            #pragma unroll
            for (int q = 0; q < 4; q++) O[i][j][q] = 0.0f;
    float mrun[4], lrun[4];
    #pragma unroll
    for (int i = 0; i < 4; i++) { mrun[i] = -1e30f; lrun[i] = 0.0f; }

    float* red = (float*)(smem + FL_RED);  // [128][2]

    for (int it = 0; it < SEQ / 64; ++it) {
        CP_WAIT(0);
        __syncthreads();
        if (it + 1 < SEQ / 64) fill_kv(it + 1);
        const uint32_t kb = sb + FL_KV0 + (uint32_t)(it & 1) * 65536;

        // ---- S = Q K^T (K=128, bf16x3) ----
        float S[2][4][4];
        #pragma unroll
        for (int mf = 0; mf < 2; mf++)
            #pragma unroll
            for (int nf = 0; nf < 4; nf++)
                #pragma unroll
                for (int q = 0; q < 4; q++) S[mf][nf][q] = 0.0f;

        #pragma unroll
        for (int ks = 0; ks < 8; ++ks) {
            const uint32_t qp = sb + (uint32_t)(ks >> 2) * 16384;
            const uint32_t kp = kb + (uint32_t)(ks >> 2) * 8192;
            const uint32_t ac = acol16 + (uint32_t)(ks & 3) * 32;
            uint32_t qh[2][4], ql[2][4];
            #pragma unroll
            for (int mf = 0; mf < 2; mf++) {
                const uint32_t ro = (arow + mf * 16) * 128 + ac;
                ldsm4(qh[mf], qp + swz(ro));
                ldsm4(ql[mf], qp + 32768 + swz(ro));
            }
            uint32_t bh2[4][2], bl2[4][2];
            #pragma unroll
            for (int g = 0; g < 2; g++) {
                const uint32_t ro = (uint32_t)(wn * 32 + nl + g * 16) * 128
                                  + kh * 16 + (ks & 3) * 32;
                uint32_t t[4];
                ldsm4(t, kp + swz(ro));
                bh2[2*g][0] = t[0]; bh2[2*g][1] = t[1];
                bh2[2*g+1][0] = t[2]; bh2[2*g+1][1] = t[3];
                ldsm4(t, kp + 16384 + swz(ro));
                bl2[2*g][0] = t[0]; bl2[2*g][1] = t[1];
                bl2[2*g+1][0] = t[2]; bl2[2*g+1][1] = t[3];
            }
            #pragma unroll
            for (int mf = 0; mf < 2; mf++)
                #pragma unroll
                for (int nf = 0; nf < 4; nf++) {
                    mma16816(S[mf][nf], qh[mf], bh2[nf][0], bh2[nf][1]);
                    mma16816(S[mf][nf], qh[mf], bl2[nf][0], bl2[nf][1]);
                    mma16816(S[mf][nf], ql[mf], bh2[nf][0], bh2[nf][1]);
                }
        }

        // ---- online softmax ----
        float mloc[4];
        #pragma unroll
        for (int i = 0; i < 4; i++) {
            const int mf = i >> 1, ch = i & 1;
            float v = -1e30f;
            #pragma unroll
            for (int nf = 0; nf < 4; nf++) {
                v = fmaxf(v, S[mf][nf][ch*2]);
                v = fmaxf(v, S[mf][nf][ch*2+1]);
            }
            v = fmaxf(v, __shfl_xor_sync(0xffffffffu, v, 1));
            v = fmaxf(v, __shfl_xor_sync(0xffffffffu, v, 2));
            mloc[i] = v;
        }
        if ((lane & 3) == 0) {
            #pragma unroll
            for (int i = 0; i < 4; i++) {
                const int r = wm*32 + (i>>1)*16 + (lane>>2) + (i&1)*8;
                red[r*2 + wn] = mloc[i];
            }
        }
        __syncthreads();
        float fac[4], mnew[4];
        #pragma unroll
        for (int i = 0; i < 4; i++) {
            const int r = wm*32 + (i>>1)*16 + (lane>>2) + (i&1)*8;
            const float mt = fmaxf(red[r*2], red[r*2+1]);
            mnew[i] = fmaxf(mrun[i], mt);
            fac[i] = __expf(mrun[i] - mnew[i]);
            mrun[i] = mnew[i];
        }
        float rs[4] = {0.f, 0.f, 0.f, 0.f};
        #pragma unroll
        for (int mf = 0; mf < 2; mf++)
            #pragma unroll
            for (int nf = 0; nf < 4; nf++)
                #pragma unroll
                for (int ch = 0; ch < 2; ch++) {
                    const int i = mf*2 + ch;
                    const float p0 = __expf(S[mf][nf][ch*2]   - mnew[i]);
                    const float p1 = __expf(S[mf][nf][ch*2+1] - mnew[i]);
                    rs[i] += p0 + p1;
                    const uint32_t r = wm*32 + mf*16 + (lane>>2) + ch*8;
                    const uint32_t cB = (uint32_t)(wn*64 + nf*16 + (lane&3)*4);
                    const uint32_t off = swz(r * 128 + cB);
                    const float h0 = __bfloat162float(__float2bfloat16(p0));
                    const float h1 = __bfloat162float(__float2bfloat16(p1));
                    *(uint32_t*)(smem + FL_P + off)         = bf2pack(h0, h1);
                    *(uint32_t*)(smem + FL_P + 16384 + off) = bf2pack(p0-h0, p1-h1);
                }
        #pragma unroll
        for (int i = 0; i < 4; i++) {
            float v = rs[i];
            v += __shfl_xor_sync(0xffffffffu, v, 1);
            v += __shfl_xor_sync(0xffffffffu, v, 2);
            lrun[i] = lrun[i] * fac[i] + v;
        }
        #pragma unroll
        for (int mf = 0; mf < 2; mf++)
            #pragma unroll
            for (int nf = 0; nf < 8; nf++)
                #pragma unroll
                for (int q = 0; q < 4; q++)
                    O[mf][nf][q] *= fac[mf*2 + (q>>1)];
        __syncthreads();

        // ---- O += P V (k=64, bf16x3) ----
        #pragma unroll
        for (int ks = 0; ks < 4; ++ks) {
            const uint32_t ac = acol16 + (uint32_t)ks * 32;
            uint32_t ph[2][4], pl[2][4];
            #pragma unroll
            for (int mf = 0; mf < 2; mf++) {
                const uint32_t ro = (arow + mf * 16) * 128 + ac;
                ldsm4(ph[mf], sb + FL_P + swz(ro));
                ldsm4(pl[mf], sb + FL_P + 16384 + swz(ro));
            }
            uint32_t vh2[8][2], vl2[8][2];
            #pragma unroll
            for (int g = 0; g < 4; g++) {
                const uint32_t ro = (uint32_t)(wn * 64 + nl + g * 16) * 128
                                  + kh * 16 + ks * 32;
                uint32_t t[4];
                ldsm4(t, kb + 32768 + swz(ro));
                vh2[2*g][0] = t[0]; vh2[2*g][1] = t[1];
                vh2[2*g+1][0] = t[2]; vh2[2*g+1][1] = t[3];
                ldsm4(t, kb + 49152 + swz(ro));
                vl2[2*g][0] = t[0]; vl2[2*g][1] = t[1];
                vl2[2*g+1][0] = t[2]; vl2[2*g+1][1] = t[3];
            }
            #pragma unroll
            for (int mf = 0; mf < 2; mf++)
                #pragma unroll
                for (int nf = 0; nf < 8; nf++) {
                    mma16816(O[mf][nf], ph[mf], vh2[nf][0], vh2[nf][1]);
                    mma16816(O[mf][nf], ph[mf], vl2[nf][0], vl2[nf][1]);
                    mma16816(O[mf][nf], pl[mf], vh2[nf][0], vh2[nf][1]);
                }
        }
    }

    // ---- final: combine l across wn, normalize, write ----
    __syncthreads();
    if ((lane & 3) == 0) {
        #pragma unroll
        for (int i = 0; i < 4; i++) {
            const int r = wm*32 + (i>>1)*16 + (lane>>2) + (i&1)*8;
            red[r*2 + wn] = lrun[i];
        }
    }
    __syncthreads();
    float linv[4];
    #pragma unroll
    for (int i = 0; i < 4; i++) {
        const int r = wm*32 + (i>>1)*16 + (lane>>2) + (i&1)*8;
        linv[i] = 1.0f / (red[r*2] + red[r*2+1]);
    }

    const int b = bh >> 4, h = bh & 15;
    #pragma unroll
    for (int mf = 0; mf < 2; mf++)
        #pragma unroll
        for (int nf = 0; nf < 8; nf++) {
            const int r = qt*128 + wm*32 + mf*16 + (lane>>2);
            const int c = wn*64 + nf*8 + (lane&3)*2;
            const size_t base = ((size_t)b * SEQ + r) * HID + (size_t)h * 128 + c;
            split2(Ah_, Al_, base,
                   O[mf][nf][0] * linv[mf*2], O[mf][nf][1] * linv[mf*2]);
            split2(Ah_, Al_, base + (size_t)8 * HID,
                   O[mf][nf][2] * linv[mf*2+1], O[mf][nf][3] * linv[mf*2+1]);
        }
}

// ============================================================================
// fp32 -> bf16 hi/lo split conversion
// ============================================================================
__global__ __launch_bounds__(256)
void conv_split(const float4* __restrict__ in, uint32_t* __restrict__ hi,
                uint32_t* __restrict__ lo, int n4)
{
    int i = blockIdx.x * blockDim.x + threadIdx.x;
    if (i >= n4) return;
    float4 v = in[i];
    float hx = __bfloat162float(__float2bfloat16(v.x));
    float hy = __bfloat162float(__float2bfloat16(v.y));
    float hz = __bfloat162float(__float2bfloat16(v.z));
    float hw = __bfloat162float(__float2bfloat16(v.w));
    hi[2 * i]     = bf2pack(hx, hy);
    hi[2 * i + 1] = bf2pack(hz, hw);
    lo[2 * i]     = bf2pack(v.x - hx, v.y - hy);
    lo[2 * i + 1] = bf2pack(v.z - hz, v.w - hw);
}

// ============================================================================
// kernel_launch
// ============================================================================
extern "C" void kernel_launch(void* const* d_in, const int* in_sizes, int n_in,
                              void* d_out, int out_size)
{
    const float* x  = (const float*)d_in[0];
    const float* Wq = (const float*)d_in[1];
    const float* bq = (const float*)d_in[2];
    const float* Wk = (const float*)d_in[3];
    const float* bk = (const float*)d_in[4];
    const float* Wv = (const float*)d_in[5];
    const float* bv = (const float*)d_in[6];
    const float* Wo = (const float*)d_in[7];
    const float* bo = (const float*)d_in[8];
    float* out = (float*)d_out;

    unsigned char* pool;
    cudaGetSymbolAddress((void**)&pool, g_pool);
    auto bfp = [&](size_t off) { return (__nv_bfloat16*)(pool + off); };
    auto u32 = [&](size_t off) { return (uint32_t*)(pool + off); };

    cudaFuncSetAttribute(gemm_mma<0>, cudaFuncAttributeMaxDynamicSharedMemorySize, SMEM_BYTES);
    cudaFuncSetAttribute(gemm_mma<1>, cudaFuncAttributeMaxDynamicSharedMemorySize, SMEM_BYTES);
    cudaFuncSetAttribute(gemm_mma<4>, cudaFuncAttributeMaxDynamicSharedMemorySize, SMEM_BYTES);
    cudaFuncSetAttribute(flash_attn,  cudaFuncAttributeMaxDynamicSharedMemorySize, FL_SMEM);

    const float scale = 0.08838834764831845f;  // 1/sqrt(128)

    // 1) split-convert inputs & weights
    conv_split<<<8192, 256>>>((const float4*)x,  u32(OFF_XH),  u32(OFF_XL), 2097152);
    conv_split<<<4096, 256>>>((const float4*)Wq, u32(OFF_WQH), u32(OFF_WQL), 1048576);
    conv_split<<<4096, 256>>>((const float4*)Wk, u32(OFF_WKH), u32(OFF_WKL), 1048576);
    conv_split<<<4096, 256>>>((const float4*)Wv, u32(OFF_WVH), u32(OFF_WVL), 1048576);
    conv_split<<<4096, 256>>>((const float4*)Wo, u32(OFF_WOH), u32(OFF_WOL), 1048576);

    // 2) projections
    dim3 gP(16, 32, 1);
    gemm_mma<0><<<gP, 256, SMEM_BYTES>>>(bfp(OFF_XH), bfp(OFF_XL), bfp(OFF_WQH), bfp(OFF_WQL),
                                         nullptr, bfp(OFF_QH), bfp(OFF_QL), bq, scale,
                                         HID, HID, HID, 0, 0);
    gemm_mma<0><<<gP, 256, SMEM_BYTES>>>(bfp(OFF_XH), bfp(OFF_XL), bfp(OFF_WKH), bfp(OFF_WKL),
                                         nullptr, bfp(OFF_KH), bfp(OFF_KL), bk, 1.0f,
                                         HID, HID, HID, 0, 0);
    gemm_mma<1><<<gP, 256, SMEM_BYTES>>>(bfp(OFF_XH), bfp(OFF_XL), bfp(OFF_WVH), bfp(OFF_WVL),
                                         nullptr, bfp(OFF_VTH), bfp(OFF_VTL), bv, 1.0f,
                                         HID, HID, HID, 0, 0);

    // 3) fused flash attention (scores + softmax + PV)
    dim3 gF(SEQ / 128, BATCH * HEADS, 1);
    flash_attn<<<gF, 256, FL_SMEM>>>(bfp(OFF_QH), bfp(OFF_QL),
                                     bfp(OFF_KH), bfp(OFF_KL),
                                     bfp(OFF_VTH), bfp(OFF_VTL),
                                     bfp(OFF_AH), bfp(OFF_AL));

    // 4) out projection
    gemm_mma<4><<<gP, 256, SMEM_BYTES>>>(bfp(OFF_AH), bfp(OFF_AL), bfp(OFF_WOH), bfp(OFF_WOL),
                                         out, nullptr, nullptr, bo, 1.0f,
                                         HID, HID, HID, 0, 0);
}

// round 7
// speedup vs baseline: 2.9508x; 1.0470x over previous
#include <cuda_runtime.h>
#include <cuda_bf16.h>
#include <cstdint>
#include <cstddef>

// ============================================================================
// Problem constants
// ============================================================================
constexpr int SEQ = 2048, HID = 2048, HEADS = 16, HD = 128, BATCH = 2;
constexpr int TILEB  = 128 * 80;         // 128x32-bf16 tile, 80B padded rows
constexpr int STAGEB = 4 * TILEB;
constexpr int SMEM_BYTES = 2 * STAGEB;   // 81920 (2 stages, 2 CTAs/SM)

// ============================================================================
// Device scratch pool
// ============================================================================
constexpr size_t MB = 1048576ull;
constexpr size_t OFF_XH  = 0,        OFF_XL  = 16*MB;
constexpr size_t OFF_WQH = 32*MB,    OFF_WQL = 40*MB;
constexpr size_t OFF_WKH = 48*MB,    OFF_WKL = 56*MB;
constexpr size_t OFF_WVH = 64*MB,    OFF_WVL = 72*MB;
constexpr size_t OFF_WOH = 80*MB,    OFF_WOL = 88*MB;
constexpr size_t OFF_QH  = 96*MB,    OFF_QL  = 112*MB;
constexpr size_t OFF_KH  = 128*MB,   OFF_KL  = 144*MB;
constexpr size_t OFF_VTH = 160*MB,   OFF_VTL = 176*MB;   // V^T [b][h][d][s]
constexpr size_t OFF_AH  = 192*MB,   OFF_AL  = 208*MB;   // attn [b*s][hid]
constexpr size_t POOL_SZ = 224*MB;

__device__ __align__(1024) unsigned char g_pool[POOL_SZ];

// ============================================================================
// Helpers
// ============================================================================
__device__ __forceinline__ uint32_t smem_u32(const void* p) {
    uint32_t a;
    asm("{ .reg .u64 t; cvta.to.shared.u64 t, %1; cvt.u32.u64 %0, t; }"
        : "=r"(a) : "l"(p));
    return a;
}
__device__ __forceinline__ void cp_async16(uint32_t dst, const void* src) {
    asm volatile("cp.async.cg.shared.global [%0], [%1], 16;"
                 :: "r"(dst), "l"(src) : "memory");
}
#define CP_COMMIT() asm volatile("cp.async.commit_group;" ::: "memory")
#define CP_WAIT(n)  asm volatile("cp.async.wait_group %0;" :: "n"(n) : "memory")

__device__ __forceinline__ void ldsm4(uint32_t r[4], uint32_t a) {
    asm volatile("ldmatrix.sync.aligned.m8n8.x4.shared.b16 {%0,%1,%2,%3}, [%4];"
                 : "=r"(r[0]), "=r"(r[1]), "=r"(r[2]), "=r"(r[3]) : "r"(a));
}
__device__ __forceinline__ void mma16816(float c[4], const uint32_t a[4],
                                         const uint32_t b0, const uint32_t b1) {
    asm volatile(
        "mma.sync.aligned.m16n8k16.row.col.f32.bf16.bf16.f32 "
        "{%0,%1,%2,%3}, {%4,%5,%6,%7}, {%8,%9}, {%0,%1,%2,%3};"
        : "+f"(c[0]), "+f"(c[1]), "+f"(c[2]), "+f"(c[3])
        : "r"(a[0]), "r"(a[1]), "r"(a[2]), "r"(a[3]), "r"(b0), "r"(b1));
}
__device__ __forceinline__ uint32_t bf2pack(float a, float b) {
    __nv_bfloat162 t;
    t.x = __float2bfloat16(a);
    t.y = __float2bfloat16(b);
    return *reinterpret_cast<uint32_t*>(&t);
}
__device__ __forceinline__ void split2(__nv_bfloat16* Ch, __nv_bfloat16* Cl,
                                       size_t idx, float v0, float v1) {
    float h0 = __bfloat162float(__float2bfloat16(v0));
    float h1 = __bfloat162float(__float2bfloat16(v1));
    *(uint32_t*)(Ch + idx) = bf2pack(h0, h1);
    *(uint32_t*)(Cl + idx) = bf2pack(v0 - h0, v1 - h1);
}
__device__ __forceinline__ uint32_t swz(uint32_t o) { return o ^ ((o >> 3) & 0x70); }

// ============================================================================
// Shared bf16x3 GEMM mainloop: 128x128 tile, BK=32, 256 thr, 2-stage cp.async,
// one-ahead register double-buffering of B fragments.
// ============================================================================
__device__ __forceinline__ void mma_mainloop(
    uint32_t sb, const unsigned char* smem_unused,
    const __nv_bfloat16* pAh, const __nv_bfloat16* pAl,
    const __nv_bfloat16* pBh, const __nv_bfloat16* pBl,
    int lda, int ldb, int K, int tid, float acc[2][8][4])
{
    const int lane = tid & 31, wid = tid >> 5;
    const int wm = wid & 3, wn = wid >> 2;
    const int frow = tid >> 2, fch = tid & 3;
    const uint32_t fdst = (uint32_t)frow * 80 + (uint32_t)fch * 16;

    #define FILL_TILE(dstBase, g, ld) do {                                      \
        const char* _g = (const char*)(g) + ((size_t)_k0 + fch * 8) * 2;        \
        cp_async16((dstBase) + fdst, _g + (size_t)frow * (ld) * 2);             \
        cp_async16((dstBase) + fdst + 64 * 80, _g + (size_t)(frow + 64) * (ld) * 2); \
    } while (0)

    #define FILL_STAGE(IT) do {                                                 \
        const uint32_t _st = sb + (uint32_t)((IT) & 1) * STAGEB;                \
        const int _k0 = (IT) * 32;                                              \
        FILL_TILE(_st,             pAh, lda);                                   \
        FILL_TILE(_st + TILEB,     pAl, lda);                                   \
        FILL_TILE(_st + 2 * TILEB, pBh, ldb);                                   \
        FILL_TILE(_st + 3 * TILEB, pBl, ldb);                                   \
        CP_COMMIT();                                                            \
    } while (0)

    const uint32_t aOff = (uint32_t)(wm * 32 + (lane & 15)) * 80
                        + (uint32_t)((lane >> 4) & 1) * 16;
    const int nl = (lane & 7) + ((lane >> 4) & 1) * 8;
    const int kh = (lane >> 3) & 1;
    const uint32_t bOff = (uint32_t)(wn * 64 + nl) * 80 + (uint32_t)kh * 16;

    const int NIT = K >> 5;
    FILL_STAGE(0);

    for (int it = 0; it < NIT; ++it) {
        if (it + 1 < NIT) { FILL_STAGE(it + 1); CP_WAIT(1); }
        else              { CP_WAIT(0); }
        __syncthreads();
        const uint32_t st = sb + (uint32_t)(it & 1) * STAGEB;
        #pragma unroll
        for (int ks = 0; ks < 2; ks++) {
            uint32_t th[2][4], tl[2][4];
            // B group 0 issued first so its latency overlaps the A loads
            ldsm4(th[0], st + 2 * TILEB + bOff + ks * 32);
            ldsm4(tl[0], st + 3 * TILEB + bOff + ks * 32);
            uint32_t ahf[2][4], alf[2][4];
            #pragma unroll
            for (int mf = 0; mf < 2; mf++) {
                ldsm4(ahf[mf], st + aOff + mf * (16 * 80) + ks * 32);
                ldsm4(alf[mf], st + TILEB + aOff + mf * (16 * 80) + ks * 32);
            }
            #pragma unroll
            for (int nq = 0; nq < 4; nq++) {
                const int cur = nq & 1;
                if (nq < 3) {  // one-ahead prefetch of next B group
                    ldsm4(th[cur ^ 1],
                          st + 2 * TILEB + bOff + (nq + 1) * (16 * 80) + ks * 32);
                    ldsm4(tl[cur ^ 1],
                          st + 3 * TILEB + bOff + (nq + 1) * (16 * 80) + ks * 32);
                }
                #pragma unroll
                for (int mf = 0; mf < 2; mf++) {
                    mma16816(acc[mf][2 * nq],     ahf[mf], th[cur][0], th[cur][1]);
                    mma16816(acc[mf][2 * nq],     ahf[mf], tl[cur][0], tl[cur][1]);
                    mma16816(acc[mf][2 * nq],     alf[mf], th[cur][0], th[cur][1]);
                    mma16816(acc[mf][2 * nq + 1], ahf[mf], th[cur][2], th[cur][3]);
                    mma16816(acc[mf][2 * nq + 1], ahf[mf], tl[cur][2], tl[cur][3]);
                    mma16816(acc[mf][2 * nq + 1], alf[mf], th[cur][2], th[cur][3]);
                }
            }
        }
        __syncthreads();
    }
    #undef FILL_STAGE
    #undef FILL_TILE
}

// ============================================================================
// Fused QKV projection: grid (16, 32, 3); z=0 -> Q (scaled), z=1 -> K,
// z=2 -> V with transposed epilogue into V^T.
// ============================================================================
__global__ void __launch_bounds__(256, 2)
qkv_mma(const __nv_bfloat16* __restrict__ Xh, const __nv_bfloat16* __restrict__ Xl,
        const __nv_bfloat16* __restrict__ Wqh, const __nv_bfloat16* __restrict__ Wql,
        const __nv_bfloat16* __restrict__ Wkh, const __nv_bfloat16* __restrict__ Wkl,
        const __nv_bfloat16* __restrict__ Wvh, const __nv_bfloat16* __restrict__ Wvl,
        const float* __restrict__ bq, const float* __restrict__ bk,
        const float* __restrict__ bv,
        __nv_bfloat16* __restrict__ Qh, __nv_bfloat16* __restrict__ Ql,
        __nv_bfloat16* __restrict__ Kh, __nv_bfloat16* __restrict__ Kl,
        __nv_bfloat16* __restrict__ VTh, __nv_bfloat16* __restrict__ VTl,
        float scale)
{
    extern __shared__ __align__(128) unsigned char smem[];
    const uint32_t sb = smem_u32(smem);
    const int tid = threadIdx.x, lane = tid & 31, wid = tid >> 5;
    const int wm = wid & 3, wn = wid >> 2;
    const int bx = blockIdx.x, by = blockIdx.y, bz = blockIdx.z;

    const __nv_bfloat16* Bh = (bz == 0) ? Wqh : (bz == 1) ? Wkh : Wvh;
    const __nv_bfloat16* Bl = (bz == 0) ? Wql : (bz == 1) ? Wkl : Wvl;
    const float* bias = (bz == 0) ? bq : (bz == 1) ? bk : bv;
    const float alpha = (bz == 0) ? scale : 1.0f;

    const __nv_bfloat16* pAh = Xh + (size_t)by * 128 * HID;
    const __nv_bfloat16* pAl = Xl + (size_t)by * 128 * HID;
    const __nv_bfloat16* pBh = Bh + (size_t)bx * 128 * HID;
    const __nv_bfloat16* pBl = Bl + (size_t)bx * 128 * HID;

    float acc[2][8][4];
    #pragma unroll
    for (int i = 0; i < 2; i++)
        #pragma unroll
        for (int j = 0; j < 8; j++)
            #pragma unroll
            for (int q = 0; q < 4; q++) acc[i][j][q] = 0.0f;

    mma_mainloop(sb, smem, pAh, pAl, pBh, pBl, HID, HID, HID, tid, acc);

    const int mrow0 = wm * 32 + (lane >> 2);
    const int ncol0 = wn * 64 + (lane & 3) * 2;

    if (bz == 2) {
        // transposed epilogue into V^T [b][h][d][s]
        float* tb = (float*)smem;  // [128][132]
        #pragma unroll
        for (int mf = 0; mf < 2; mf++)
            #pragma unroll
            for (int nf = 0; nf < 8; nf++) {
                const int r = mrow0 + mf * 16;
                const int c = ncol0 + nf * 8;
                tb[r * 132 + c]           = acc[mf][nf][0];
                tb[r * 132 + c + 1]       = acc[mf][nf][1];
                tb[(r + 8) * 132 + c]     = acc[mf][nf][2];
                tb[(r + 8) * 132 + c + 1] = acc[mf][nf][3];
            }
        __syncthreads();
        const int d = tid & 127, sh = tid >> 7;
        const float bvv = bias[bx * 128 + d];
        const int b = by >> 4;
        const size_t base = (((size_t)(b * HEADS + bx)) * HD + d) * SEQ
                          + (size_t)(by & 15) * 128 + sh * 64;
        #pragma unroll 8
        for (int s = 0; s < 64; s += 2) {
            float v0 = tb[(sh * 64 + s) * 132 + d] + bvv;
            float v1 = tb[(sh * 64 + s + 1) * 132 + d] + bvv;
            split2(VTh, VTl, base + s, v0, v1);
        }
        return;
    }

    __nv_bfloat16* Ch = (bz == 0) ? Qh : Kh;
    __nv_bfloat16* Cl = (bz == 0) ? Ql : Kl;
    #pragma unroll
    for (int mf = 0; mf < 2; mf++)
        #pragma unroll
        for (int nf = 0; nf < 8; nf++) {
            const int r = by * 128 + mrow0 + mf * 16;
            const int c = ncol0 + nf * 8;
            const float* a = acc[mf][nf];
            const int b = r >> 11, s = r & 2047;
            const float b0 = bias[bx * 128 + c], b1 = bias[bx * 128 + c + 1];
            const size_t base = (((size_t)(b * HEADS + bx)) * SEQ + s) * HD + c;
            split2(Ch, Cl, base, (a[0] + b0) * alpha, (a[1] + b1) * alpha);
            split2(Ch, Cl, base + (size_t)8 * HD,
                   (a[2] + b0) * alpha, (a[3] + b1) * alpha);
        }
}

// ============================================================================
// Output projection GEMM: fp32 out = A @ Wo^T + bo
// ============================================================================
__global__ void __launch_bounds__(256, 2)
gemm_out(const __nv_bfloat16* __restrict__ Ah, const __nv_bfloat16* __restrict__ Al,
         const __nv_bfloat16* __restrict__ Bh, const __nv_bfloat16* __restrict__ Bl,
         float* __restrict__ Cf, const float* __restrict__ bias)
{
    extern __shared__ __align__(128) unsigned char smem[];
    const uint32_t sb = smem_u32(smem);
    const int tid = threadIdx.x, lane = tid & 31, wid = tid >> 5;
    const int wm = wid & 3, wn = wid >> 2;
    const int bx = blockIdx.x, by = blockIdx.y;

    const __nv_bfloat16* pAh = Ah + (size_t)by * 128 * HID;
    const __nv_bfloat16* pAl = Al + (size_t)by * 128 * HID;
    const __nv_bfloat16* pBh = Bh + (size_t)bx * 128 * HID;
    const __nv_bfloat16* pBl = Bl + (size_t)bx * 128 * HID;

    float acc[2][8][4];
    #pragma unroll
    for (int i = 0; i < 2; i++)
        #pragma unroll
        for (int j = 0; j < 8; j++)
            #pragma unroll
            for (int q = 0; q < 4; q++) acc[i][j][q] = 0.0f;

    mma_mainloop(sb, smem, pAh, pAl, pBh, pBl, HID, HID, HID, tid, acc);

    const int mrow0 = wm * 32 + (lane >> 2);
    const int ncol0 = wn * 64 + (lane & 3) * 2;
    #pragma unroll
    for (int mf = 0; mf < 2; mf++)
        #pragma unroll
        for (int nf = 0; nf < 8; nf++) {
            const int r = by * 128 + mrow0 + mf * 16;
            const int c = ncol0 + nf * 8;
            const float* a = acc[mf][nf];
            const float b0 = bias[bx * 128 + c], b1 = bias[bx * 128 + c + 1];
            float* p0 = Cf + (size_t)r * HID + (size_t)bx * 128 + c;
            float2 w0; w0.x = a[0] + b0; w0.y = a[1] + b1;
            float2 w1; w1.x = a[2] + b0; w1.y = a[3] + b1;
            *(float2*)p0 = w0;
            *(float2*)(p0 + (size_t)8 * HID) = w1;
        }
}

// ============================================================================
// Fused flash attention (identical to R6 passing version)
// ============================================================================
constexpr int FL_KV0  = 65536;
constexpr int FL_P    = 196608;
constexpr int FL_RED  = 229376;
constexpr int FL_SMEM = 230400;

__global__ void __launch_bounds__(256, 1)
flash_attn(const __nv_bfloat16* __restrict__ Qh_, const __nv_bfloat16* __restrict__ Ql_,
           const __nv_bfloat16* __restrict__ Kh_, const __nv_bfloat16* __restrict__ Kl_,
           const __nv_bfloat16* __restrict__ Vh_, const __nv_bfloat16* __restrict__ Vl_,
           __nv_bfloat16* __restrict__ Ah_, __nv_bfloat16* __restrict__ Al_)
{
    extern __shared__ __align__(128) unsigned char smem[];
    const uint32_t sb = smem_u32(smem);
    const int tid = threadIdx.x, lane = tid & 31, wid = tid >> 5;
    const int wm = wid & 3, wn = wid >> 2;
    const int qt = blockIdx.x, bh = blockIdx.y;

    const size_t qoff = ((size_t)bh * SEQ + (size_t)qt * 128) * HD;
    const size_t koff = (size_t)bh * SEQ * HD;
    const size_t voff = (size_t)bh * HD * SEQ;

    {
        const int r = tid >> 1;
        const size_t gq = qoff + (size_t)r * HD;
        #pragma unroll
        for (int j = 0; j < 4; j++) {
            const uint32_t cb = (uint32_t)(tid & 1) * 64 + j * 16;
            const uint32_t off = swz((uint32_t)r * 128 + cb);
            cp_async16(sb + off,         (const char*)(Qh_ + gq)      + cb);
            cp_async16(sb + 16384 + off, (const char*)(Qh_ + gq + 64) + cb);
            cp_async16(sb + 32768 + off, (const char*)(Ql_ + gq)      + cb);
            cp_async16(sb + 49152 + off, (const char*)(Ql_ + gq + 64) + cb);
        }
    }

    auto fill_kv = [&](int it) {
        const uint32_t bufb = sb + FL_KV0 + (uint32_t)(it & 1) * 65536;
        {
            const int r = tid >> 2;
            const size_t gk = koff + ((size_t)it * 64 + r) * HD;
            #pragma unroll
            for (int j = 0; j < 2; j++) {
                const uint32_t cb = (uint32_t)(tid & 3) * 32 + j * 16;
                const uint32_t off = swz((uint32_t)r * 128 + cb);
                cp_async16(bufb + off,         (const char*)(Kh_ + gk)      + cb);
                cp_async16(bufb + 8192 + off,  (const char*)(Kh_ + gk + 64) + cb);
                cp_async16(bufb + 16384 + off, (const char*)(Kl_ + gk)      + cb);
                cp_async16(bufb + 24576 + off, (const char*)(Kl_ + gk + 64) + cb);
            }
        }
        {
            const int r = tid >> 1;
            const size_t gv = voff + (size_t)r * SEQ + (size_t)it * 64;
            #pragma unroll
            for (int j = 0; j < 4; j++) {
                const uint32_t cb = (uint32_t)(tid & 1) * 64 + j * 16;
                const uint32_t off = swz((uint32_t)r * 128 + cb);
                cp_async16(bufb + 32768 + off, (const char*)(Vh_ + gv) + cb);
                cp_async16(bufb + 49152 + off, (const char*)(Vl_ + gv) + cb);
            }
        }
        CP_COMMIT();
    };

    fill_kv(0);

    const int nl = (lane & 7) + ((lane >> 4) & 1) * 8;
    const int kh = (lane >> 3) & 1;
    const uint32_t arow = (uint32_t)(wm * 32 + (lane & 15));
    const uint32_t acol16 = (uint32_t)(((lane >> 4) & 1) * 16);

    float O[2][8][4];
    #pragma unroll
    for (int i = 0; i < 2; i++)
        #pragma unroll
        for (int j = 0; j < 8; j++)
            #pragma unroll
            for (int q = 0; q < 4; q++) O[i][j][q] = 0.0f;
    float mrun[4], lrun[4];
    #pragma unroll
    for (int i = 0; i < 4; i++) { mrun[i] = -1e30f; lrun[i] = 0.0f; }

    float* red = (float*)(smem + FL_RED);

    for (int it = 0; it < SEQ / 64; ++it) {
        CP_WAIT(0);
        __syncthreads();
        if (it + 1 < SEQ / 64) fill_kv(it + 1);
        const uint32_t kb = sb + FL_KV0 + (uint32_t)(it & 1) * 65536;

        float S[2][4][4];
        #pragma unroll
        for (int mf = 0; mf < 2; mf++)
            #pragma unroll
            for (int nf = 0; nf < 4; nf++)
                #pragma unroll
                for (int q = 0; q < 4; q++) S[mf][nf][q] = 0.0f;

        #pragma unroll
        for (int ks = 0; ks < 8; ++ks) {
            const uint32_t qp = sb + (uint32_t)(ks >> 2) * 16384;
            const uint32_t kp = kb + (uint32_t)(ks >> 2) * 8192;
            const uint32_t ac = acol16 + (uint32_t)(ks & 3) * 32;
            uint32_t qh[2][4], ql[2][4];
            #pragma unroll
            for (int mf = 0; mf < 2; mf++) {
                const uint32_t ro = (arow + mf * 16) * 128 + ac;
                ldsm4(qh[mf], qp + swz(ro));
                ldsm4(ql[mf], qp + 32768 + swz(ro));
            }
            uint32_t bh2[4][2], bl2[4][2];
            #pragma unroll
            for (int g = 0; g < 2; g++) {
                const uint32_t ro = (uint32_t)(wn * 32 + nl + g * 16) * 128
                                  + kh * 16 + (ks & 3) * 32;
                uint32_t t[4];
                ldsm4(t, kp + swz(ro));
                bh2[2*g][0] = t[0]; bh2[2*g][1] = t[1];
                bh2[2*g+1][0] = t[2]; bh2[2*g+1][1] = t[3];
                ldsm4(t, kp + 16384 + swz(ro));
                bl2[2*g][0] = t[0]; bl2[2*g][1] = t[1];
                bl2[2*g+1][0] = t[2]; bl2[2*g+1][1] = t[3];
            }
            #pragma unroll
            for (int mf = 0; mf < 2; mf++)
                #pragma unroll
                for (int nf = 0; nf < 4; nf++) {
                    mma16816(S[mf][nf], qh[mf], bh2[nf][0], bh2[nf][1]);
                    mma16816(S[mf][nf], qh[mf], bl2[nf][0], bl2[nf][1]);
                    mma16816(S[mf][nf], ql[mf], bh2[nf][0], bh2[nf][1]);
                }
        }

        float mloc[4];
        #pragma unroll
        for (int i = 0; i < 4; i++) {
            const int mf = i >> 1, ch = i & 1;
            float v = -1e30f;
            #pragma unroll
            for (int nf = 0; nf < 4; nf++) {
                v = fmaxf(v, S[mf][nf][ch*2]);
                v = fmaxf(v, S[mf][nf][ch*2+1]);
            }
            v = fmaxf(v, __shfl_xor_sync(0xffffffffu, v, 1));
            v = fmaxf(v, __shfl_xor_sync(0xffffffffu, v, 2));
            mloc[i] = v;
        }
        if ((lane & 3) == 0) {
            #pragma unroll
            for (int i = 0; i < 4; i++) {
                const int r = wm*32 + (i>>1)*16 + (lane>>2) + (i&1)*8;
                red[r*2 + wn] = mloc[i];
            }
        }
        __syncthreads();
        float fac[4], mnew[4];
        #pragma unroll
        for (int i = 0; i < 4; i++) {
            const int r = wm*32 + (i>>1)*16 + (lane>>2) + (i&1)*8;
            const float mt = fmaxf(red[r*2], red[r*2+1]);
            mnew[i] = fmaxf(mrun[i], mt);
            fac[i] = __expf(mrun[i] - mnew[i]);
            mrun[i] = mnew[i];
        }
        float rs[4] = {0.f, 0.f, 0.f, 0.f};
        #pragma unroll
        for (int mf = 0; mf < 2; mf++)
            #pragma unroll
            for (int nf = 0; nf < 4; nf++)
                #pragma unroll
                for (int ch = 0; ch < 2; ch++) {
                    const int i = mf*2 + ch;
                    const float p0 = __expf(S[mf][nf][ch*2]   - mnew[i]);
                    const float p1 = __expf(S[mf][nf][ch*2+1] - mnew[i]);
                    rs[i] += p0 + p1;
                    const uint32_t r = wm*32 + mf*16 + (lane>>2) + ch*8;
                    const uint32_t cB = (uint32_t)(wn*64 + nf*16 + (lane&3)*4);
                    const uint32_t off = swz(r * 128 + cB);
                    const float h0 = __bfloat162float(__float2bfloat16(p0));
                    const float h1 = __bfloat162float(__float2bfloat16(p1));
                    *(uint32_t*)(smem + FL_P + off)         = bf2pack(h0, h1);
                    *(uint32_t*)(smem + FL_P + 16384 + off) = bf2pack(p0-h0, p1-h1);
                }
        #pragma unroll
        for (int i = 0; i < 4; i++) {
            float v = rs[i];
            v += __shfl_xor_sync(0xffffffffu, v, 1);
            v += __shfl_xor_sync(0xffffffffu, v, 2);
            lrun[i] = lrun[i] * fac[i] + v;
        }
        #pragma unroll
        for (int mf = 0; mf < 2; mf++)
            #pragma unroll
            for (int nf = 0; nf < 8; nf++)
                #pragma unroll
                for (int q = 0; q < 4; q++)
                    O[mf][nf][q] *= fac[mf*2 + (q>>1)];
        __syncthreads();

        #pragma unroll
        for (int ks = 0; ks < 4; ++ks) {
            const uint32_t ac = acol16 + (uint32_t)ks * 32;
            uint32_t ph[2][4], pl[2][4];
            #pragma unroll
            for (int mf = 0; mf < 2; mf++) {
                const uint32_t ro = (arow + mf * 16) * 128 + ac;
                ldsm4(ph[mf], sb + FL_P + swz(ro));
                ldsm4(pl[mf], sb + FL_P + 16384 + swz(ro));
            }
            uint32_t vh2[8][2], vl2[8][2];
            #pragma unroll
            for (int g = 0; g < 4; g++) {
                const uint32_t ro = (uint32_t)(wn * 64 + nl + g * 16) * 128
                                  + kh * 16 + ks * 32;
                uint32_t t[4];
                ldsm4(t, kb + 32768 + swz(ro));
                vh2[2*g][0] = t[0]; vh2[2*g][1] = t[1];
                vh2[2*g+1][0] = t[2]; vh2[2*g+1][1] = t[3];
                ldsm4(t, kb + 49152 + swz(ro));
                vl2[2*g][0] = t[0]; vl2[2*g][1] = t[1];
                vl2[2*g+1][0] = t[2]; vl2[2*g+1][1] = t[3];
            }
            #pragma unroll
            for (int mf = 0; mf < 2; mf++)
                #pragma unroll
                for (int nf = 0; nf < 8; nf++) {
                    mma16816(O[mf][nf], ph[mf], vh2[nf][0], vh2[nf][1]);
                    mma16816(O[mf][nf], ph[mf], vl2[nf][0], vl2[nf][1]);
                    mma16816(O[mf][nf], pl[mf], vh2[nf][0], vh2[nf][1]);
                }
        }
    }

    __syncthreads();
    if ((lane & 3) == 0) {
        #pragma unroll
        for (int i = 0; i < 4; i++) {
            const int r = wm*32 + (i>>1)*16 + (lane>>2) + (i&1)*8;
            red[r*2 + wn] = lrun[i];
        }
    }
    __syncthreads();
    float linv[4];
    #pragma unroll
    for (int i = 0; i < 4; i++) {
        const int r = wm*32 + (i>>1)*16 + (lane>>2) + (i&1)*8;
        linv[i] = 1.0f / (red[r*2] + red[r*2+1]);
    }

    const int b = bh >> 4, h = bh & 15;
    #pragma unroll
    for (int mf = 0; mf < 2; mf++)
        #pragma unroll
        for (int nf = 0; nf < 8; nf++) {
            const int r = qt*128 + wm*32 + mf*16 + (lane>>2);
            const int c = wn*64 + nf*8 + (lane&3)*2;
            const size_t base = ((size_t)b * SEQ + r) * HID + (size_t)h * 128 + c;
            split2(Ah_, Al_, base,
                   O[mf][nf][0] * linv[mf*2], O[mf][nf][1] * linv[mf*2]);
            split2(Ah_, Al_, base + (size_t)8 * HID,
                   O[mf][nf][2] * linv[mf*2+1], O[mf][nf][3] * linv[mf*2+1]);
        }
}

// ============================================================================
// fp32 -> bf16 hi/lo split conversion
// ============================================================================
__global__ __launch_bounds__(256)
void conv_split(const float4* __restrict__ in, uint32_t* __restrict__ hi,
                uint32_t* __restrict__ lo, int n4)
{
    int i = blockIdx.x * blockDim.x + threadIdx.x;
    if (i >= n4) return;
    float4 v = in[i];
    float hx = __bfloat162float(__float2bfloat16(v.x));
    float hy = __bfloat162float(__float2bfloat16(v.y));
    float hz = __bfloat162float(__float2bfloat16(v.z));
    float hw = __bfloat162float(__float2bfloat16(v.w));
    hi[2 * i]     = bf2pack(hx, hy);
    hi[2 * i + 1] = bf2pack(hz, hw);
    lo[2 * i]     = bf2pack(v.x - hx, v.y - hy);
    lo[2 * i + 1] = bf2pack(v.z - hz, v.w - hw);
}

// ============================================================================
// kernel_launch
// ============================================================================
extern "C" void kernel_launch(void* const* d_in, const int* in_sizes, int n_in,
                              void* d_out, int out_size)
{
    const float* x  = (const float*)d_in[0];
    const float* Wq = (const float*)d_in[1];
    const float* bq = (const float*)d_in[2];
    const float* Wk = (const float*)d_in[3];
    const float* bk = (const float*)d_in[4];
    const float* Wv = (const float*)d_in[5];
    const float* bv = (const float*)d_in[6];
    const float* Wo = (const float*)d_in[7];
    const float* bo = (const float*)d_in[8];
    float* out = (float*)d_out;

    unsigned char* pool;
    cudaGetSymbolAddress((void**)&pool, g_pool);
    auto bfp = [&](size_t off) { return (__nv_bfloat16*)(pool + off); };
    auto u32 = [&](size_t off) { return (uint32_t*)(pool + off); };

    cudaFuncSetAttribute(qkv_mma,    cudaFuncAttributeMaxDynamicSharedMemorySize, SMEM_BYTES);
    cudaFuncSetAttribute(gemm_out,   cudaFuncAttributeMaxDynamicSharedMemorySize, SMEM_BYTES);
    cudaFuncSetAttribute(flash_attn, cudaFuncAttributeMaxDynamicSharedMemorySize, FL_SMEM);

    const float scale = 0.08838834764831845f;  // 1/sqrt(128)

    // 1) split-convert inputs & weights
    conv_split<<<8192, 256>>>((const float4*)x,  u32(OFF_XH),  u32(OFF_XL), 2097152);
    conv_split<<<4096, 256>>>((const float4*)Wq, u32(OFF_WQH), u32(OFF_WQL), 1048576);
    conv_split<<<4096, 256>>>((const float4*)Wk, u32(OFF_WKH), u32(OFF_WKL), 1048576);
    conv_split<<<4096, 256>>>((const float4*)Wv, u32(OFF_WVH), u32(OFF_WVL), 1048576);
    conv_split<<<4096, 256>>>((const float4*)Wo, u32(OFF_WOH), u32(OFF_WOL), 1048576);

    // 2) fused QKV projections (one launch, z = {Q, K, V})
    dim3 gQKV(16, 32, 3);
    qkv_mma<<<gQKV, 256, SMEM_BYTES>>>(
        bfp(OFF_XH), bfp(OFF_XL),
        bfp(OFF_WQH), bfp(OFF_WQL), bfp(OFF_WKH), bfp(OFF_WKL),
        bfp(OFF_WVH), bfp(OFF_WVL),
        bq, bk, bv,
        bfp(OFF_QH), bfp(OFF_QL), bfp(OFF_KH), bfp(OFF_KL),
        bfp(OFF_VTH), bfp(OFF_VTL), scale);

    // 3) fused flash attention
    dim3 gF(SEQ / 128, BATCH * HEADS, 1);
    flash_attn<<<gF, 256, FL_SMEM>>>(bfp(OFF_QH), bfp(OFF_QL),
                                     bfp(OFF_KH), bfp(OFF_KL),
                                     bfp(OFF_VTH), bfp(OFF_VTL),
                                     bfp(OFF_AH), bfp(OFF_AL));

    // 4) output projection
    dim3 gO(16, 32, 1);
    gemm_out<<<gO, 256, SMEM_BYTES>>>(bfp(OFF_AH), bfp(OFF_AL),
                                      bfp(OFF_WOH), bfp(OFF_WOL), out, bo);
}

// round 8
// speedup vs baseline: 4.4131x; 1.4956x over previous
#include <cuda_runtime.h>
#include <cuda_fp16.h>
#include <cstdint>
#include <cstddef>

// ============================================================================
// Problem constants
// ============================================================================
constexpr int SEQ = 2048, HID = 2048, HEADS = 16, HD = 128, BATCH = 2;
constexpr int TILEB  = 128 * 80;          // 128x32-fp16 tile, 80B padded rows
constexpr int STAGEB = 3 * TILEB;         // Ah, Al, Bh
constexpr int SMEM_BYTES = 67584;         // max(2*STAGEB=61440, transpose 128*132*4)

// ============================================================================
// Device scratch pool
// ============================================================================
constexpr size_t MB = 1048576ull;
constexpr size_t OFF_XH  = 0,       OFF_XL  = 16*MB;
constexpr size_t OFF_WQH = 32*MB;
constexpr size_t OFF_WKH = 40*MB;
constexpr size_t OFF_WVH = 48*MB;
constexpr size_t OFF_WOH = 56*MB;
constexpr size_t OFF_QH  = 64*MB,   OFF_QL  = 80*MB;   // Q fp16 hi/lo
constexpr size_t OFF_KH  = 96*MB;                       // K fp16 (rounded)
constexpr size_t OFF_VTH = 112*MB;                      // V^T fp16 (rounded)
constexpr size_t OFF_AH  = 128*MB,  OFF_AL  = 144*MB;  // attn fp16 hi/lo
constexpr size_t POOL_SZ = 160*MB;

__device__ __align__(1024) unsigned char g_pool[POOL_SZ];

// ============================================================================
// Helpers
// ============================================================================
__device__ __forceinline__ uint32_t smem_u32(const void* p) {
    uint32_t a;
    asm("{ .reg .u64 t; cvta.to.shared.u64 t, %1; cvt.u32.u64 %0, t; }"
        : "=r"(a) : "l"(p));
    return a;
}
__device__ __forceinline__ void cp_async16(uint32_t dst, const void* src) {
    asm volatile("cp.async.cg.shared.global [%0], [%1], 16;"
                 :: "r"(dst), "l"(src) : "memory");
}
#define CP_COMMIT() asm volatile("cp.async.commit_group;" ::: "memory")
#define CP_WAIT(n)  asm volatile("cp.async.wait_group %0;" :: "n"(n) : "memory")

__device__ __forceinline__ void ldsm4(uint32_t r[4], uint32_t a) {
    asm volatile("ldmatrix.sync.aligned.m8n8.x4.shared.b16 {%0,%1,%2,%3}, [%4];"
                 : "=r"(r[0]), "=r"(r[1]), "=r"(r[2]), "=r"(r[3]) : "r"(a));
}
__device__ __forceinline__ void mma16816(float c[4], const uint32_t a[4],
                                         const uint32_t b0, const uint32_t b1) {
    asm volatile(
        "mma.sync.aligned.m16n8k16.row.col.f32.f16.f16.f32 "
        "{%0,%1,%2,%3}, {%4,%5,%6,%7}, {%8,%9}, {%0,%1,%2,%3};"
        : "+f"(c[0]), "+f"(c[1]), "+f"(c[2]), "+f"(c[3])
        : "r"(a[0]), "r"(a[1]), "r"(a[2]), "r"(a[3]), "r"(b0), "r"(b1));
}
__device__ __forceinline__ uint32_t hf2pack(float a, float b) {
    __half2 t;
    t.x = __float2half_rn(a);
    t.y = __float2half_rn(b);
    return *reinterpret_cast<uint32_t*>(&t);
}
__device__ __forceinline__ void split2h(__half* Ch, __half* Cl,
                                        size_t idx, float v0, float v1) {
    float h0 = __half2float(__float2half_rn(v0));
    float h1 = __half2float(__float2half_rn(v1));
    *(uint32_t*)(Ch + idx) = hf2pack(h0, h1);
    *(uint32_t*)(Cl + idx) = hf2pack(v0 - h0, v1 - h1);
}
__device__ __forceinline__ uint32_t swz(uint32_t o) { return o ^ ((o >> 3) & 0x70); }

// ============================================================================
// fp16x2 GEMM mainloop: acc = (Ah+Al) @ Bh^T.  128x128 tile, BK=32, 256 thr,
// 2-stage cp.async, one-ahead B-fragment double buffering. 3 tiles per stage.
// ============================================================================
__device__ __forceinline__ void mma_mainloop(
    uint32_t sb,
    const __half* pAh, const __half* pAl, const __half* pBh,
    int lda, int ldb, int K, int tid, float acc[2][8][4])
{
    const int lane = tid & 31, wid = tid >> 5;
    const int wm = wid & 3, wn = wid >> 2;
    const int frow = tid >> 2, fch = tid & 3;
    const uint32_t fdst = (uint32_t)frow * 80 + (uint32_t)fch * 16;

    #define FILL_TILE(dstBase, g, ld) do {                                      \
        const char* _g = (const char*)(g) + ((size_t)_k0 + fch * 8) * 2;        \
        cp_async16((dstBase) + fdst, _g + (size_t)frow * (ld) * 2);             \
        cp_async16((dstBase) + fdst + 64 * 80, _g + (size_t)(frow + 64) * (ld) * 2); \
    } while (0)

    #define FILL_STAGE(IT) do {                                                 \
        const uint32_t _st = sb + (uint32_t)((IT) & 1) * STAGEB;                \
        const int _k0 = (IT) * 32;                                              \
        FILL_TILE(_st,             pAh, lda);                                   \
        FILL_TILE(_st + TILEB,     pAl, lda);                                   \
        FILL_TILE(_st + 2 * TILEB, pBh, ldb);                                   \
        CP_COMMIT();                                                            \
    } while (0)

    const uint32_t aOff = (uint32_t)(wm * 32 + (lane & 15)) * 80
                        + (uint32_t)((lane >> 4) & 1) * 16;
    const int nl = (lane & 7) + ((lane >> 4) & 1) * 8;
    const int kh = (lane >> 3) & 1;
    const uint32_t bOff = (uint32_t)(wn * 64 + nl) * 80 + (uint32_t)kh * 16;

    const int NIT = K >> 5;
    FILL_STAGE(0);

    for (int it = 0; it < NIT; ++it) {
        if (it + 1 < NIT) { FILL_STAGE(it + 1); CP_WAIT(1); }
        else              { CP_WAIT(0); }
        __syncthreads();
        const uint32_t st = sb + (uint32_t)(it & 1) * STAGEB;
        #pragma unroll
        for (int ks = 0; ks < 2; ks++) {
            uint32_t th[2][4];
            ldsm4(th[0], st + 2 * TILEB + bOff + ks * 32);
            uint32_t ahf[2][4], alf[2][4];
            #pragma unroll
            for (int mf = 0; mf < 2; mf++) {
                ldsm4(ahf[mf], st + aOff + mf * (16 * 80) + ks * 32);
                ldsm4(alf[mf], st + TILEB + aOff + mf * (16 * 80) + ks * 32);
            }
            #pragma unroll
            for (int nq = 0; nq < 4; nq++) {
                const int cur = nq & 1;
                if (nq < 3) {
                    ldsm4(th[cur ^ 1],
                          st + 2 * TILEB + bOff + (nq + 1) * (16 * 80) + ks * 32);
                }
                #pragma unroll
                for (int mf = 0; mf < 2; mf++) {
                    mma16816(acc[mf][2 * nq],     ahf[mf], th[cur][0], th[cur][1]);
                    mma16816(acc[mf][2 * nq],     alf[mf], th[cur][0], th[cur][1]);
                    mma16816(acc[mf][2 * nq + 1], ahf[mf], th[cur][2], th[cur][3]);
                    mma16816(acc[mf][2 * nq + 1], alf[mf], th[cur][2], th[cur][3]);
                }
            }
        }
        __syncthreads();
    }
    #undef FILL_STAGE
    #undef FILL_TILE
}

// ============================================================================
// Fused QKV projection: grid (16, 32, 3); z=0 -> Q (scaled, split fp16),
// z=1 -> K (rounded fp16), z=2 -> V transposed into V^T (rounded fp16).
// ============================================================================
__global__ void __launch_bounds__(256, 2)
qkv_mma(const __half* __restrict__ Xh, const __half* __restrict__ Xl,
        const __half* __restrict__ Wqh, const __half* __restrict__ Wkh,
        const __half* __restrict__ Wvh,
        const float* __restrict__ bq, const float* __restrict__ bk,
        const float* __restrict__ bv,
        __half* __restrict__ Qh, __half* __restrict__ Ql,
        __half* __restrict__ Kh, __half* __restrict__ VTh,
        float scale)
{
    extern __shared__ __align__(128) unsigned char smem[];
    const uint32_t sb = smem_u32(smem);
    const int tid = threadIdx.x, lane = tid & 31, wid = tid >> 5;
    const int wm = wid & 3, wn = wid >> 2;
    const int bx = blockIdx.x, by = blockIdx.y, bz = blockIdx.z;

    const __half* Bh = (bz == 0) ? Wqh : (bz == 1) ? Wkh : Wvh;
    const float* bias = (bz == 0) ? bq : (bz == 1) ? bk : bv;
    const float alpha = (bz == 0) ? scale : 1.0f;

    const __half* pAh = Xh + (size_t)by * 128 * HID;
    const __half* pAl = Xl + (size_t)by * 128 * HID;
    const __half* pBh = Bh + (size_t)bx * 128 * HID;

    float acc[2][8][4];
    #pragma unroll
    for (int i = 0; i < 2; i++)
        #pragma unroll
        for (int j = 0; j < 8; j++)
            #pragma unroll
            for (int q = 0; q < 4; q++) acc[i][j][q] = 0.0f;

    mma_mainloop(sb, pAh, pAl, pBh, HID, HID, HID, tid, acc);

    const int mrow0 = wm * 32 + (lane >> 2);
    const int ncol0 = wn * 64 + (lane & 3) * 2;

    if (bz == 2) {
        // transposed epilogue into V^T [b][h][d][s], rounded fp16
        float* tb = (float*)smem;  // [128][132]
        #pragma unroll
        for (int mf = 0; mf < 2; mf++)
            #pragma unroll
            for (int nf = 0; nf < 8; nf++) {
                const int r = mrow0 + mf * 16;
                const int c = ncol0 + nf * 8;
                tb[r * 132 + c]           = acc[mf][nf][0];
                tb[r * 132 + c + 1]       = acc[mf][nf][1];
                tb[(r + 8) * 132 + c]     = acc[mf][nf][2];
                tb[(r + 8) * 132 + c + 1] = acc[mf][nf][3];
            }
        __syncthreads();
        const int d = tid & 127, sh = tid >> 7;
        const float bvv = bias[bx * 128 + d];
        const int b = by >> 4;
        const size_t base = (((size_t)(b * HEADS + bx)) * HD + d) * SEQ
                          + (size_t)(by & 15) * 128 + sh * 64;
        #pragma unroll 8
        for (int s = 0; s < 64; s += 2) {
            float v0 = tb[(sh * 64 + s) * 132 + d] + bvv;
            float v1 = tb[(sh * 64 + s + 1) * 132 + d] + bvv;
            *(uint32_t*)(VTh + base + s) = hf2pack(v0, v1);
        }
        return;
    }

    #pragma unroll
    for (int mf = 0; mf < 2; mf++)
        #pragma unroll
        for (int nf = 0; nf < 8; nf++) {
            const int r = by * 128 + mrow0 + mf * 16;
            const int c = ncol0 + nf * 8;
            const float* a = acc[mf][nf];
            const int b = r >> 11, s = r & 2047;
            const float b0 = bias[bx * 128 + c], b1 = bias[bx * 128 + c + 1];
            const size_t base = (((size_t)(b * HEADS + bx)) * SEQ + s) * HD + c;
            if (bz == 0) {
                split2h(Qh, Ql, base, (a[0] + b0) * alpha, (a[1] + b1) * alpha);
                split2h(Qh, Ql, base + (size_t)8 * HD,
                        (a[2] + b0) * alpha, (a[3] + b1) * alpha);
            } else {
                *(uint32_t*)(Kh + base) = hf2pack(a[0] + b0, a[1] + b1);
                *(uint32_t*)(Kh + base + (size_t)8 * HD) = hf2pack(a[2] + b0, a[3] + b1);
            }
        }
}

// ============================================================================
// Output projection GEMM: fp32 out = (Ah+Al) @ Woh^T + bo
// ============================================================================
__global__ void __launch_bounds__(256, 2)
gemm_out(const __half* __restrict__ Ah, const __half* __restrict__ Al,
         const __half* __restrict__ Bh,
         float* __restrict__ Cf, const float* __restrict__ bias)
{
    extern __shared__ __align__(128) unsigned char smem[];
    const uint32_t sb = smem_u32(smem);
    const int tid = threadIdx.x, lane = tid & 31, wid = tid >> 5;
    const int wm = wid & 3, wn = wid >> 2;
    const int bx = blockIdx.x, by = blockIdx.y;

    const __half* pAh = Ah + (size_t)by * 128 * HID;
    const __half* pAl = Al + (size_t)by * 128 * HID;
    const __half* pBh = Bh + (size_t)bx * 128 * HID;

    float acc[2][8][4];
    #pragma unroll
    for (int i = 0; i < 2; i++)
        #pragma unroll
        for (int j = 0; j < 8; j++)
            #pragma unroll
            for (int q = 0; q < 4; q++) acc[i][j][q] = 0.0f;

    mma_mainloop(sb, pAh, pAl, pBh, HID, HID, HID, tid, acc);

    const int mrow0 = wm * 32 + (lane >> 2);
    const int ncol0 = wn * 64 + (lane & 3) * 2;
    #pragma unroll
    for (int mf = 0; mf < 2; mf++)
        #pragma unroll
        for (int nf = 0; nf < 8; nf++) {
            const int r = by * 128 + mrow0 + mf * 16;
            const int c = ncol0 + nf * 8;
            const float* a = acc[mf][nf];
            const float b0 = bias[bx * 128 + c], b1 = bias[bx * 128 + c + 1];
            float* p0 = Cf + (size_t)r * HID + (size_t)bx * 128 + c;
            float2 w0; w0.x = a[0] + b0; w0.y = a[1] + b1;
            float2 w1; w1.x = a[2] + b0; w1.y = a[3] + b1;
            *(float2*)p0 = w0;
            *(float2*)(p0 + (size_t)8 * HID) = w1;
        }
}

// ============================================================================
// Fused flash attention, fp16x2:
//   S = (Qh+Ql) K^T ; P split fp16 ; O += (Ph+Pl) V
// smem: Q 0..64K (Qh p0/p1, Ql p0/p1, 16K each)
//       KV buf b @ 64K + b*32K: Kh p0 (8K), Kh p1 (8K), V (16K)
//       P @ 128K: Ph 16K, Pl 16K ; red @ 160K
// ============================================================================
constexpr int FL_KV0  = 65536;
constexpr int FL_P    = 131072;
constexpr int FL_RED  = 163840;
constexpr int FL_SMEM = 164864;

__global__ void __launch_bounds__(256, 1)
flash_attn(const __half* __restrict__ Qh_, const __half* __restrict__ Ql_,
           const __half* __restrict__ Kh_, const __half* __restrict__ Vh_,
           __half* __restrict__ Ah_, __half* __restrict__ Al_)
{
    extern __shared__ __align__(128) unsigned char smem[];
    const uint32_t sb = smem_u32(smem);
    const int tid = threadIdx.x, lane = tid & 31, wid = tid >> 5;
    const int wm = wid & 3, wn = wid >> 2;
    const int qt = blockIdx.x, bh = blockIdx.y;

    const size_t qoff = ((size_t)bh * SEQ + (size_t)qt * 128) * HD;
    const size_t koff = (size_t)bh * SEQ * HD;
    const size_t voff = (size_t)bh * HD * SEQ;

    {
        const int r = tid >> 1;
        const size_t gq = qoff + (size_t)r * HD;
        #pragma unroll
        for (int j = 0; j < 4; j++) {
            const uint32_t cb = (uint32_t)(tid & 1) * 64 + j * 16;
            const uint32_t off = swz((uint32_t)r * 128 + cb);
            cp_async16(sb + off,         (const char*)(Qh_ + gq)      + cb);
            cp_async16(sb + 16384 + off, (const char*)(Qh_ + gq + 64) + cb);
            cp_async16(sb + 32768 + off, (const char*)(Ql_ + gq)      + cb);
            cp_async16(sb + 49152 + off, (const char*)(Ql_ + gq + 64) + cb);
        }
    }

    auto fill_kv = [&](int it) {
        const uint32_t bufb = sb + FL_KV0 + (uint32_t)(it & 1) * 32768;
        {   // K: 64 rows x 128 d, fp16, two 128B panels
            const int r = tid >> 2;
            const size_t gk = koff + ((size_t)it * 64 + r) * HD;
            #pragma unroll
            for (int j = 0; j < 2; j++) {
                const uint32_t cb = (uint32_t)(tid & 3) * 32 + j * 16;
                const uint32_t off = swz((uint32_t)r * 128 + cb);
                cp_async16(bufb + off,        (const char*)(Kh_ + gk)      + cb);
                cp_async16(bufb + 8192 + off, (const char*)(Kh_ + gk + 64) + cb);
            }
        }
        {   // V^T: 128 d-rows x 64 kv cols fp16 (128B rows)
            const int r = tid >> 1;
            const size_t gv = voff + (size_t)r * SEQ + (size_t)it * 64;
            #pragma unroll
            for (int j = 0; j < 2; j++) {
                const uint32_t cb = (uint32_t)(tid & 1) * 64 + j * 32;
                const uint32_t off0 = swz((uint32_t)r * 128 + cb);
                const uint32_t off1 = swz((uint32_t)r * 128 + cb + 16);
                cp_async16(bufb + 16384 + off0, (const char*)(Vh_ + gv) + cb);
                cp_async16(bufb + 16384 + off1, (const char*)(Vh_ + gv) + cb + 16);
            }
        }
        CP_COMMIT();
    };

    fill_kv(0);

    const int nl = (lane & 7) + ((lane >> 4) & 1) * 8;
    const int kh = (lane >> 3) & 1;
    const uint32_t arow = (uint32_t)(wm * 32 + (lane & 15));
    const uint32_t acol16 = (uint32_t)(((lane >> 4) & 1) * 16);

    float O[2][8][4];
    #pragma unroll
    for (int i = 0; i < 2; i++)
        #pragma unroll
        for (int j = 0; j < 8; j++)
            #pragma unroll
            for (int q = 0; q < 4; q++) O[i][j][q] = 0.0f;
    float mrun[4], lrun[4];
    #pragma unroll
    for (int i = 0; i < 4; i++) { mrun[i] = -1e30f; lrun[i] = 0.0f; }

    float* red = (float*)(smem + FL_RED);

    for (int it = 0; it < SEQ / 64; ++it) {
        CP_WAIT(0);
        __syncthreads();
        if (it + 1 < SEQ / 64) fill_kv(it + 1);
        const uint32_t kb = sb + FL_KV0 + (uint32_t)(it & 1) * 32768;

        float S[2][4][4];
        #pragma unroll
        for (int mf = 0; mf < 2; mf++)
            #pragma unroll
            for (int nf = 0; nf < 4; nf++)
                #pragma unroll
                for (int q = 0; q < 4; q++) S[mf][nf][q] = 0.0f;

        #pragma unroll
        for (int ks = 0; ks < 8; ++ks) {
            const uint32_t qp = sb + (uint32_t)(ks >> 2) * 16384;
            const uint32_t kp = kb + (uint32_t)(ks >> 2) * 8192;
            const uint32_t ac = acol16 + (uint32_t)(ks & 3) * 32;
            uint32_t qh[2][4], ql[2][4];
            #pragma unroll
            for (int mf = 0; mf < 2; mf++) {
                const uint32_t ro = (arow + mf * 16) * 128 + ac;
                ldsm4(qh[mf], qp + swz(ro));
                ldsm4(ql[mf], qp + 32768 + swz(ro));
            }
            uint32_t bh2[4][2];
            #pragma unroll
            for (int g = 0; g < 2; g++) {
                const uint32_t ro = (uint32_t)(wn * 32 + nl + g * 16) * 128
                                  + kh * 16 + (ks & 3) * 32;
                uint32_t t[4];
                ldsm4(t, kp + swz(ro));
                bh2[2*g][0] = t[0]; bh2[2*g][1] = t[1];
                bh2[2*g+1][0] = t[2]; bh2[2*g+1][1] = t[3];
            }
            #pragma unroll
            for (int mf = 0; mf < 2; mf++)
                #pragma unroll
                for (int nf = 0; nf < 4; nf++) {
                    mma16816(S[mf][nf], qh[mf], bh2[nf][0], bh2[nf][1]);
                    mma16816(S[mf][nf], ql[mf], bh2[nf][0], bh2[nf][1]);
                }
        }

        float mloc[4];
        #pragma unroll
        for (int i = 0; i < 4; i++) {
            const int mf = i >> 1, ch = i & 1;
            float v = -1e30f;
            #pragma unroll
            for (int nf = 0; nf < 4; nf++) {
                v = fmaxf(v, S[mf][nf][ch*2]);
                v = fmaxf(v, S[mf][nf][ch*2+1]);
            }
            v = fmaxf(v, __shfl_xor_sync(0xffffffffu, v, 1));
            v = fmaxf(v, __shfl_xor_sync(0xffffffffu, v, 2));
            mloc[i] = v;
        }
        if ((lane & 3) == 0) {
            #pragma unroll
            for (int i = 0; i < 4; i++) {
                const int r = wm*32 + (i>>1)*16 + (lane>>2) + (i&1)*8;
                red[r*2 + wn] = mloc[i];
            }
        }
        __syncthreads();
        float fac[4], mnew[4];
        #pragma unroll
        for (int i = 0; i < 4; i++) {
            const int r = wm*32 + (i>>1)*16 + (lane>>2) + (i&1)*8;
            const float mt = fmaxf(red[r*2], red[r*2+1]);
            mnew[i] = fmaxf(mrun[i], mt);
            fac[i] = __expf(mrun[i] - mnew[i]);
            mrun[i] = mnew[i];
        }
        float rs[4] = {0.f, 0.f, 0.f, 0.f};
        #pragma unroll
        for (int mf = 0; mf < 2; mf++)
            #pragma unroll
            for (int nf = 0; nf < 4; nf++)
                #pragma unroll
                for (int ch = 0; ch < 2; ch++) {
                    const int i = mf*2 + ch;
                    const float p0 = __expf(S[mf][nf][ch*2]   - mnew[i]);
                    const float p1 = __expf(S[mf][nf][ch*2+1] - mnew[i]);
                    rs[i] += p0 + p1;
                    const uint32_t r = wm*32 + mf*16 + (lane>>2) + ch*8;
                    const uint32_t cB = (uint32_t)(wn*64 + nf*16 + (lane&3)*4);
                    const uint32_t off = swz(r * 128 + cB);
                    const float h0 = __half2float(__float2half_rn(p0));
                    const float h1 = __half2float(__float2half_rn(p1));
                    *(uint32_t*)(smem + FL_P + off)         = hf2pack(h0, h1);
                    *(uint32_t*)(smem + FL_P + 16384 + off) = hf2pack(p0-h0, p1-h1);
                }
        #pragma unroll
        for (int i = 0; i < 4; i++) {
            float v = rs[i];
            v += __shfl_xor_sync(0xffffffffu, v, 1);
            v += __shfl_xor_sync(0xffffffffu, v, 2);
            lrun[i] = lrun[i] * fac[i] + v;
        }
        #pragma unroll
        for (int mf = 0; mf < 2; mf++)
            #pragma unroll
            for (int nf = 0; nf < 8; nf++)
                #pragma unroll
                for (int q = 0; q < 4; q++)
                    O[mf][nf][q] *= fac[mf*2 + (q>>1)];
        __syncthreads();

        #pragma unroll
        for (int ks = 0; ks < 4; ++ks) {
            const uint32_t ac = acol16 + (uint32_t)ks * 32;
            uint32_t ph[2][4], pl[2][4];
            #pragma unroll
            for (int mf = 0; mf < 2; mf++) {
                const uint32_t ro = (arow + mf * 16) * 128 + ac;
                ldsm4(ph[mf], sb + FL_P + swz(ro));
                ldsm4(pl[mf], sb + FL_P + 16384 + swz(ro));
            }
            uint32_t vh2[8][2];
            #pragma unroll
            for (int g = 0; g < 4; g++) {
                const uint32_t ro = (uint32_t)(wn * 64 + nl + g * 16) * 128
                                  + kh * 16 + ks * 32;
                uint32_t t[4];
                ldsm4(t, kb + 16384 + swz(ro));
                vh2[2*g][0] = t[0]; vh2[2*g][1] = t[1];
                vh2[2*g+1][0] = t[2]; vh2[2*g+1][1] = t[3];
            }
            #pragma unroll
            for (int mf = 0; mf < 2; mf++)
                #pragma unroll
                for (int nf = 0; nf < 8; nf++) {
                    mma16816(O[mf][nf], ph[mf], vh2[nf][0], vh2[nf][1]);
                    mma16816(O[mf][nf], pl[mf], vh2[nf][0], vh2[nf][1]);
                }
        }
    }

    __syncthreads();
    if ((lane & 3) == 0) {
        #pragma unroll
        for (int i = 0; i < 4; i++) {
            const int r = wm*32 + (i>>1)*16 + (lane>>2) + (i&1)*8;
            red[r*2 + wn] = lrun[i];
        }
    }
    __syncthreads();
    float linv[4];
    #pragma unroll
    for (int i = 0; i < 4; i++) {
        const int r = wm*32 + (i>>1)*16 + (lane>>2) + (i&1)*8;
        linv[i] = 1.0f / (red[r*2] + red[r*2+1]);
    }

    const int b = bh >> 4, h = bh & 15;
    #pragma unroll
    for (int mf = 0; mf < 2; mf++)
        #pragma unroll
        for (int nf = 0; nf < 8; nf++) {
            const int r = qt*128 + wm*32 + mf*16 + (lane>>2);
            const int c = wn*64 + nf*8 + (lane&3)*2;
            const size_t base = ((size_t)b * SEQ + r) * HID + (size_t)h * 128 + c;
            split2h(Ah_, Al_, base,
                    O[mf][nf][0] * linv[mf*2], O[mf][nf][1] * linv[mf*2]);
            split2h(Ah_, Al_, base + (size_t)8 * HID,
                    O[mf][nf][2] * linv[mf*2+1], O[mf][nf][3] * linv[mf*2+1]);
        }
}

// ============================================================================
// fp32 -> fp16 hi/lo split, and fp32 -> fp16 round-only conversions
// ============================================================================
__global__ __launch_bounds__(256)
void conv_split_h(const float4* __restrict__ in, uint32_t* __restrict__ hi,
                  uint32_t* __restrict__ lo, int n4)
{
    int i = blockIdx.x * blockDim.x + threadIdx.x;
    if (i >= n4) return;
    float4 v = in[i];
    float hx = __half2float(__float2half_rn(v.x));
    float hy = __half2float(__float2half_rn(v.y));
    float hz = __half2float(__float2half_rn(v.z));
    float hw = __half2float(__float2half_rn(v.w));
    hi[2 * i]     = hf2pack(hx, hy);
    hi[2 * i + 1] = hf2pack(hz, hw);
    lo[2 * i]     = hf2pack(v.x - hx, v.y - hy);
    lo[2 * i + 1] = hf2pack(v.z - hz, v.w - hw);
}

__global__ __launch_bounds__(256)
void conv_round_h(const float4* __restrict__ in, uint32_t* __restrict__ hi, int n4)
{
    int i = blockIdx.x * blockDim.x + threadIdx.x;
    if (i >= n4) return;
    float4 v = in[i];
    hi[2 * i]     = hf2pack(v.x, v.y);
    hi[2 * i + 1] = hf2pack(v.z, v.w);
}

// ============================================================================
// kernel_launch
// ============================================================================
extern "C" void kernel_launch(void* const* d_in, const int* in_sizes, int n_in,
                              void* d_out, int out_size)
{
    const float* x  = (const float*)d_in[0];
    const float* Wq = (const float*)d_in[1];
    const float* bq = (const float*)d_in[2];
    const float* Wk = (const float*)d_in[3];
    const float* bk = (const float*)d_in[4];
    const float* Wv = (const float*)d_in[5];
    const float* bv = (const float*)d_in[6];
    const float* Wo = (const float*)d_in[7];
    const float* bo = (const float*)d_in[8];
    float* out = (float*)d_out;

    unsigned char* pool;
    cudaGetSymbolAddress((void**)&pool, g_pool);
    auto hfp = [&](size_t off) { return (__half*)(pool + off); };
    auto u32 = [&](size_t off) { return (uint32_t*)(pool + off); };

    cudaFuncSetAttribute(qkv_mma,    cudaFuncAttributeMaxDynamicSharedMemorySize, SMEM_BYTES);
    cudaFuncSetAttribute(gemm_out,   cudaFuncAttributeMaxDynamicSharedMemorySize, SMEM_BYTES);
    cudaFuncSetAttribute(flash_attn, cudaFuncAttributeMaxDynamicSharedMemorySize, FL_SMEM);

    const float scale = 0.08838834764831845f;  // 1/sqrt(128)

    // 1) convert: X split fp16 hi/lo; weights rounded fp16
    conv_split_h<<<8192, 256>>>((const float4*)x, u32(OFF_XH), u32(OFF_XL), 2097152);
    conv_round_h<<<4096, 256>>>((const float4*)Wq, u32(OFF_WQH), 1048576);
    conv_round_h<<<4096, 256>>>((const float4*)Wk, u32(OFF_WKH), 1048576);
    conv_round_h<<<4096, 256>>>((const float4*)Wv, u32(OFF_WVH), 1048576);
    conv_round_h<<<4096, 256>>>((const float4*)Wo, u32(OFF_WOH), 1048576);

    // 2) fused QKV projections (one launch, z = {Q, K, V})
    dim3 gQKV(16, 32, 3);
    qkv_mma<<<gQKV, 256, SMEM_BYTES>>>(
        hfp(OFF_XH), hfp(OFF_XL),
        hfp(OFF_WQH), hfp(OFF_WKH), hfp(OFF_WVH),
        bq, bk, bv,
        hfp(OFF_QH), hfp(OFF_QL), hfp(OFF_KH), hfp(OFF_VTH), scale);

    // 3) fused flash attention
    dim3 gF(SEQ / 128, BATCH * HEADS, 1);
    flash_attn<<<gF, 256, FL_SMEM>>>(hfp(OFF_QH), hfp(OFF_QL),
                                     hfp(OFF_KH), hfp(OFF_VTH),
                                     hfp(OFF_AH), hfp(OFF_AL));

    // 4) output projection
    dim3 gO(16, 32, 1);
    gemm_out<<<gO, 256, SMEM_BYTES>>>(hfp(OFF_AH), hfp(OFF_AL),
                                      hfp(OFF_WOH), out, bo);
}

// round 9
// speedup vs baseline: 5.0058x; 1.1343x over previous
#include <cuda_runtime.h>
#include <cuda_fp16.h>
#include <cstdint>
#include <cstddef>

// ============================================================================
// Problem constants
// ============================================================================
constexpr int SEQ = 2048, HID = 2048, HEADS = 16, HD = 128, BATCH = 2;
constexpr int TILEB  = 128 * 80;          // 128x32-fp16 tile, 80B padded rows
constexpr int STAGEB = 3 * TILEB;         // Ah, Al, Bh
constexpr int SMEM_BYTES = 67584;         // max(2*STAGEB=61440, transpose 128*132*4)

// ============================================================================
// Device scratch pool
// ============================================================================
constexpr size_t MB = 1048576ull;
constexpr size_t OFF_XH  = 0,       OFF_XL  = 16*MB;
constexpr size_t OFF_WQH = 32*MB;
constexpr size_t OFF_WKH = 40*MB;
constexpr size_t OFF_WVH = 48*MB;
constexpr size_t OFF_WOH = 56*MB;
constexpr size_t OFF_QH  = 64*MB,   OFF_QL  = 80*MB;   // Q fp16 hi/lo
constexpr size_t OFF_KH  = 96*MB;                       // K fp16 (rounded)
constexpr size_t OFF_VTH = 112*MB;                      // V^T fp16 (rounded)
constexpr size_t OFF_AH  = 128*MB,  OFF_AL  = 144*MB;  // attn fp16 hi/lo
constexpr size_t POOL_SZ = 160*MB;

__device__ __align__(1024) unsigned char g_pool[POOL_SZ];

// ============================================================================
// Helpers
// ============================================================================
__device__ __forceinline__ uint32_t smem_u32(const void* p) {
    uint32_t a;
    asm("{ .reg .u64 t; cvta.to.shared.u64 t, %1; cvt.u32.u64 %0, t; }"
        : "=r"(a) : "l"(p));
    return a;
}
__device__ __forceinline__ void cp_async16(uint32_t dst, const void* src) {
    asm volatile("cp.async.cg.shared.global [%0], [%1], 16;"
                 :: "r"(dst), "l"(src) : "memory");
}
#define CP_COMMIT() asm volatile("cp.async.commit_group;" ::: "memory")
#define CP_WAIT(n)  asm volatile("cp.async.wait_group %0;" :: "n"(n) : "memory")

__device__ __forceinline__ void ldsm4(uint32_t r[4], uint32_t a) {
    asm volatile("ldmatrix.sync.aligned.m8n8.x4.shared.b16 {%0,%1,%2,%3}, [%4];"
                 : "=r"(r[0]), "=r"(r[1]), "=r"(r[2]), "=r"(r[3]) : "r"(a));
}
__device__ __forceinline__ void mma16816(float c[4], const uint32_t a[4],
                                         const uint32_t b0, const uint32_t b1) {
    asm volatile(
        "mma.sync.aligned.m16n8k16.row.col.f32.f16.f16.f32 "
        "{%0,%1,%2,%3}, {%4,%5,%6,%7}, {%8,%9}, {%0,%1,%2,%3};"
        : "+f"(c[0]), "+f"(c[1]), "+f"(c[2]), "+f"(c[3])
        : "r"(a[0]), "r"(a[1]), "r"(a[2]), "r"(a[3]), "r"(b0), "r"(b1));
}
__device__ __forceinline__ uint32_t hf2pack(float a, float b) {
    __half2 t;
    t.x = __float2half_rn(a);
    t.y = __float2half_rn(b);
    return *reinterpret_cast<uint32_t*>(&t);
}
__device__ __forceinline__ void split2h(__half* Ch, __half* Cl,
                                        size_t idx, float v0, float v1) {
    float h0 = __half2float(__float2half_rn(v0));
    float h1 = __half2float(__float2half_rn(v1));
    *(uint32_t*)(Ch + idx) = hf2pack(h0, h1);
    *(uint32_t*)(Cl + idx) = hf2pack(v0 - h0, v1 - h1);
}
__device__ __forceinline__ uint32_t swz(uint32_t o) { return o ^ ((o >> 3) & 0x70); }

// ============================================================================
// fp16 GEMM mainloop: acc = (Ah[+Al]) @ Bh^T.  128x128 tile, BK=32, 256 thr,
// 2-stage cp.async, one-ahead B-fragment double buffering.
// USE_AL=true: 2-product split-precision; false: single product.
// ============================================================================
template <bool USE_AL>
__device__ __forceinline__ void mma_mainloop(
    uint32_t sb,
    const __half* pAh, const __half* pAl, const __half* pBh,
    int lda, int ldb, int K, int tid, float acc[2][8][4])
{
    const int lane = tid & 31, wid = tid >> 5;
    const int wm = wid & 3, wn = wid >> 2;
    const int frow = tid >> 2, fch = tid & 3;
    const uint32_t fdst = (uint32_t)frow * 80 + (uint32_t)fch * 16;

    #define FILL_TILE(dstBase, g, ld) do {                                      \
        const char* _g = (const char*)(g) + ((size_t)_k0 + fch * 8) * 2;        \
        cp_async16((dstBase) + fdst, _g + (size_t)frow * (ld) * 2);             \
        cp_async16((dstBase) + fdst + 64 * 80, _g + (size_t)(frow + 64) * (ld) * 2); \
    } while (0)

    #define FILL_STAGE(IT) do {                                                 \
        const uint32_t _st = sb + (uint32_t)((IT) & 1) * STAGEB;                \
        const int _k0 = (IT) * 32;                                              \
        FILL_TILE(_st, pAh, lda);                                               \
        if (USE_AL) FILL_TILE(_st + TILEB, pAl, lda);                           \
        FILL_TILE(_st + 2 * TILEB, pBh, ldb);                                   \
        CP_COMMIT();                                                            \
    } while (0)

    const uint32_t aOff = (uint32_t)(wm * 32 + (lane & 15)) * 80
                        + (uint32_t)((lane >> 4) & 1) * 16;
    const int nl = (lane & 7) + ((lane >> 4) & 1) * 8;
    const int kh = (lane >> 3) & 1;
    const uint32_t bOff = (uint32_t)(wn * 64 + nl) * 80 + (uint32_t)kh * 16;

    const int NIT = K >> 5;
    FILL_STAGE(0);

    for (int it = 0; it < NIT; ++it) {
        if (it + 1 < NIT) { FILL_STAGE(it + 1); CP_WAIT(1); }
        else              { CP_WAIT(0); }
        __syncthreads();
        const uint32_t st = sb + (uint32_t)(it & 1) * STAGEB;
        #pragma unroll
        for (int ks = 0; ks < 2; ks++) {
            uint32_t th[2][4];
            ldsm4(th[0], st + 2 * TILEB + bOff + ks * 32);
            uint32_t ahf[2][4], alf[2][4];
            #pragma unroll
            for (int mf = 0; mf < 2; mf++) {
                ldsm4(ahf[mf], st + aOff + mf * (16 * 80) + ks * 32);
                if (USE_AL)
                    ldsm4(alf[mf], st + TILEB + aOff + mf * (16 * 80) + ks * 32);
            }
            #pragma unroll
            for (int nq = 0; nq < 4; nq++) {
                const int cur = nq & 1;
                if (nq < 3) {
                    ldsm4(th[cur ^ 1],
                          st + 2 * TILEB + bOff + (nq + 1) * (16 * 80) + ks * 32);
                }
                #pragma unroll
                for (int mf = 0; mf < 2; mf++) {
                    mma16816(acc[mf][2 * nq],     ahf[mf], th[cur][0], th[cur][1]);
                    if (USE_AL)
                        mma16816(acc[mf][2 * nq], alf[mf], th[cur][0], th[cur][1]);
                    mma16816(acc[mf][2 * nq + 1], ahf[mf], th[cur][2], th[cur][3]);
                    if (USE_AL)
                        mma16816(acc[mf][2 * nq + 1], alf[mf], th[cur][2], th[cur][3]);
                }
            }
        }
        __syncthreads();
    }
    #undef FILL_STAGE
    #undef FILL_TILE
}

// ============================================================================
// Fused QKV projection: grid (16, 32, 3);
// z=0 -> Q: 2-product (Xh+Xl)@Wq, scaled, split fp16 output
// z=1 -> K: 1-product Xh@Wk, rounded fp16 output
// z=2 -> V: 1-product Xh@Wv, transposed into V^T, rounded fp16 output
// ============================================================================
__global__ void __launch_bounds__(256, 2)
qkv_mma(const __half* __restrict__ Xh, const __half* __restrict__ Xl,
        const __half* __restrict__ Wqh, const __half* __restrict__ Wkh,
        const __half* __restrict__ Wvh,
        const float* __restrict__ bq, const float* __restrict__ bk,
        const float* __restrict__ bv,
        __half* __restrict__ Qh, __half* __restrict__ Ql,
        __half* __restrict__ Kh, __half* __restrict__ VTh,
        float scale)
{
    extern __shared__ __align__(128) unsigned char smem[];
    const uint32_t sb = smem_u32(smem);
    const int tid = threadIdx.x, lane = tid & 31, wid = tid >> 5;
    const int wm = wid & 3, wn = wid >> 2;
    const int bx = blockIdx.x, by = blockIdx.y, bz = blockIdx.z;

    const __half* Bh = (bz == 0) ? Wqh : (bz == 1) ? Wkh : Wvh;
    const float* bias = (bz == 0) ? bq : (bz == 1) ? bk : bv;

    const __half* pAh = Xh + (size_t)by * 128 * HID;
    const __half* pAl = Xl + (size_t)by * 128 * HID;
    const __half* pBh = Bh + (size_t)bx * 128 * HID;

    float acc[2][8][4];
    #pragma unroll
    for (int i = 0; i < 2; i++)
        #pragma unroll
        for (int j = 0; j < 8; j++)
            #pragma unroll
            for (int q = 0; q < 4; q++) acc[i][j][q] = 0.0f;

    if (bz == 0) mma_mainloop<true >(sb, pAh, pAl, pBh, HID, HID, HID, tid, acc);
    else         mma_mainloop<false>(sb, pAh, pAl, pBh, HID, HID, HID, tid, acc);

    const int mrow0 = wm * 32 + (lane >> 2);
    const int ncol0 = wn * 64 + (lane & 3) * 2;

    if (bz == 2) {
        // transposed epilogue into V^T [b][h][d][s], rounded fp16
        float* tb = (float*)smem;  // [128][132]
        #pragma unroll
        for (int mf = 0; mf < 2; mf++)
            #pragma unroll
            for (int nf = 0; nf < 8; nf++) {
                const int r = mrow0 + mf * 16;
                const int c = ncol0 + nf * 8;
                tb[r * 132 + c]           = acc[mf][nf][0];
                tb[r * 132 + c + 1]       = acc[mf][nf][1];
                tb[(r + 8) * 132 + c]     = acc[mf][nf][2];
                tb[(r + 8) * 132 + c + 1] = acc[mf][nf][3];
            }
        __syncthreads();
        const int d = tid & 127, sh = tid >> 7;
        const float bvv = bias[bx * 128 + d];
        const int b = by >> 4;
        const size_t base = (((size_t)(b * HEADS + bx)) * HD + d) * SEQ
                          + (size_t)(by & 15) * 128 + sh * 64;
        #pragma unroll 8
        for (int s = 0; s < 64; s += 2) {
            float v0 = tb[(sh * 64 + s) * 132 + d] + bvv;
            float v1 = tb[(sh * 64 + s + 1) * 132 + d] + bvv;
            *(uint32_t*)(VTh + base + s) = hf2pack(v0, v1);
        }
        return;
    }

    #pragma unroll
    for (int mf = 0; mf < 2; mf++)
        #pragma unroll
        for (int nf = 0; nf < 8; nf++) {
            const int r = by * 128 + mrow0 + mf * 16;
            const int c = ncol0 + nf * 8;
            const float* a = acc[mf][nf];
            const int b = r >> 11, s = r & 2047;
            const float b0 = bias[bx * 128 + c], b1 = bias[bx * 128 + c + 1];
            const size_t base = (((size_t)(b * HEADS + bx)) * SEQ + s) * HD + c;
            if (bz == 0) {
                split2h(Qh, Ql, base, (a[0] + b0) * scale, (a[1] + b1) * scale);
                split2h(Qh, Ql, base + (size_t)8 * HD,
                        (a[2] + b0) * scale, (a[3] + b1) * scale);
            } else {
                *(uint32_t*)(Kh + base) = hf2pack(a[0] + b0, a[1] + b1);
                *(uint32_t*)(Kh + base + (size_t)8 * HD) = hf2pack(a[2] + b0, a[3] + b1);
            }
        }
}

// ============================================================================
// Output projection GEMM: fp32 out = (Ah+Al) @ Woh^T + bo   (2-product)
// ============================================================================
__global__ void __launch_bounds__(256, 2)
gemm_out(const __half* __restrict__ Ah, const __half* __restrict__ Al,
         const __half* __restrict__ Bh,
         float* __restrict__ Cf, const float* __restrict__ bias)
{
    extern __shared__ __align__(128) unsigned char smem[];
    const uint32_t sb = smem_u32(smem);
    const int tid = threadIdx.x, lane = tid & 31, wid = tid >> 5;
    const int wm = wid & 3, wn = wid >> 2;
    const int bx = blockIdx.x, by = blockIdx.y;

    const __half* pAh = Ah + (size_t)by * 128 * HID;
    const __half* pAl = Al + (size_t)by * 128 * HID;
    const __half* pBh = Bh + (size_t)bx * 128 * HID;

    float acc[2][8][4];
    #pragma unroll
    for (int i = 0; i < 2; i++)
        #pragma unroll
        for (int j = 0; j < 8; j++)
            #pragma unroll
            for (int q = 0; q < 4; q++) acc[i][j][q] = 0.0f;

    mma_mainloop<true>(sb, pAh, pAl, pBh, HID, HID, HID, tid, acc);

    const int mrow0 = wm * 32 + (lane >> 2);
    const int ncol0 = wn * 64 + (lane & 3) * 2;
    #pragma unroll
    for (int mf = 0; mf < 2; mf++)
        #pragma unroll
        for (int nf = 0; nf < 8; nf++) {
            const int r = by * 128 + mrow0 + mf * 16;
            const int c = ncol0 + nf * 8;
            const float* a = acc[mf][nf];
            const float b0 = bias[bx * 128 + c], b1 = bias[bx * 128 + c + 1];
            float* p0 = Cf + (size_t)r * HID + (size_t)bx * 128 + c;
            float2 w0; w0.x = a[0] + b0; w0.y = a[1] + b1;
            float2 w1; w1.x = a[2] + b0; w1.y = a[3] + b1;
            *(float2*)p0 = w0;
            *(float2*)(p0 + (size_t)8 * HID) = w1;
        }
}

// ============================================================================
// Fused flash attention, fp16x2 (identical to R8 passing version)
// ============================================================================
constexpr int FL_KV0  = 65536;
constexpr int FL_P    = 131072;
constexpr int FL_RED  = 163840;
constexpr int FL_SMEM = 164864;

__global__ void __launch_bounds__(256, 1)
flash_attn(const __half* __restrict__ Qh_, const __half* __restrict__ Ql_,
           const __half* __restrict__ Kh_, const __half* __restrict__ Vh_,
           __half* __restrict__ Ah_, __half* __restrict__ Al_)
{
    extern __shared__ __align__(128) unsigned char smem[];
    const uint32_t sb = smem_u32(smem);
    const int tid = threadIdx.x, lane = tid & 31, wid = tid >> 5;
    const int wm = wid & 3, wn = wid >> 2;
    const int qt = blockIdx.x, bh = blockIdx.y;

    const size_t qoff = ((size_t)bh * SEQ + (size_t)qt * 128) * HD;
    const size_t koff = (size_t)bh * SEQ * HD;
    const size_t voff = (size_t)bh * HD * SEQ;

    {
        const int r = tid >> 1;
        const size_t gq = qoff + (size_t)r * HD;
        #pragma unroll
        for (int j = 0; j < 4; j++) {
            const uint32_t cb = (uint32_t)(tid & 1) * 64 + j * 16;
            const uint32_t off = swz((uint32_t)r * 128 + cb);
            cp_async16(sb + off,         (const char*)(Qh_ + gq)      + cb);
            cp_async16(sb + 16384 + off, (const char*)(Qh_ + gq + 64) + cb);
            cp_async16(sb + 32768 + off, (const char*)(Ql_ + gq)      + cb);
            cp_async16(sb + 49152 + off, (const char*)(Ql_ + gq + 64) + cb);
        }
    }

    auto fill_kv = [&](int it) {
        const uint32_t bufb = sb + FL_KV0 + (uint32_t)(it & 1) * 32768;
        {
            const int r = tid >> 2;
            const size_t gk = koff + ((size_t)it * 64 + r) * HD;
            #pragma unroll
            for (int j = 0; j < 2; j++) {
                const uint32_t cb = (uint32_t)(tid & 3) * 32 + j * 16;
                const uint32_t off = swz((uint32_t)r * 128 + cb);
                cp_async16(bufb + off,        (const char*)(Kh_ + gk)      + cb);
                cp_async16(bufb + 8192 + off, (const char*)(Kh_ + gk + 64) + cb);
            }
        }
        {
            const int r = tid >> 1;
            const size_t gv = voff + (size_t)r * SEQ + (size_t)it * 64;
            #pragma unroll
            for (int j = 0; j < 2; j++) {
                const uint32_t cb = (uint32_t)(tid & 1) * 64 + j * 32;
                const uint32_t off0 = swz((uint32_t)r * 128 + cb);
                const uint32_t off1 = swz((uint32_t)r * 128 + cb + 16);
                cp_async16(bufb + 16384 + off0, (const char*)(Vh_ + gv) + cb);
                cp_async16(bufb + 16384 + off1, (const char*)(Vh_ + gv) + cb + 16);
            }
        }
        CP_COMMIT();
    };

    fill_kv(0);

    const int nl = (lane & 7) + ((lane >> 4) & 1) * 8;
    const int kh = (lane >> 3) & 1;
    const uint32_t arow = (uint32_t)(wm * 32 + (lane & 15));
    const uint32_t acol16 = (uint32_t)(((lane >> 4) & 1) * 16);

    float O[2][8][4];
    #pragma unroll
    for (int i = 0; i < 2; i++)
        #pragma unroll
        for (int j = 0; j < 8; j++)
            #pragma unroll
            for (int q = 0; q < 4; q++) O[i][j][q] = 0.0f;
    float mrun[4], lrun[4];
    #pragma unroll
    for (int i = 0; i < 4; i++) { mrun[i] = -1e30f; lrun[i] = 0.0f; }

    float* red = (float*)(smem + FL_RED);

    for (int it = 0; it < SEQ / 64; ++it) {
        CP_WAIT(0);
        __syncthreads();
        if (it + 1 < SEQ / 64) fill_kv(it + 1);
        const uint32_t kb = sb + FL_KV0 + (uint32_t)(it & 1) * 32768;

        float S[2][4][4];
        #pragma unroll
        for (int mf = 0; mf < 2; mf++)
            #pragma unroll
            for (int nf = 0; nf < 4; nf++)
                #pragma unroll
                for (int q = 0; q < 4; q++) S[mf][nf][q] = 0.0f;

        #pragma unroll
        for (int ks = 0; ks < 8; ++ks) {
            const uint32_t qp = sb + (uint32_t)(ks >> 2) * 16384;
            const uint32_t kp = kb + (uint32_t)(ks >> 2) * 8192;
            const uint32_t ac = acol16 + (uint32_t)(ks & 3) * 32;
            uint32_t qh[2][4], ql[2][4];
            #pragma unroll
            for (int mf = 0; mf < 2; mf++) {
                const uint32_t ro = (arow + mf * 16) * 128 + ac;
                ldsm4(qh[mf], qp + swz(ro));
                ldsm4(ql[mf], qp + 32768 + swz(ro));
            }
            uint32_t bh2[4][2];
            #pragma unroll
            for (int g = 0; g < 2; g++) {
                const uint32_t ro = (uint32_t)(wn * 32 + nl + g * 16) * 128
                                  + kh * 16 + (ks & 3) * 32;
                uint32_t t[4];
                ldsm4(t, kp + swz(ro));
                bh2[2*g][0] = t[0]; bh2[2*g][1] = t[1];
                bh2[2*g+1][0] = t[2]; bh2[2*g+1][1] = t[3];
            }
            #pragma unroll
            for (int mf = 0; mf < 2; mf++)
                #pragma unroll
                for (int nf = 0; nf < 4; nf++) {
                    mma16816(S[mf][nf], qh[mf], bh2[nf][0], bh2[nf][1]);
                    mma16816(S[mf][nf], ql[mf], bh2[nf][0], bh2[nf][1]);
                }
        }

        float mloc[4];
        #pragma unroll
        for (int i = 0; i < 4; i++) {
            const int mf = i >> 1, ch = i & 1;
            float v = -1e30f;
            #pragma unroll
            for (int nf = 0; nf < 4; nf++) {
                v = fmaxf(v, S[mf][nf][ch*2]);
                v = fmaxf(v, S[mf][nf][ch*2+1]);
            }
            v = fmaxf(v, __shfl_xor_sync(0xffffffffu, v, 1));
            v = fmaxf(v, __shfl_xor_sync(0xffffffffu, v, 2));
            mloc[i] = v;
        }
        if ((lane & 3) == 0) {
            #pragma unroll
            for (int i = 0; i < 4; i++) {
                const int r = wm*32 + (i>>1)*16 + (lane>>2) + (i&1)*8;
                red[r*2 + wn] = mloc[i];
            }
        }
        __syncthreads();
        float fac[4], mnew[4];
        #pragma unroll
        for (int i = 0; i < 4; i++) {
            const int r = wm*32 + (i>>1)*16 + (lane>>2) + (i&1)*8;
            const float mt = fmaxf(red[r*2], red[r*2+1]);
            mnew[i] = fmaxf(mrun[i], mt);
            fac[i] = __expf(mrun[i] - mnew[i]);
            mrun[i] = mnew[i];
        }
        float rs[4] = {0.f, 0.f, 0.f, 0.f};
        #pragma unroll
        for (int mf = 0; mf < 2; mf++)
            #pragma unroll
            for (int nf = 0; nf < 4; nf++)
                #pragma unroll
                for (int ch = 0; ch < 2; ch++) {
                    const int i = mf*2 + ch;
                    const float p0 = __expf(S[mf][nf][ch*2]   - mnew[i]);
                    const float p1 = __expf(S[mf][nf][ch*2+1] - mnew[i]);
                    rs[i] += p0 + p1;
                    const uint32_t r = wm*32 + mf*16 + (lane>>2) + ch*8;
                    const uint32_t cB = (uint32_t)(wn*64 + nf*16 + (lane&3)*4);
                    const uint32_t off = swz(r * 128 + cB);
                    const float h0 = __half2float(__float2half_rn(p0));
                    const float h1 = __half2float(__float2half_rn(p1));
                    *(uint32_t*)(smem + FL_P + off)         = hf2pack(h0, h1);
                    *(uint32_t*)(smem + FL_P + 16384 + off) = hf2pack(p0-h0, p1-h1);
                }
        #pragma unroll
        for (int i = 0; i < 4; i++) {
            float v = rs[i];
            v += __shfl_xor_sync(0xffffffffu, v, 1);
            v += __shfl_xor_sync(0xffffffffu, v, 2);
            lrun[i] = lrun[i] * fac[i] + v;
        }
        #pragma unroll
        for (int mf = 0; mf < 2; mf++)
            #pragma unroll
            for (int nf = 0; nf < 8; nf++)
                #pragma unroll
                for (int q = 0; q < 4; q++)
                    O[mf][nf][q] *= fac[mf*2 + (q>>1)];
        __syncthreads();

        #pragma unroll
        for (int ks = 0; ks < 4; ++ks) {
            const uint32_t ac = acol16 + (uint32_t)ks * 32;
            uint32_t ph[2][4], pl[2][4];
            #pragma unroll
            for (int mf = 0; mf < 2; mf++) {
                const uint32_t ro = (arow + mf * 16) * 128 + ac;
                ldsm4(ph[mf], sb + FL_P + swz(ro));
                ldsm4(pl[mf], sb + FL_P + 16384 + swz(ro));
            }
            uint32_t vh2[8][2];
            #pragma unroll
            for (int g = 0; g < 4; g++) {
                const uint32_t ro = (uint32_t)(wn * 64 + nl + g * 16) * 128
                                  + kh * 16 + ks * 32;
                uint32_t t[4];
                ldsm4(t, kb + 16384 + swz(ro));
                vh2[2*g][0] = t[0]; vh2[2*g][1] = t[1];
                vh2[2*g+1][0] = t[2]; vh2[2*g+1][1] = t[3];
            }
            #pragma unroll
            for (int mf = 0; mf < 2; mf++)
                #pragma unroll
                for (int nf = 0; nf < 8; nf++) {
                    mma16816(O[mf][nf], ph[mf], vh2[nf][0], vh2[nf][1]);
                    mma16816(O[mf][nf], pl[mf], vh2[nf][0], vh2[nf][1]);
                }
        }
    }

    __syncthreads();
    if ((lane & 3) == 0) {
        #pragma unroll
        for (int i = 0; i < 4; i++) {
            const int r = wm*32 + (i>>1)*16 + (lane>>2) + (i&1)*8;
            red[r*2 + wn] = lrun[i];
        }
    }
    __syncthreads();
    float linv[4];
    #pragma unroll
    for (int i = 0; i < 4; i++) {
        const int r = wm*32 + (i>>1)*16 + (lane>>2) + (i&1)*8;
        linv[i] = 1.0f / (red[r*2] + red[r*2+1]);
    }

    const int b = bh >> 4, h = bh & 15;
    #pragma unroll
    for (int mf = 0; mf < 2; mf++)
        #pragma unroll
        for (int nf = 0; nf < 8; nf++) {
            const int r = qt*128 + wm*32 + mf*16 + (lane>>2);
            const int c = wn*64 + nf*8 + (lane&3)*2;
            const size_t base = ((size_t)b * SEQ + r) * HID + (size_t)h * 128 + c;
            split2h(Ah_, Al_, base,
                    O[mf][nf][0] * linv[mf*2], O[mf][nf][1] * linv[mf*2]);
            split2h(Ah_, Al_, base + (size_t)8 * HID,
                    O[mf][nf][2] * linv[mf*2+1], O[mf][nf][3] * linv[mf*2+1]);
        }
}

// ============================================================================
// Conversions: X split fp16 hi/lo; 4 weight matrices rounded (one launch)
// ============================================================================
__global__ __launch_bounds__(256)
void conv_split_h(const float4* __restrict__ in, uint32_t* __restrict__ hi,
                  uint32_t* __restrict__ lo, int n4)
{
    int i = blockIdx.x * blockDim.x + threadIdx.x;
    if (i >= n4) return;
    float4 v = in[i];
    float hx = __half2float(__float2half_rn(v.x));
    float hy = __half2float(__float2half_rn(v.y));
    float hz = __half2float(__float2half_rn(v.z));
    float hw = __half2float(__float2half_rn(v.w));
    hi[2 * i]     = hf2pack(hx, hy);
    hi[2 * i + 1] = hf2pack(hz, hw);
    lo[2 * i]     = hf2pack(v.x - hx, v.y - hy);
    lo[2 * i + 1] = hf2pack(v.z - hz, v.w - hw);
}

__global__ __launch_bounds__(256)
void conv_round_h4(const float4* __restrict__ w0, const float4* __restrict__ w1,
                   const float4* __restrict__ w2, const float4* __restrict__ w3,
                   uint32_t* __restrict__ o0, uint32_t* __restrict__ o1,
                   uint32_t* __restrict__ o2, uint32_t* __restrict__ o3, int n4)
{
    int i = blockIdx.x * blockDim.x + threadIdx.x;
    if (i >= n4) return;
    const float4* in = (blockIdx.y == 0) ? w0 : (blockIdx.y == 1) ? w1
                     : (blockIdx.y == 2) ? w2 : w3;
    uint32_t* hi = (blockIdx.y == 0) ? o0 : (blockIdx.y == 1) ? o1
                 : (blockIdx.y == 2) ? o2 : o3;
    float4 v = in[i];
    hi[2 * i]     = hf2pack(v.x, v.y);
    hi[2 * i + 1] = hf2pack(v.z, v.w);
}

// ============================================================================
// kernel_launch
// ============================================================================
extern "C" void kernel_launch(void* const* d_in, const int* in_sizes, int n_in,
                              void* d_out, int out_size)
{
    const float* x  = (const float*)d_in[0];
    const float* Wq = (const float*)d_in[1];
    const float* bq = (const float*)d_in[2];
    const float* Wk = (const float*)d_in[3];
    const float* bk = (const float*)d_in[4];
    const float* Wv = (const float*)d_in[5];
    const float* bv = (const float*)d_in[6];
    const float* Wo = (const float*)d_in[7];
    const float* bo = (const float*)d_in[8];
    float* out = (float*)d_out;

    unsigned char* pool;
    cudaGetSymbolAddress((void**)&pool, g_pool);
    auto hfp = [&](size_t off) { return (__half*)(pool + off); };
    auto u32 = [&](size_t off) { return (uint32_t*)(pool + off); };

    cudaFuncSetAttribute(qkv_mma,    cudaFuncAttributeMaxDynamicSharedMemorySize, SMEM_BYTES);
    cudaFuncSetAttribute(gemm_out,   cudaFuncAttributeMaxDynamicSharedMemorySize, SMEM_BYTES);
    cudaFuncSetAttribute(flash_attn, cudaFuncAttributeMaxDynamicSharedMemorySize, FL_SMEM);

    const float scale = 0.08838834764831845f;  // 1/sqrt(128)

    // 1) conversions: X split; all four weights rounded in one launch
    conv_split_h<<<8192, 256>>>((const float4*)x, u32(OFF_XH), u32(OFF_XL), 2097152);
    dim3 gW(4096, 4, 1);
    conv_round_h4<<<gW, 256>>>((const float4*)Wq, (const float4*)Wk,
                               (const float4*)Wv, (const float4*)Wo,
                               u32(OFF_WQH), u32(OFF_WKH),
                               u32(OFF_WVH), u32(OFF_WOH), 1048576);

    // 2) fused QKV projections (one launch, z = {Q, K, V})
    dim3 gQKV(16, 32, 3);
    qkv_mma<<<gQKV, 256, SMEM_BYTES>>>(
        hfp(OFF_XH), hfp(OFF_XL),
        hfp(OFF_WQH), hfp(OFF_WKH), hfp(OFF_WVH),
        bq, bk, bv,
        hfp(OFF_QH), hfp(OFF_QL), hfp(OFF_KH), hfp(OFF_VTH), scale);

    // 3) fused flash attention
    dim3 gF(SEQ / 128, BATCH * HEADS, 1);
    flash_attn<<<gF, 256, FL_SMEM>>>(hfp(OFF_QH), hfp(OFF_QL),
                                     hfp(OFF_KH), hfp(OFF_VTH),
                                     hfp(OFF_AH), hfp(OFF_AL));

    // 4) output projection
    dim3 gO(16, 32, 1);
    gemm_out<<<gO, 256, SMEM_BYTES>>>(hfp(OFF_AH), hfp(OFF_AL),
                                      hfp(OFF_WOH), out, bo);
}

// round 10
// speedup vs baseline: 5.9057x; 1.1798x over previous
#include <cuda_runtime.h>
#include <cuda_fp16.h>
#include <cstdint>
#include <cstddef>

// ============================================================================
// Problem constants
// ============================================================================
constexpr int SEQ = 2048, HID = 2048, HEADS = 16, HD = 128, BATCH = 2;
constexpr int TILEB  = 128 * 80;          // 128x32-fp16 tile, 80B padded rows
constexpr int STAGEB = 3 * TILEB;         // Ah, Al, Bh
constexpr int SMEM_BYTES = 67584;         // max(2*STAGEB=61440, transpose 128*132*4)

// ============================================================================
// Device scratch pool
// ============================================================================
constexpr size_t MB = 1048576ull;
constexpr size_t OFF_XH  = 0,       OFF_XL  = 16*MB;
constexpr size_t OFF_WQH = 32*MB;
constexpr size_t OFF_WKH = 40*MB;
constexpr size_t OFF_WVH = 48*MB;
constexpr size_t OFF_WOH = 56*MB;
constexpr size_t OFF_QH  = 64*MB,   OFF_QL  = 80*MB;   // Q fp16 hi/lo
constexpr size_t OFF_KH  = 96*MB;                       // K fp16 (rounded)
constexpr size_t OFF_VTH = 112*MB;                      // V^T fp16 (rounded)
constexpr size_t OFF_AH  = 128*MB;                      // attn fp16 (rounded)
constexpr size_t POOL_SZ = 144*MB;

__device__ __align__(1024) unsigned char g_pool[POOL_SZ];

// ============================================================================
// Helpers
// ============================================================================
__device__ __forceinline__ uint32_t smem_u32(const void* p) {
    uint32_t a;
    asm("{ .reg .u64 t; cvta.to.shared.u64 t, %1; cvt.u32.u64 %0, t; }"
        : "=r"(a) : "l"(p));
    return a;
}
__device__ __forceinline__ void cp_async16(uint32_t dst, const void* src) {
    asm volatile("cp.async.cg.shared.global [%0], [%1], 16;"
                 :: "r"(dst), "l"(src) : "memory");
}
#define CP_COMMIT() asm volatile("cp.async.commit_group;" ::: "memory")
#define CP_WAIT(n)  asm volatile("cp.async.wait_group %0;" :: "n"(n) : "memory")

__device__ __forceinline__ void ldsm4(uint32_t r[4], uint32_t a) {
    asm volatile("ldmatrix.sync.aligned.m8n8.x4.shared.b16 {%0,%1,%2,%3}, [%4];"
                 : "=r"(r[0]), "=r"(r[1]), "=r"(r[2]), "=r"(r[3]) : "r"(a));
}
__device__ __forceinline__ void mma16816(float c[4], const uint32_t a[4],
                                         const uint32_t b0, const uint32_t b1) {
    asm volatile(
        "mma.sync.aligned.m16n8k16.row.col.f32.f16.f16.f32 "
        "{%0,%1,%2,%3}, {%4,%5,%6,%7}, {%8,%9}, {%0,%1,%2,%3};"
        : "+f"(c[0]), "+f"(c[1]), "+f"(c[2]), "+f"(c[3])
        : "r"(a[0]), "r"(a[1]), "r"(a[2]), "r"(a[3]), "r"(b0), "r"(b1));
}
__device__ __forceinline__ uint32_t hf2pack(float a, float b) {
    __half2 t;
    t.x = __float2half_rn(a);
    t.y = __float2half_rn(b);
    return *reinterpret_cast<uint32_t*>(&t);
}
__device__ __forceinline__ void split2h(__half* Ch, __half* Cl,
                                        size_t idx, float v0, float v1) {
    float h0 = __half2float(__float2half_rn(v0));
    float h1 = __half2float(__float2half_rn(v1));
    *(uint32_t*)(Ch + idx) = hf2pack(h0, h1);
    *(uint32_t*)(Cl + idx) = hf2pack(v0 - h0, v1 - h1);
}
__device__ __forceinline__ uint32_t swz(uint32_t o) { return o ^ ((o >> 3) & 0x70); }

// ============================================================================
// fp16 GEMM mainloop: acc = (Ah[+Al]) @ Bh^T.  128x128 tile, BK=32, 256 thr,
// 2-stage cp.async, one-ahead B-fragment double buffering.
// ============================================================================
template <bool USE_AL>
__device__ __forceinline__ void mma_mainloop(
    uint32_t sb,
    const __half* pAh, const __half* pAl, const __half* pBh,
    int lda, int ldb, int K, int tid, float acc[2][8][4])
{
    const int lane = tid & 31, wid = tid >> 5;
    const int wm = wid & 3, wn = wid >> 2;
    const int frow = tid >> 2, fch = tid & 3;
    const uint32_t fdst = (uint32_t)frow * 80 + (uint32_t)fch * 16;

    #define FILL_TILE(dstBase, g, ld) do {                                      \
        const char* _g = (const char*)(g) + ((size_t)_k0 + fch * 8) * 2;        \
        cp_async16((dstBase) + fdst, _g + (size_t)frow * (ld) * 2);             \
        cp_async16((dstBase) + fdst + 64 * 80, _g + (size_t)(frow + 64) * (ld) * 2); \
    } while (0)

    #define FILL_STAGE(IT) do {                                                 \
        const uint32_t _st = sb + (uint32_t)((IT) & 1) * STAGEB;                \
        const int _k0 = (IT) * 32;                                              \
        FILL_TILE(_st, pAh, lda);                                               \
        if (USE_AL) FILL_TILE(_st + TILEB, pAl, lda);                           \
        FILL_TILE(_st + 2 * TILEB, pBh, ldb);                                   \
        CP_COMMIT();                                                            \
    } while (0)

    const uint32_t aOff = (uint32_t)(wm * 32 + (lane & 15)) * 80
                        + (uint32_t)((lane >> 4) & 1) * 16;
    const int nl = (lane & 7) + ((lane >> 4) & 1) * 8;
    const int kh = (lane >> 3) & 1;
    const uint32_t bOff = (uint32_t)(wn * 64 + nl) * 80 + (uint32_t)kh * 16;

    const int NIT = K >> 5;
    FILL_STAGE(0);

    for (int it = 0; it < NIT; ++it) {
        if (it + 1 < NIT) { FILL_STAGE(it + 1); CP_WAIT(1); }
        else              { CP_WAIT(0); }
        __syncthreads();
        const uint32_t st = sb + (uint32_t)(it & 1) * STAGEB;
        #pragma unroll
        for (int ks = 0; ks < 2; ks++) {
            uint32_t th[2][4];
            ldsm4(th[0], st + 2 * TILEB + bOff + ks * 32);
            uint32_t ahf[2][4], alf[2][4];
            #pragma unroll
            for (int mf = 0; mf < 2; mf++) {
                ldsm4(ahf[mf], st + aOff + mf * (16 * 80) + ks * 32);
                if (USE_AL)
                    ldsm4(alf[mf], st + TILEB + aOff + mf * (16 * 80) + ks * 32);
            }
            #pragma unroll
            for (int nq = 0; nq < 4; nq++) {
                const int cur = nq & 1;
                if (nq < 3) {
                    ldsm4(th[cur ^ 1],
                          st + 2 * TILEB + bOff + (nq + 1) * (16 * 80) + ks * 32);
                }
                #pragma unroll
                for (int mf = 0; mf < 2; mf++) {
                    mma16816(acc[mf][2 * nq],     ahf[mf], th[cur][0], th[cur][1]);
                    if (USE_AL)
                        mma16816(acc[mf][2 * nq], alf[mf], th[cur][0], th[cur][1]);
                    mma16816(acc[mf][2 * nq + 1], ahf[mf], th[cur][2], th[cur][3]);
                    if (USE_AL)
                        mma16816(acc[mf][2 * nq + 1], alf[mf], th[cur][2], th[cur][3]);
                }
            }
        }
        __syncthreads();
    }
    #undef FILL_STAGE
    #undef FILL_TILE
}

// ============================================================================
// Fused QKV projection: grid (16, 32, 3);
// z=0 -> Q: 2-product (Xh+Xl)@Wq, scaled, split fp16 output
// z=1 -> K: 1-product Xh@Wk, rounded fp16 output
// z=2 -> V: 1-product Xh@Wv, transposed into V^T, rounded fp16 output
// ============================================================================
__global__ void __launch_bounds__(256, 2)
qkv_mma(const __half* __restrict__ Xh, const __half* __restrict__ Xl,
        const __half* __restrict__ Wqh, const __half* __restrict__ Wkh,
        const __half* __restrict__ Wvh,
        const float* __restrict__ bq, const float* __restrict__ bk,
        const float* __restrict__ bv,
        __half* __restrict__ Qh, __half* __restrict__ Ql,
        __half* __restrict__ Kh, __half* __restrict__ VTh,
        float scale)
{
    extern __shared__ __align__(128) unsigned char smem[];
    const uint32_t sb = smem_u32(smem);
    const int tid = threadIdx.x, lane = tid & 31, wid = tid >> 5;
    const int wm = wid & 3, wn = wid >> 2;
    const int bx = blockIdx.x, by = blockIdx.y, bz = blockIdx.z;

    const __half* Bh = (bz == 0) ? Wqh : (bz == 1) ? Wkh : Wvh;
    const float* bias = (bz == 0) ? bq : (bz == 1) ? bk : bv;

    const __half* pAh = Xh + (size_t)by * 128 * HID;
    const __half* pAl = Xl + (size_t)by * 128 * HID;
    const __half* pBh = Bh + (size_t)bx * 128 * HID;

    float acc[2][8][4];
    #pragma unroll
    for (int i = 0; i < 2; i++)
        #pragma unroll
        for (int j = 0; j < 8; j++)
            #pragma unroll
            for (int q = 0; q < 4; q++) acc[i][j][q] = 0.0f;

    if (bz == 0) mma_mainloop<true >(sb, pAh, pAl, pBh, HID, HID, HID, tid, acc);
    else         mma_mainloop<false>(sb, pAh, pAl, pBh, HID, HID, HID, tid, acc);

    const int mrow0 = wm * 32 + (lane >> 2);
    const int ncol0 = wn * 64 + (lane & 3) * 2;

    if (bz == 2) {
        // transposed epilogue into V^T [b][h][d][s], rounded fp16
        float* tb = (float*)smem;  // [128][132]
        #pragma unroll
        for (int mf = 0; mf < 2; mf++)
            #pragma unroll
            for (int nf = 0; nf < 8; nf++) {
                const int r = mrow0 + mf * 16;
                const int c = ncol0 + nf * 8;
                tb[r * 132 + c]           = acc[mf][nf][0];
                tb[r * 132 + c + 1]       = acc[mf][nf][1];
                tb[(r + 8) * 132 + c]     = acc[mf][nf][2];
                tb[(r + 8) * 132 + c + 1] = acc[mf][nf][3];
            }
        __syncthreads();
        const int d = tid & 127, sh = tid >> 7;
        const float bvv = bias[bx * 128 + d];
        const int b = by >> 4;
        const size_t base = (((size_t)(b * HEADS + bx)) * HD + d) * SEQ
                          + (size_t)(by & 15) * 128 + sh * 64;
        #pragma unroll 8
        for (int s = 0; s < 64; s += 2) {
            float v0 = tb[(sh * 64 + s) * 132 + d] + bvv;
            float v1 = tb[(sh * 64 + s + 1) * 132 + d] + bvv;
            *(uint32_t*)(VTh + base + s) = hf2pack(v0, v1);
        }
        return;
    }

    #pragma unroll
    for (int mf = 0; mf < 2; mf++)
        #pragma unroll
        for (int nf = 0; nf < 8; nf++) {
            const int r = by * 128 + mrow0 + mf * 16;
            const int c = ncol0 + nf * 8;
            const float* a = acc[mf][nf];
            const int b = r >> 11, s = r & 2047;
            const float b0 = bias[bx * 128 + c], b1 = bias[bx * 128 + c + 1];
            const size_t base = (((size_t)(b * HEADS + bx)) * SEQ + s) * HD + c;
            if (bz == 0) {
                split2h(Qh, Ql, base, (a[0] + b0) * scale, (a[1] + b1) * scale);
                split2h(Qh, Ql, base + (size_t)8 * HD,
                        (a[2] + b0) * scale, (a[3] + b1) * scale);
            } else {
                *(uint32_t*)(Kh + base) = hf2pack(a[0] + b0, a[1] + b1);
                *(uint32_t*)(Kh + base + (size_t)8 * HD) = hf2pack(a[2] + b0, a[3] + b1);
            }
        }
}

// ============================================================================
// Output projection GEMM: fp32 out = Ah @ Woh^T + bo   (single product)
// ============================================================================
__global__ void __launch_bounds__(256, 2)
gemm_out(const __half* __restrict__ Ah, const __half* __restrict__ Bh,
         float* __restrict__ Cf, const float* __restrict__ bias)
{
    extern __shared__ __align__(128) unsigned char smem[];
    const uint32_t sb = smem_u32(smem);
    const int tid = threadIdx.x, lane = tid & 31, wid = tid >> 5;
    const int wm = wid & 3, wn = wid >> 2;
    const int bx = blockIdx.x, by = blockIdx.y;

    const __half* pAh = Ah + (size_t)by * 128 * HID;
    const __half* pBh = Bh + (size_t)bx * 128 * HID;

    float acc[2][8][4];
    #pragma unroll
    for (int i = 0; i < 2; i++)
        #pragma unroll
        for (int j = 0; j < 8; j++)
            #pragma unroll
            for (int q = 0; q < 4; q++) acc[i][j][q] = 0.0f;

    mma_mainloop<false>(sb, pAh, nullptr, pBh, HID, HID, HID, tid, acc);

    const int mrow0 = wm * 32 + (lane >> 2);
    const int ncol0 = wn * 64 + (lane & 3) * 2;
    #pragma unroll
    for (int mf = 0; mf < 2; mf++)
        #pragma unroll
        for (int nf = 0; nf < 8; nf++) {
            const int r = by * 128 + mrow0 + mf * 16;
            const int c = ncol0 + nf * 8;
            const float* a = acc[mf][nf];
            const float b0 = bias[bx * 128 + c], b1 = bias[bx * 128 + c + 1];
            float* p0 = Cf + (size_t)r * HID + (size_t)bx * 128 + c;
            float2 w0; w0.x = a[0] + b0; w0.y = a[1] + b1;
            float2 w1; w1.x = a[2] + b0; w1.y = a[3] + b1;
            *(float2*)p0 = w0;
            *(float2*)(p0 + (size_t)8 * HID) = w1;
        }
}

// ============================================================================
// Fused flash attention, S = (Qh+Ql) K^T ; P rounded fp16 ; O += P V
// smem: Q 0..64K (Qh p0/p1, Ql p0/p1, 16K each)
//       KV buf b @ 64K + b*32K: Kh p0 (8K), Kh p1 (8K), V (16K)
//       P @ 128K: 16K (hi only) ; red @ 144K
// ============================================================================
constexpr int FL_KV0  = 65536;
constexpr int FL_P    = 131072;
constexpr int FL_RED  = 147456;
constexpr int FL_SMEM = 148480;

__global__ void __launch_bounds__(256, 1)
flash_attn(const __half* __restrict__ Qh_, const __half* __restrict__ Ql_,
           const __half* __restrict__ Kh_, const __half* __restrict__ Vh_,
           __half* __restrict__ Ah_)
{
    extern __shared__ __align__(128) unsigned char smem[];
    const uint32_t sb = smem_u32(smem);
    const int tid = threadIdx.x, lane = tid & 31, wid = tid >> 5;
    const int wm = wid & 3, wn = wid >> 2;
    const int qt = blockIdx.x, bh = blockIdx.y;

    const size_t qoff = ((size_t)bh * SEQ + (size_t)qt * 128) * HD;
    const size_t koff = (size_t)bh * SEQ * HD;
    const size_t voff = (size_t)bh * HD * SEQ;

    {
        const int r = tid >> 1;
        const size_t gq = qoff + (size_t)r * HD;
        #pragma unroll
        for (int j = 0; j < 4; j++) {
            const uint32_t cb = (uint32_t)(tid & 1) * 64 + j * 16;
            const uint32_t off = swz((uint32_t)r * 128 + cb);
            cp_async16(sb + off,         (const char*)(Qh_ + gq)      + cb);
            cp_async16(sb + 16384 + off, (const char*)(Qh_ + gq + 64) + cb);
            cp_async16(sb + 32768 + off, (const char*)(Ql_ + gq)      + cb);
            cp_async16(sb + 49152 + off, (const char*)(Ql_ + gq + 64) + cb);
        }
    }

    auto fill_kv = [&](int it) {
        const uint32_t bufb = sb + FL_KV0 + (uint32_t)(it & 1) * 32768;
        {
            const int r = tid >> 2;
            const size_t gk = koff + ((size_t)it * 64 + r) * HD;
            #pragma unroll
            for (int j = 0; j < 2; j++) {
                const uint32_t cb = (uint32_t)(tid & 3) * 32 + j * 16;
                const uint32_t off = swz((uint32_t)r * 128 + cb);
                cp_async16(bufb + off,        (const char*)(Kh_ + gk)      + cb);
                cp_async16(bufb + 8192 + off, (const char*)(Kh_ + gk + 64) + cb);
            }
        }
        {
            const int r = tid >> 1;
            const size_t gv = voff + (size_t)r * SEQ + (size_t)it * 64;
            #pragma unroll
            for (int j = 0; j < 2; j++) {
                const uint32_t cb = (uint32_t)(tid & 1) * 64 + j * 32;
                const uint32_t off0 = swz((uint32_t)r * 128 + cb);
                const uint32_t off1 = swz((uint32_t)r * 128 + cb + 16);
                cp_async16(bufb + 16384 + off0, (const char*)(Vh_ + gv) + cb);
                cp_async16(bufb + 16384 + off1, (const char*)(Vh_ + gv) + cb + 16);
            }
        }
        CP_COMMIT();
    };

    fill_kv(0);

    const int nl = (lane & 7) + ((lane >> 4) & 1) * 8;
    const int kh = (lane >> 3) & 1;
    const uint32_t arow = (uint32_t)(wm * 32 + (lane & 15));
    const uint32_t acol16 = (uint32_t)(((lane >> 4) & 1) * 16);

    float O[2][8][4];
    #pragma unroll
    for (int i = 0; i < 2; i++)
        #pragma unroll
        for (int j = 0; j < 8; j++)
            #pragma unroll
            for (int q = 0; q < 4; q++) O[i][j][q] = 0.0f;
    float mrun[4], lrun[4];
    #pragma unroll
    for (int i = 0; i < 4; i++) { mrun[i] = -1e30f; lrun[i] = 0.0f; }

    float* red = (float*)(smem + FL_RED);

    for (int it = 0; it < SEQ / 64; ++it) {
        CP_WAIT(0);
        __syncthreads();
        if (it + 1 < SEQ / 64) fill_kv(it + 1);
        const uint32_t kb = sb + FL_KV0 + (uint32_t)(it & 1) * 32768;

        float S[2][4][4];
        #pragma unroll
        for (int mf = 0; mf < 2; mf++)
            #pragma unroll
            for (int nf = 0; nf < 4; nf++)
                #pragma unroll
                for (int q = 0; q < 4; q++) S[mf][nf][q] = 0.0f;

        #pragma unroll
        for (int ks = 0; ks < 8; ++ks) {
            const uint32_t qp = sb + (uint32_t)(ks >> 2) * 16384;
            const uint32_t kp = kb + (uint32_t)(ks >> 2) * 8192;
            const uint32_t ac = acol16 + (uint32_t)(ks & 3) * 32;
            uint32_t qh[2][4], ql[2][4];
            #pragma unroll
            for (int mf = 0; mf < 2; mf++) {
                const uint32_t ro = (arow + mf * 16) * 128 + ac;
                ldsm4(qh[mf], qp + swz(ro));
                ldsm4(ql[mf], qp + 32768 + swz(ro));
            }
            uint32_t bh2[4][2];
            #pragma unroll
            for (int g = 0; g < 2; g++) {
                const uint32_t ro = (uint32_t)(wn * 32 + nl + g * 16) * 128
                                  + kh * 16 + (ks & 3) * 32;
                uint32_t t[4];
                ldsm4(t, kp + swz(ro));
                bh2[2*g][0] = t[0]; bh2[2*g][1] = t[1];
                bh2[2*g+1][0] = t[2]; bh2[2*g+1][1] = t[3];
            }
            #pragma unroll
            for (int mf = 0; mf < 2; mf++)
                #pragma unroll
                for (int nf = 0; nf < 4; nf++) {
                    mma16816(S[mf][nf], qh[mf], bh2[nf][0], bh2[nf][1]);
                    mma16816(S[mf][nf], ql[mf], bh2[nf][0], bh2[nf][1]);
                }
        }

        float mloc[4];
        #pragma unroll
        for (int i = 0; i < 4; i++) {
            const int mf = i >> 1, ch = i & 1;
            float v = -1e30f;
            #pragma unroll
            for (int nf = 0; nf < 4; nf++) {
                v = fmaxf(v, S[mf][nf][ch*2]);
                v = fmaxf(v, S[mf][nf][ch*2+1]);
            }
            v = fmaxf(v, __shfl_xor_sync(0xffffffffu, v, 1));
            v = fmaxf(v, __shfl_xor_sync(0xffffffffu, v, 2));
            mloc[i] = v;
        }
        if ((lane & 3) == 0) {
            #pragma unroll
            for (int i = 0; i < 4; i++) {
                const int r = wm*32 + (i>>1)*16 + (lane>>2) + (i&1)*8;
                red[r*2 + wn] = mloc[i];
            }
        }
        __syncthreads();
        float fac[4], mnew[4];
        #pragma unroll
        for (int i = 0; i < 4; i++) {
            const int r = wm*32 + (i>>1)*16 + (lane>>2) + (i&1)*8;
            const float mt = fmaxf(red[r*2], red[r*2+1]);
            mnew[i] = fmaxf(mrun[i], mt);
            fac[i] = __expf(mrun[i] - mnew[i]);
            mrun[i] = mnew[i];
        }
        float rs[4] = {0.f, 0.f, 0.f, 0.f};
        #pragma unroll
        for (int mf = 0; mf < 2; mf++)
            #pragma unroll
            for (int nf = 0; nf < 4; nf++)
                #pragma unroll
                for (int ch = 0; ch < 2; ch++) {
                    const int i = mf*2 + ch;
                    const float p0 = __expf(S[mf][nf][ch*2]   - mnew[i]);
                    const float p1 = __expf(S[mf][nf][ch*2+1] - mnew[i]);
                    rs[i] += p0 + p1;
                    const uint32_t r = wm*32 + mf*16 + (lane>>2) + ch*8;
                    const uint32_t cB = (uint32_t)(wn*64 + nf*16 + (lane&3)*4);
                    const uint32_t off = swz(r * 128 + cB);
                    *(uint32_t*)(smem + FL_P + off) = hf2pack(p0, p1);
                }
        #pragma unroll
        for (int i = 0; i < 4; i++) {
            float v = rs[i];
            v += __shfl_xor_sync(0xffffffffu, v, 1);
            v += __shfl_xor_sync(0xffffffffu, v, 2);
            lrun[i] = lrun[i] * fac[i] + v;
        }
        #pragma unroll
        for (int mf = 0; mf < 2; mf++)
            #pragma unroll
            for (int nf = 0; nf < 8; nf++)
                #pragma unroll
                for (int q = 0; q < 4; q++)
                    O[mf][nf][q] *= fac[mf*2 + (q>>1)];
        __syncthreads();

        #pragma unroll
        for (int ks = 0; ks < 4; ++ks) {
            const uint32_t ac = acol16 + (uint32_t)ks * 32;
            uint32_t ph[2][4];
            #pragma unroll
            for (int mf = 0; mf < 2; mf++) {
                const uint32_t ro = (arow + mf * 16) * 128 + ac;
                ldsm4(ph[mf], sb + FL_P + swz(ro));
            }
            uint32_t vh2[8][2];
            #pragma unroll
            for (int g = 0; g < 4; g++) {
                const uint32_t ro = (uint32_t)(wn * 64 + nl + g * 16) * 128
                                  + kh * 16 + ks * 32;
                uint32_t t[4];
                ldsm4(t, kb + 16384 + swz(ro));
                vh2[2*g][0] = t[0]; vh2[2*g][1] = t[1];
                vh2[2*g+1][0] = t[2]; vh2[2*g+1][1] = t[3];
            }
            #pragma unroll
            for (int mf = 0; mf < 2; mf++)
                #pragma unroll
                for (int nf = 0; nf < 8; nf++)
                    mma16816(O[mf][nf], ph[mf], vh2[nf][0], vh2[nf][1]);
        }
    }

    __syncthreads();
    if ((lane & 3) == 0) {
        #pragma unroll
        for (int i = 0; i < 4; i++) {
            const int r = wm*32 + (i>>1)*16 + (lane>>2) + (i&1)*8;
            red[r*2 + wn] = lrun[i];
        }
    }
    __syncthreads();
    float linv[4];
    #pragma unroll
    for (int i = 0; i < 4; i++) {
        const int r = wm*32 + (i>>1)*16 + (lane>>2) + (i&1)*8;
        linv[i] = 1.0f / (red[r*2] + red[r*2+1]);
    }

    const int b = bh >> 4, h = bh & 15;
    #pragma unroll
    for (int mf = 0; mf < 2; mf++)
        #pragma unroll
        for (int nf = 0; nf < 8; nf++) {
            const int r = qt*128 + wm*32 + mf*16 + (lane>>2);
            const int c = wn*64 + nf*8 + (lane&3)*2;
            const size_t base = ((size_t)b * SEQ + r) * HID + (size_t)h * 128 + c;
            *(uint32_t*)(Ah_ + base) =
                hf2pack(O[mf][nf][0] * linv[mf*2], O[mf][nf][1] * linv[mf*2]);
            *(uint32_t*)(Ah_ + base + (size_t)8 * HID) =
                hf2pack(O[mf][nf][2] * linv[mf*2+1], O[mf][nf][3] * linv[mf*2+1]);
        }
}

// ============================================================================
// Conversions: X split fp16 hi/lo; 4 weight matrices rounded (one launch)
// ============================================================================
__global__ __launch_bounds__(256)
void conv_split_h(const float4* __restrict__ in, uint32_t* __restrict__ hi,
                  uint32_t* __restrict__ lo, int n4)
{
    int i = blockIdx.x * blockDim.x + threadIdx.x;
    if (i >= n4) return;
    float4 v = in[i];
    float hx = __half2float(__float2half_rn(v.x));
    float hy = __half2float(__float2half_rn(v.y));
    float hz = __half2float(__float2half_rn(v.z));
    float hw = __half2float(__float2half_rn(v.w));
    hi[2 * i]     = hf2pack(hx, hy);
    hi[2 * i + 1] = hf2pack(hz, hw);
    lo[2 * i]     = hf2pack(v.x - hx, v.y - hy);
    lo[2 * i + 1] = hf2pack(v.z - hz, v.w - hw);
}

__global__ __launch_bounds__(256)
void conv_round_h4(const float4* __restrict__ w0, const float4* __restrict__ w1,
                   const float4* __restrict__ w2, const float4* __restrict__ w3,
                   uint32_t* __restrict__ o0, uint32_t* __restrict__ o1,
                   uint32_t* __restrict__ o2, uint32_t* __restrict__ o3, int n4)
{
    int i = blockIdx.x * blockDim.x + threadIdx.x;
    if (i >= n4) return;
    const float4* in = (blockIdx.y == 0) ? w0 : (blockIdx.y == 1) ? w1
                     : (blockIdx.y == 2) ? w2 : w3;
    uint32_t* hi = (blockIdx.y == 0) ? o0 : (blockIdx.y == 1) ? o1
                 : (blockIdx.y == 2) ? o2 : o3;
    float4 v = in[i];
    hi[2 * i]     = hf2pack(v.x, v.y);
    hi[2 * i + 1] = hf2pack(v.z, v.w);
}

// ============================================================================
// kernel_launch
// ============================================================================
extern "C" void kernel_launch(void* const* d_in, const int* in_sizes, int n_in,
                              void* d_out, int out_size)
{
    const float* x  = (const float*)d_in[0];
    const float* Wq = (const float*)d_in[1];
    const float* bq = (const float*)d_in[2];
    const float* Wk = (const float*)d_in[3];
    const float* bk = (const float*)d_in[4];
    const float* Wv = (const float*)d_in[5];
    const float* bv = (const float*)d_in[6];
    const float* Wo = (const float*)d_in[7];
    const float* bo = (const float*)d_in[8];
    float* out = (float*)d_out;

    unsigned char* pool;
    cudaGetSymbolAddress((void**)&pool, g_pool);
    auto hfp = [&](size_t off) { return (__half*)(pool + off); };
    auto u32 = [&](size_t off) { return (uint32_t*)(pool + off); };

    cudaFuncSetAttribute(qkv_mma,    cudaFuncAttributeMaxDynamicSharedMemorySize, SMEM_BYTES);
    cudaFuncSetAttribute(gemm_out,   cudaFuncAttributeMaxDynamicSharedMemorySize, SMEM_BYTES);
    cudaFuncSetAttribute(flash_attn, cudaFuncAttributeMaxDynamicSharedMemorySize, FL_SMEM);

    const float scale = 0.08838834764831845f;  // 1/sqrt(128)

    // 1) conversions
    conv_split_h<<<8192, 256>>>((const float4*)x, u32(OFF_XH), u32(OFF_XL), 2097152);
    dim3 gW(4096, 4, 1);
    conv_round_h4<<<gW, 256>>>((const float4*)Wq, (const float4*)Wk,
                               (const float4*)Wv, (const float4*)Wo,
                               u32(OFF_WQH), u32(OFF_WKH),
                               u32(OFF_WVH), u32(OFF_WOH), 1048576);

    // 2) fused QKV projections
    dim3 gQKV(16, 32, 3);
    qkv_mma<<<gQKV, 256, SMEM_BYTES>>>(
        hfp(OFF_XH), hfp(OFF_XL),
        hfp(OFF_WQH), hfp(OFF_WKH), hfp(OFF_WVH),
        bq, bk, bv,
        hfp(OFF_QH), hfp(OFF_QL), hfp(OFF_KH), hfp(OFF_VTH), scale);

    // 3) fused flash attention
    dim3 gF(SEQ / 128, BATCH * HEADS, 1);
    flash_attn<<<gF, 256, FL_SMEM>>>(hfp(OFF_QH), hfp(OFF_QL),
                                     hfp(OFF_KH), hfp(OFF_VTH),
                                     hfp(OFF_AH));

    // 4) output projection (single product)
    dim3 gO(16, 32, 1);
    gemm_out<<<gO, 256, SMEM_BYTES>>>(hfp(OFF_AH), hfp(OFF_WOH), out, bo);
}

// round 11
// speedup vs baseline: 6.9784x; 1.1816x over previous
#include <cuda_runtime.h>
#include <cuda_fp16.h>
#include <cstdint>
#include <cstddef>

// ============================================================================
// Problem constants
// ============================================================================
constexpr int SEQ = 2048, HID = 2048, HEADS = 16, HD = 128, BATCH = 2;
constexpr int TILEB  = 128 * 80;          // 128x32-fp16 tile, 80B padded rows
constexpr int STAGEB = 2 * TILEB;         // A, B tiles
constexpr int SMEM_BYTES = 67584;         // max(2*STAGEB=40960, transpose 128*132*4)

// ============================================================================
// Device scratch pool (all fp16 now)
// ============================================================================
constexpr size_t MB = 1048576ull;
constexpr size_t OFF_XH  = 0;          // X fp16 16MB
constexpr size_t OFF_WQH = 16*MB;
constexpr size_t OFF_WKH = 24*MB;
constexpr size_t OFF_WVH = 32*MB;
constexpr size_t OFF_WOH = 40*MB;
constexpr size_t OFF_QH  = 48*MB;      // Q fp16 (scaled, rounded)
constexpr size_t OFF_KH  = 64*MB;      // K fp16
constexpr size_t OFF_VTH = 80*MB;      // V^T fp16
constexpr size_t OFF_AH  = 96*MB;      // attn fp16
constexpr size_t POOL_SZ = 112*MB;

__device__ __align__(1024) unsigned char g_pool[POOL_SZ];

// ============================================================================
// Helpers
// ============================================================================
__device__ __forceinline__ uint32_t smem_u32(const void* p) {
    uint32_t a;
    asm("{ .reg .u64 t; cvta.to.shared.u64 t, %1; cvt.u32.u64 %0, t; }"
        : "=r"(a) : "l"(p));
    return a;
}
__device__ __forceinline__ void cp_async16(uint32_t dst, const void* src) {
    asm volatile("cp.async.cg.shared.global [%0], [%1], 16;"
                 :: "r"(dst), "l"(src) : "memory");
}
#define CP_COMMIT() asm volatile("cp.async.commit_group;" ::: "memory")
#define CP_WAIT(n)  asm volatile("cp.async.wait_group %0;" :: "n"(n) : "memory")

__device__ __forceinline__ void ldsm4(uint32_t r[4], uint32_t a) {
    asm volatile("ldmatrix.sync.aligned.m8n8.x4.shared.b16 {%0,%1,%2,%3}, [%4];"
                 : "=r"(r[0]), "=r"(r[1]), "=r"(r[2]), "=r"(r[3]) : "r"(a));
}
__device__ __forceinline__ void mma16816(float c[4], const uint32_t a[4],
                                         const uint32_t b0, const uint32_t b1) {
    asm volatile(
        "mma.sync.aligned.m16n8k16.row.col.f32.f16.f16.f32 "
        "{%0,%1,%2,%3}, {%4,%5,%6,%7}, {%8,%9}, {%0,%1,%2,%3};"
        : "+f"(c[0]), "+f"(c[1]), "+f"(c[2]), "+f"(c[3])
        : "r"(a[0]), "r"(a[1]), "r"(a[2]), "r"(a[3]), "r"(b0), "r"(b1));
}
__device__ __forceinline__ uint32_t hf2pack(float a, float b) {
    __half2 t;
    t.x = __float2half_rn(a);
    t.y = __float2half_rn(b);
    return *reinterpret_cast<uint32_t*>(&t);
}
__device__ __forceinline__ uint32_t swz(uint32_t o) { return o ^ ((o >> 3) & 0x70); }

// ============================================================================
// fp16 GEMM mainloop: acc = A @ B^T.  128x128 tile, BK=32, 256 thr,
// 2-stage cp.async, one-ahead B-fragment double buffering.
// ============================================================================
__device__ __forceinline__ void mma_mainloop(
    uint32_t sb, const __half* pAh, const __half* pBh,
    int lda, int ldb, int K, int tid, float acc[2][8][4])
{
    const int lane = tid & 31, wid = tid >> 5;
    const int wm = wid & 3, wn = wid >> 2;
    const int frow = tid >> 2, fch = tid & 3;
    const uint32_t fdst = (uint32_t)frow * 80 + (uint32_t)fch * 16;

    #define FILL_TILE(dstBase, g, ld) do {                                      \
        const char* _g = (const char*)(g) + ((size_t)_k0 + fch * 8) * 2;        \
        cp_async16((dstBase) + fdst, _g + (size_t)frow * (ld) * 2);             \
        cp_async16((dstBase) + fdst + 64 * 80, _g + (size_t)(frow + 64) * (ld) * 2); \
    } while (0)

    #define FILL_STAGE(IT) do {                                                 \
        const uint32_t _st = sb + (uint32_t)((IT) & 1) * STAGEB;                \
        const int _k0 = (IT) * 32;                                              \
        FILL_TILE(_st, pAh, lda);                                               \
        FILL_TILE(_st + TILEB, pBh, ldb);                                       \
        CP_COMMIT();                                                            \
    } while (0)

    const uint32_t aOff = (uint32_t)(wm * 32 + (lane & 15)) * 80
                        + (uint32_t)((lane >> 4) & 1) * 16;
    const int nl = (lane & 7) + ((lane >> 4) & 1) * 8;
    const int kh = (lane >> 3) & 1;
    const uint32_t bOff = (uint32_t)(wn * 64 + nl) * 80 + (uint32_t)kh * 16;

    const int NIT = K >> 5;
    FILL_STAGE(0);

    for (int it = 0; it < NIT; ++it) {
        if (it + 1 < NIT) { FILL_STAGE(it + 1); CP_WAIT(1); }
        else              { CP_WAIT(0); }
        __syncthreads();
        const uint32_t st = sb + (uint32_t)(it & 1) * STAGEB;
        #pragma unroll
        for (int ks = 0; ks < 2; ks++) {
            uint32_t th[2][4];
            ldsm4(th[0], st + TILEB + bOff + ks * 32);
            uint32_t ahf[2][4];
            #pragma unroll
            for (int mf = 0; mf < 2; mf++)
                ldsm4(ahf[mf], st + aOff + mf * (16 * 80) + ks * 32);
            #pragma unroll
            for (int nq = 0; nq < 4; nq++) {
                const int cur = nq & 1;
                if (nq < 3) {
                    ldsm4(th[cur ^ 1],
                          st + TILEB + bOff + (nq + 1) * (16 * 80) + ks * 32);
                }
                #pragma unroll
                for (int mf = 0; mf < 2; mf++) {
                    mma16816(acc[mf][2 * nq],     ahf[mf], th[cur][0], th[cur][1]);
                    mma16816(acc[mf][2 * nq + 1], ahf[mf], th[cur][2], th[cur][3]);
                }
            }
        }
        __syncthreads();
    }
    #undef FILL_STAGE
    #undef FILL_TILE
}

// ============================================================================
// Fused QKV projection: grid (16, 32, 3); all single-product fp16.
// z=0 -> Q (scaled), z=1 -> K, z=2 -> V transposed into V^T.
// ============================================================================
__global__ void __launch_bounds__(256, 2)
qkv_mma(const __half* __restrict__ Xh,
        const __half* __restrict__ Wqh, const __half* __restrict__ Wkh,
        const __half* __restrict__ Wvh,
        const float* __restrict__ bq, const float* __restrict__ bk,
        const float* __restrict__ bv,
        __half* __restrict__ Qh, __half* __restrict__ Kh,
        __half* __restrict__ VTh, float scale)
{
    extern __shared__ __align__(128) unsigned char smem[];
    const uint32_t sb = smem_u32(smem);
    const int tid = threadIdx.x, lane = tid & 31, wid = tid >> 5;
    const int wm = wid & 3, wn = wid >> 2;
    const int bx = blockIdx.x, by = blockIdx.y, bz = blockIdx.z;

    const __half* Bh = (bz == 0) ? Wqh : (bz == 1) ? Wkh : Wvh;
    const float* bias = (bz == 0) ? bq : (bz == 1) ? bk : bv;
    const float alpha = (bz == 0) ? scale : 1.0f;

    const __half* pAh = Xh + (size_t)by * 128 * HID;
    const __half* pBh = Bh + (size_t)bx * 128 * HID;

    float acc[2][8][4];
    #pragma unroll
    for (int i = 0; i < 2; i++)
        #pragma unroll
        for (int j = 0; j < 8; j++)
            #pragma unroll
            for (int q = 0; q < 4; q++) acc[i][j][q] = 0.0f;

    mma_mainloop(sb, pAh, pBh, HID, HID, HID, tid, acc);

    const int mrow0 = wm * 32 + (lane >> 2);
    const int ncol0 = wn * 64 + (lane & 3) * 2;

    if (bz == 2) {
        // transposed epilogue into V^T [b][h][d][s], rounded fp16
        float* tb = (float*)smem;  // [128][132]
        #pragma unroll
        for (int mf = 0; mf < 2; mf++)
            #pragma unroll
            for (int nf = 0; nf < 8; nf++) {
                const int r = mrow0 + mf * 16;
                const int c = ncol0 + nf * 8;
                tb[r * 132 + c]           = acc[mf][nf][0];
                tb[r * 132 + c + 1]       = acc[mf][nf][1];
                tb[(r + 8) * 132 + c]     = acc[mf][nf][2];
                tb[(r + 8) * 132 + c + 1] = acc[mf][nf][3];
            }
        __syncthreads();
        const int d = tid & 127, sh = tid >> 7;
        const float bvv = bias[bx * 128 + d];
        const int b = by >> 4;
        const size_t base = (((size_t)(b * HEADS + bx)) * HD + d) * SEQ
                          + (size_t)(by & 15) * 128 + sh * 64;
        #pragma unroll 8
        for (int s = 0; s < 64; s += 2) {
            float v0 = tb[(sh * 64 + s) * 132 + d] + bvv;
            float v1 = tb[(sh * 64 + s + 1) * 132 + d] + bvv;
            *(uint32_t*)(VTh + base + s) = hf2pack(v0, v1);
        }
        return;
    }

    __half* Ch = (bz == 0) ? Qh : Kh;
    #pragma unroll
    for (int mf = 0; mf < 2; mf++)
        #pragma unroll
        for (int nf = 0; nf < 8; nf++) {
            const int r = by * 128 + mrow0 + mf * 16;
            const int c = ncol0 + nf * 8;
            const float* a = acc[mf][nf];
            const int b = r >> 11, s = r & 2047;
            const float b0 = bias[bx * 128 + c], b1 = bias[bx * 128 + c + 1];
            const size_t base = (((size_t)(b * HEADS + bx)) * SEQ + s) * HD + c;
            *(uint32_t*)(Ch + base) =
                hf2pack((a[0] + b0) * alpha, (a[1] + b1) * alpha);
            *(uint32_t*)(Ch + base + (size_t)8 * HD) =
                hf2pack((a[2] + b0) * alpha, (a[3] + b1) * alpha);
        }
}

// ============================================================================
// Output projection GEMM: fp32 out = Ah @ Woh^T + bo
// ============================================================================
__global__ void __launch_bounds__(256, 2)
gemm_out(const __half* __restrict__ Ah, const __half* __restrict__ Bh,
         float* __restrict__ Cf, const float* __restrict__ bias)
{
    extern __shared__ __align__(128) unsigned char smem[];
    const uint32_t sb = smem_u32(smem);
    const int tid = threadIdx.x, lane = tid & 31, wid = tid >> 5;
    const int wm = wid & 3, wn = wid >> 2;
    const int bx = blockIdx.x, by = blockIdx.y;

    const __half* pAh = Ah + (size_t)by * 128 * HID;
    const __half* pBh = Bh + (size_t)bx * 128 * HID;

    float acc[2][8][4];
    #pragma unroll
    for (int i = 0; i < 2; i++)
        #pragma unroll
        for (int j = 0; j < 8; j++)
            #pragma unroll
            for (int q = 0; q < 4; q++) acc[i][j][q] = 0.0f;

    mma_mainloop(sb, pAh, pBh, HID, HID, HID, tid, acc);

    const int mrow0 = wm * 32 + (lane >> 2);
    const int ncol0 = wn * 64 + (lane & 3) * 2;
    #pragma unroll
    for (int mf = 0; mf < 2; mf++)
        #pragma unroll
        for (int nf = 0; nf < 8; nf++) {
            const int r = by * 128 + mrow0 + mf * 16;
            const int c = ncol0 + nf * 8;
            const float* a = acc[mf][nf];
            const float b0 = bias[bx * 128 + c], b1 = bias[bx * 128 + c + 1];
            float* p0 = Cf + (size_t)r * HID + (size_t)bx * 128 + c;
            float2 w0; w0.x = a[0] + b0; w0.y = a[1] + b1;
            float2 w1; w1.x = a[2] + b0; w1.y = a[3] + b1;
            *(float2*)p0 = w0;
            *(float2*)(p0 + (size_t)8 * HID) = w1;
        }
}

// ============================================================================
// Fused flash attention, all-fp16: S = Q K^T ; P rounded fp16 ; O += P V
// smem: Q 0..32K (Qh p0/p1, 16K each)
//       KV buf b @ 32K + b*32K: K p0 (8K), K p1 (8K), V (16K)
//       P @ 96K: 16K ; red @ 112K
// ============================================================================
constexpr int FL_KV0  = 32768;
constexpr int FL_P    = 98304;
constexpr int FL_RED  = 114688;
constexpr int FL_SMEM = 115712;

__global__ void __launch_bounds__(256, 1)
flash_attn(const __half* __restrict__ Qh_, const __half* __restrict__ Kh_,
           const __half* __restrict__ Vh_, __half* __restrict__ Ah_)
{
    extern __shared__ __align__(128) unsigned char smem[];
    const uint32_t sb = smem_u32(smem);
    const int tid = threadIdx.x, lane = tid & 31, wid = tid >> 5;
    const int wm = wid & 3, wn = wid >> 2;
    const int qt = blockIdx.x, bh = blockIdx.y;

    const size_t qoff = ((size_t)bh * SEQ + (size_t)qt * 128) * HD;
    const size_t koff = (size_t)bh * SEQ * HD;
    const size_t voff = (size_t)bh * HD * SEQ;

    {
        const int r = tid >> 1;
        const size_t gq = qoff + (size_t)r * HD;
        #pragma unroll
        for (int j = 0; j < 4; j++) {
            const uint32_t cb = (uint32_t)(tid & 1) * 64 + j * 16;
            const uint32_t off = swz((uint32_t)r * 128 + cb);
            cp_async16(sb + off,         (const char*)(Qh_ + gq)      + cb);
            cp_async16(sb + 16384 + off, (const char*)(Qh_ + gq + 64) + cb);
        }
    }

    auto fill_kv = [&](int it) {
        const uint32_t bufb = sb + FL_KV0 + (uint32_t)(it & 1) * 32768;
        {
            const int r = tid >> 2;
            const size_t gk = koff + ((size_t)it * 64 + r) * HD;
            #pragma unroll
            for (int j = 0; j < 2; j++) {
                const uint32_t cb = (uint32_t)(tid & 3) * 32 + j * 16;
                const uint32_t off = swz((uint32_t)r * 128 + cb);
                cp_async16(bufb + off,        (const char*)(Kh_ + gk)      + cb);
                cp_async16(bufb + 8192 + off, (const char*)(Kh_ + gk + 64) + cb);
            }
        }
        {
            const int r = tid >> 1;
            const size_t gv = voff + (size_t)r * SEQ + (size_t)it * 64;
            #pragma unroll
            for (int j = 0; j < 2; j++) {
                const uint32_t cb = (uint32_t)(tid & 1) * 64 + j * 32;
                const uint32_t off0 = swz((uint32_t)r * 128 + cb);
                const uint32_t off1 = swz((uint32_t)r * 128 + cb + 16);
                cp_async16(bufb + 16384 + off0, (const char*)(Vh_ + gv) + cb);
                cp_async16(bufb + 16384 + off1, (const char*)(Vh_ + gv) + cb + 16);
            }
        }
        CP_COMMIT();
    };

    fill_kv(0);

    const int nl = (lane & 7) + ((lane >> 4) & 1) * 8;
    const int kh = (lane >> 3) & 1;
    const uint32_t arow = (uint32_t)(wm * 32 + (lane & 15));
    const uint32_t acol16 = (uint32_t)(((lane >> 4) & 1) * 16);

    float O[2][8][4];
    #pragma unroll
    for (int i = 0; i < 2; i++)
        #pragma unroll
        for (int j = 0; j < 8; j++)
            #pragma unroll
            for (int q = 0; q < 4; q++) O[i][j][q] = 0.0f;
    float mrun[4], lrun[4];
    #pragma unroll
    for (int i = 0; i < 4; i++) { mrun[i] = -1e30f; lrun[i] = 0.0f; }

    float* red = (float*)(smem + FL_RED);

    for (int it = 0; it < SEQ / 64; ++it) {
        CP_WAIT(0);
        __syncthreads();
        if (it + 1 < SEQ / 64) fill_kv(it + 1);
        const uint32_t kb = sb + FL_KV0 + (uint32_t)(it & 1) * 32768;

        float S[2][4][4];
        #pragma unroll
        for (int mf = 0; mf < 2; mf++)
            #pragma unroll
            for (int nf = 0; nf < 4; nf++)
                #pragma unroll
                for (int q = 0; q < 4; q++) S[mf][nf][q] = 0.0f;

        #pragma unroll
        for (int ks = 0; ks < 8; ++ks) {
            const uint32_t qp = sb + (uint32_t)(ks >> 2) * 16384;
            const uint32_t kp = kb + (uint32_t)(ks >> 2) * 8192;
            const uint32_t ac = acol16 + (uint32_t)(ks & 3) * 32;
            uint32_t qh[2][4];
            #pragma unroll
            for (int mf = 0; mf < 2; mf++) {
                const uint32_t ro = (arow + mf * 16) * 128 + ac;
                ldsm4(qh[mf], qp + swz(ro));
            }
            uint32_t bh2[4][2];
            #pragma unroll
            for (int g = 0; g < 2; g++) {
                const uint32_t ro = (uint32_t)(wn * 32 + nl + g * 16) * 128
                                  + kh * 16 + (ks & 3) * 32;
                uint32_t t[4];
                ldsm4(t, kp + swz(ro));
                bh2[2*g][0] = t[0]; bh2[2*g][1] = t[1];
                bh2[2*g+1][0] = t[2]; bh2[2*g+1][1] = t[3];
            }
            #pragma unroll
            for (int mf = 0; mf < 2; mf++)
                #pragma unroll
                for (int nf = 0; nf < 4; nf++)
                    mma16816(S[mf][nf], qh[mf], bh2[nf][0], bh2[nf][1]);
        }

        float mloc[4];
        #pragma unroll
        for (int i = 0; i < 4; i++) {
            const int mf = i >> 1, ch = i & 1;
            float v = -1e30f;
            #pragma unroll
            for (int nf = 0; nf < 4; nf++) {
                v = fmaxf(v, S[mf][nf][ch*2]);
                v = fmaxf(v, S[mf][nf][ch*2+1]);
            }
            v = fmaxf(v, __shfl_xor_sync(0xffffffffu, v, 1));
            v = fmaxf(v, __shfl_xor_sync(0xffffffffu, v, 2));
            mloc[i] = v;
        }
        if ((lane & 3) == 0) {
            #pragma unroll
            for (int i = 0; i < 4; i++) {
                const int r = wm*32 + (i>>1)*16 + (lane>>2) + (i&1)*8;
                red[r*2 + wn] = mloc[i];
            }
        }
        __syncthreads();
        float fac[4], mnew[4];
        #pragma unroll
        for (int i = 0; i < 4; i++) {
            const int r = wm*32 + (i>>1)*16 + (lane>>2) + (i&1)*8;
            const float mt = fmaxf(red[r*2], red[r*2+1]);
            mnew[i] = fmaxf(mrun[i], mt);
            fac[i] = __expf(mrun[i] - mnew[i]);
            mrun[i] = mnew[i];
        }
        float rs[4] = {0.f, 0.f, 0.f, 0.f};
        #pragma unroll
        for (int mf = 0; mf < 2; mf++)
            #pragma unroll
            for (int nf = 0; nf < 4; nf++)
                #pragma unroll
                for (int ch = 0; ch < 2; ch++) {
                    const int i = mf*2 + ch;
                    const float p0 = __expf(S[mf][nf][ch*2]   - mnew[i]);
                    const float p1 = __expf(S[mf][nf][ch*2+1] - mnew[i]);
                    rs[i] += p0 + p1;
                    const uint32_t r = wm*32 + mf*16 + (lane>>2) + ch*8;
                    const uint32_t cB = (uint32_t)(wn*64 + nf*16 + (lane&3)*4);
                    const uint32_t off = swz(r * 128 + cB);
                    *(uint32_t*)(smem + FL_P + off) = hf2pack(p0, p1);
                }
        #pragma unroll
        for (int i = 0; i < 4; i++) {
            float v = rs[i];
            v += __shfl_xor_sync(0xffffffffu, v, 1);
            v += __shfl_xor_sync(0xffffffffu, v, 2);
            lrun[i] = lrun[i] * fac[i] + v;
        }
        #pragma unroll
        for (int mf = 0; mf < 2; mf++)
            #pragma unroll
            for (int nf = 0; nf < 8; nf++)
                #pragma unroll
                for (int q = 0; q < 4; q++)
                    O[mf][nf][q] *= fac[mf*2 + (q>>1)];
        __syncthreads();

        #pragma unroll
        for (int ks = 0; ks < 4; ++ks) {
            const uint32_t ac = acol16 + (uint32_t)ks * 32;
            uint32_t ph[2][4];
            #pragma unroll
            for (int mf = 0; mf < 2; mf++) {
                const uint32_t ro = (arow + mf * 16) * 128 + ac;
                ldsm4(ph[mf], sb + FL_P + swz(ro));
            }
            uint32_t vh2[8][2];
            #pragma unroll
            for (int g = 0; g < 4; g++) {
                const uint32_t ro = (uint32_t)(wn * 64 + nl + g * 16) * 128
                                  + kh * 16 + ks * 32;
                uint32_t t[4];
                ldsm4(t, kb + 16384 + swz(ro));
                vh2[2*g][0] = t[0]; vh2[2*g][1] = t[1];
                vh2[2*g+1][0] = t[2]; vh2[2*g+1][1] = t[3];
            }
            #pragma unroll
            for (int mf = 0; mf < 2; mf++)
                #pragma unroll
                for (int nf = 0; nf < 8; nf++)
                    mma16816(O[mf][nf], ph[mf], vh2[nf][0], vh2[nf][1]);
        }
    }

    __syncthreads();
    if ((lane & 3) == 0) {
        #pragma unroll
        for (int i = 0; i < 4; i++) {
            const int r = wm*32 + (i>>1)*16 + (lane>>2) + (i&1)*8;
            red[r*2 + wn] = lrun[i];
        }
    }
    __syncthreads();
    float linv[4];
    #pragma unroll
    for (int i = 0; i < 4; i++) {
        const int r = wm*32 + (i>>1)*16 + (lane>>2) + (i&1)*8;
        linv[i] = 1.0f / (red[r*2] + red[r*2+1]);
    }

    const int b = bh >> 4, h = bh & 15;
    #pragma unroll
    for (int mf = 0; mf < 2; mf++)
        #pragma unroll
        for (int nf = 0; nf < 8; nf++) {
            const int r = qt*128 + wm*32 + mf*16 + (lane>>2);
            const int c = wn*64 + nf*8 + (lane&3)*2;
            const size_t base = ((size_t)b * SEQ + r) * HID + (size_t)h * 128 + c;
            *(uint32_t*)(Ah_ + base) =
                hf2pack(O[mf][nf][0] * linv[mf*2], O[mf][nf][1] * linv[mf*2]);
            *(uint32_t*)(Ah_ + base + (size_t)8 * HID) =
                hf2pack(O[mf][nf][2] * linv[mf*2+1], O[mf][nf][3] * linv[mf*2+1]);
        }
}

// ============================================================================
// Conversions: fp32 -> fp16 round (X and 4 weights)
// ============================================================================
__global__ __launch_bounds__(256)
void conv_round_h(const float4* __restrict__ in, uint32_t* __restrict__ hi, int n4)
{
    int i = blockIdx.x * blockDim.x + threadIdx.x;
    if (i >= n4) return;
    float4 v = in[i];
    hi[2 * i]     = hf2pack(v.x, v.y);
    hi[2 * i + 1] = hf2pack(v.z, v.w);
}

__global__ __launch_bounds__(256)
void conv_round_h4(const float4* __restrict__ w0, const float4* __restrict__ w1,
                   const float4* __restrict__ w2, const float4* __restrict__ w3,
                   uint32_t* __restrict__ o0, uint32_t* __restrict__ o1,
                   uint32_t* __restrict__ o2, uint32_t* __restrict__ o3, int n4)
{
    int i = blockIdx.x * blockDim.x + threadIdx.x;
    if (i >= n4) return;
    const float4* in = (blockIdx.y == 0) ? w0 : (blockIdx.y == 1) ? w1
                     : (blockIdx.y == 2) ? w2 : w3;
    uint32_t* hi = (blockIdx.y == 0) ? o0 : (blockIdx.y == 1) ? o1
                 : (blockIdx.y == 2) ? o2 : o3;
    float4 v = in[i];
    hi[2 * i]     = hf2pack(v.x, v.y);
    hi[2 * i + 1] = hf2pack(v.z, v.w);
}

// ============================================================================
// kernel_launch
// ============================================================================
extern "C" void kernel_launch(void* const* d_in, const int* in_sizes, int n_in,
                              void* d_out, int out_size)
{
    const float* x  = (const float*)d_in[0];
    const float* Wq = (const float*)d_in[1];
    const float* bq = (const float*)d_in[2];
    const float* Wk = (const float*)d_in[3];
    const float* bk = (const float*)d_in[4];
    const float* Wv = (const float*)d_in[5];
    const float* bv = (const float*)d_in[6];
    const float* Wo = (const float*)d_in[7];
    const float* bo = (const float*)d_in[8];
    float* out = (float*)d_out;

    unsigned char* pool;
    cudaGetSymbolAddress((void**)&pool, g_pool);
    auto hfp = [&](size_t off) { return (__half*)(pool + off); };
    auto u32 = [&](size_t off) { return (uint32_t*)(pool + off); };

    cudaFuncSetAttribute(qkv_mma,    cudaFuncAttributeMaxDynamicSharedMemorySize, SMEM_BYTES);
    cudaFuncSetAttribute(gemm_out,   cudaFuncAttributeMaxDynamicSharedMemorySize, SMEM_BYTES);
    cudaFuncSetAttribute(flash_attn, cudaFuncAttributeMaxDynamicSharedMemorySize, FL_SMEM);

    const float scale = 0.08838834764831845f;  // 1/sqrt(128)

    // 1) conversions (all round-to-fp16)
    conv_round_h<<<8192, 256>>>((const float4*)x, u32(OFF_XH), 2097152);
    dim3 gW(4096, 4, 1);
    conv_round_h4<<<gW, 256>>>((const float4*)Wq, (const float4*)Wk,
                               (const float4*)Wv, (const float4*)Wo,
                               u32(OFF_WQH), u32(OFF_WKH),
                               u32(OFF_WVH), u32(OFF_WOH), 1048576);

    // 2) fused QKV projections (single-product fp16)
    dim3 gQKV(16, 32, 3);
    qkv_mma<<<gQKV, 256, SMEM_BYTES>>>(
        hfp(OFF_XH),
        hfp(OFF_WQH), hfp(OFF_WKH), hfp(OFF_WVH),
        bq, bk, bv,
        hfp(OFF_QH), hfp(OFF_KH), hfp(OFF_VTH), scale);

    // 3) fused flash attention (all fp16)
    dim3 gF(SEQ / 128, BATCH * HEADS, 1);
    flash_attn<<<gF, 256, FL_SMEM>>>(hfp(OFF_QH), hfp(OFF_KH),
                                     hfp(OFF_VTH), hfp(OFF_AH));

    // 4) output projection
    dim3 gO(16, 32, 1);
    gemm_out<<<gO, 256, SMEM_BYTES>>>(hfp(OFF_AH), hfp(OFF_WOH), out, bo);
}

// round 12
// speedup vs baseline: 7.2161x; 1.0341x over previous
#include <cuda_runtime.h>
#include <cuda_fp16.h>
#include <cstdint>
#include <cstddef>

// ============================================================================
// Problem constants
// ============================================================================
constexpr int SEQ = 2048, HID = 2048, HEADS = 16, HD = 128, BATCH = 2;
constexpr int TILEB  = 128 * 80;          // 128x32-fp16 tile, 80B padded rows
constexpr int STAGEB = 2 * TILEB;         // A, B tiles
constexpr int SMEM_BYTES = 67584;         // max(2*STAGEB=40960, transpose 128*132*4)

// ============================================================================
// Device scratch pool (all fp16)
// ============================================================================
constexpr size_t MB = 1048576ull;
constexpr size_t OFF_XH  = 0;
constexpr size_t OFF_WQH = 16*MB;
constexpr size_t OFF_WKH = 24*MB;
constexpr size_t OFF_WVH = 32*MB;
constexpr size_t OFF_WOH = 40*MB;
constexpr size_t OFF_QH  = 48*MB;      // Q fp16 (scale*log2e folded in)
constexpr size_t OFF_KH  = 64*MB;
constexpr size_t OFF_VTH = 80*MB;      // V^T fp16
constexpr size_t OFF_AH  = 96*MB;      // attn fp16
constexpr size_t POOL_SZ = 112*MB;

__device__ __align__(1024) unsigned char g_pool[POOL_SZ];

// ============================================================================
// Helpers
// ============================================================================
__device__ __forceinline__ uint32_t smem_u32(const void* p) {
    uint32_t a;
    asm("{ .reg .u64 t; cvta.to.shared.u64 t, %1; cvt.u32.u64 %0, t; }"
        : "=r"(a) : "l"(p));
    return a;
}
__device__ __forceinline__ void cp_async16(uint32_t dst, const void* src) {
    asm volatile("cp.async.cg.shared.global [%0], [%1], 16;"
                 :: "r"(dst), "l"(src) : "memory");
}
#define CP_COMMIT() asm volatile("cp.async.commit_group;" ::: "memory")
#define CP_WAIT(n)  asm volatile("cp.async.wait_group %0;" :: "n"(n) : "memory")

__device__ __forceinline__ void ldsm4(uint32_t r[4], uint32_t a) {
    asm volatile("ldmatrix.sync.aligned.m8n8.x4.shared.b16 {%0,%1,%2,%3}, [%4];"
                 : "=r"(r[0]), "=r"(r[1]), "=r"(r[2]), "=r"(r[3]) : "r"(a));
}
__device__ __forceinline__ void mma16816(float c[4], const uint32_t a[4],
                                         const uint32_t b0, const uint32_t b1) {
    asm volatile(
        "mma.sync.aligned.m16n8k16.row.col.f32.f16.f16.f32 "
        "{%0,%1,%2,%3}, {%4,%5,%6,%7}, {%8,%9}, {%0,%1,%2,%3};"
        : "+f"(c[0]), "+f"(c[1]), "+f"(c[2]), "+f"(c[3])
        : "r"(a[0]), "r"(a[1]), "r"(a[2]), "r"(a[3]), "r"(b0), "r"(b1));
}
__device__ __forceinline__ uint32_t hf2pack(float a, float b) {
    __half2 t;
    t.x = __float2half_rn(a);
    t.y = __float2half_rn(b);
    return *reinterpret_cast<uint32_t*>(&t);
}
// pack (lo, hi) fp32 -> f16x2 in one cvt
__device__ __forceinline__ uint32_t cvt_f16x2(float lo, float hi) {
    uint32_t d;
    asm("cvt.rn.f16x2.f32 %0, %1, %2;" : "=r"(d) : "f"(hi), "f"(lo));
    return d;
}
__device__ __forceinline__ uint32_t ex2_f16x2(uint32_t s) {
    uint32_t d;
    asm("ex2.approx.f16x2 %0, %1;" : "=r"(d) : "r"(s));
    return d;
}
__device__ __forceinline__ float sum_f16x2(uint32_t p) {
    __half2 h = *reinterpret_cast<__half2*>(&p);
    float2 f = __half22float2(h);
    return f.x + f.y;
}
__device__ __forceinline__ uint32_t swz(uint32_t o) { return o ^ ((o >> 3) & 0x70); }

// ============================================================================
// fp16 GEMM mainloop (unchanged from R11): acc = A @ B^T, 128x128, BK=32.
// ============================================================================
__device__ __forceinline__ void mma_mainloop(
    uint32_t sb, const __half* pAh, const __half* pBh,
    int lda, int ldb, int K, int tid, float acc[2][8][4])
{
    const int lane = tid & 31, wid = tid >> 5;
    const int wm = wid & 3, wn = wid >> 2;
    const int frow = tid >> 2, fch = tid & 3;
    const uint32_t fdst = (uint32_t)frow * 80 + (uint32_t)fch * 16;

    #define FILL_TILE(dstBase, g, ld) do {                                      \
        const char* _g = (const char*)(g) + ((size_t)_k0 + fch * 8) * 2;        \
        cp_async16((dstBase) + fdst, _g + (size_t)frow * (ld) * 2);             \
        cp_async16((dstBase) + fdst + 64 * 80, _g + (size_t)(frow + 64) * (ld) * 2); \
    } while (0)

    #define FILL_STAGE(IT) do {                                                 \
        const uint32_t _st = sb + (uint32_t)((IT) & 1) * STAGEB;                \
        const int _k0 = (IT) * 32;                                              \
        FILL_TILE(_st, pAh, lda);                                               \
        FILL_TILE(_st + TILEB, pBh, ldb);                                       \
        CP_COMMIT();                                                            \
    } while (0)

    const uint32_t aOff = (uint32_t)(wm * 32 + (lane & 15)) * 80
                        + (uint32_t)((lane >> 4) & 1) * 16;
    const int nl = (lane & 7) + ((lane >> 4) & 1) * 8;
    const int kh = (lane >> 3) & 1;
    const uint32_t bOff = (uint32_t)(wn * 64 + nl) * 80 + (uint32_t)kh * 16;

    const int NIT = K >> 5;
    FILL_STAGE(0);

    for (int it = 0; it < NIT; ++it) {
        if (it + 1 < NIT) { FILL_STAGE(it + 1); CP_WAIT(1); }
        else              { CP_WAIT(0); }
        __syncthreads();
        const uint32_t st = sb + (uint32_t)(it & 1) * STAGEB;
        #pragma unroll
        for (int ks = 0; ks < 2; ks++) {
            uint32_t th[2][4];
            ldsm4(th[0], st + TILEB + bOff + ks * 32);
            uint32_t ahf[2][4];
            #pragma unroll
            for (int mf = 0; mf < 2; mf++)
                ldsm4(ahf[mf], st + aOff + mf * (16 * 80) + ks * 32);
            #pragma unroll
            for (int nq = 0; nq < 4; nq++) {
                const int cur = nq & 1;
                if (nq < 3) {
                    ldsm4(th[cur ^ 1],
                          st + TILEB + bOff + (nq + 1) * (16 * 80) + ks * 32);
                }
                #pragma unroll
                for (int mf = 0; mf < 2; mf++) {
                    mma16816(acc[mf][2 * nq],     ahf[mf], th[cur][0], th[cur][1]);
                    mma16816(acc[mf][2 * nq + 1], ahf[mf], th[cur][2], th[cur][3]);
                }
            }
        }
        __syncthreads();
    }
    #undef FILL_STAGE
    #undef FILL_TILE
}

// ============================================================================
// Fused QKV projection (unchanged from R11, scale includes log2e)
// ============================================================================
__global__ void __launch_bounds__(256, 2)
qkv_mma(const __half* __restrict__ Xh,
        const __half* __restrict__ Wqh, const __half* __restrict__ Wkh,
        const __half* __restrict__ Wvh,
        const float* __restrict__ bq, const float* __restrict__ bk,
        const float* __restrict__ bv,
        __half* __restrict__ Qh, __half* __restrict__ Kh,
        __half* __restrict__ VTh, float scale)
{
    extern __shared__ __align__(128) unsigned char smem[];
    const uint32_t sb = smem_u32(smem);
    const int tid = threadIdx.x, lane = tid & 31, wid = tid >> 5;
    const int wm = wid & 3, wn = wid >> 2;
    const int bx = blockIdx.x, by = blockIdx.y, bz = blockIdx.z;

    const __half* Bh = (bz == 0) ? Wqh : (bz == 1) ? Wkh : Wvh;
    const float* bias = (bz == 0) ? bq : (bz == 1) ? bk : bv;
    const float alpha = (bz == 0) ? scale : 1.0f;

    const __half* pAh = Xh + (size_t)by * 128 * HID;
    const __half* pBh = Bh + (size_t)bx * 128 * HID;

    float acc[2][8][4];
    #pragma unroll
    for (int i = 0; i < 2; i++)
        #pragma unroll
        for (int j = 0; j < 8; j++)
            #pragma unroll
            for (int q = 0; q < 4; q++) acc[i][j][q] = 0.0f;

    mma_mainloop(sb, pAh, pBh, HID, HID, HID, tid, acc);

    const int mrow0 = wm * 32 + (lane >> 2);
    const int ncol0 = wn * 64 + (lane & 3) * 2;

    if (bz == 2) {
        float* tb = (float*)smem;  // [128][132]
        #pragma unroll
        for (int mf = 0; mf < 2; mf++)
            #pragma unroll
            for (int nf = 0; nf < 8; nf++) {
                const int r = mrow0 + mf * 16;
                const int c = ncol0 + nf * 8;
                tb[r * 132 + c]           = acc[mf][nf][0];
                tb[r * 132 + c + 1]       = acc[mf][nf][1];
                tb[(r + 8) * 132 + c]     = acc[mf][nf][2];
                tb[(r + 8) * 132 + c + 1] = acc[mf][nf][3];
            }
        __syncthreads();
        const int d = tid & 127, sh = tid >> 7;
        const float bvv = bias[bx * 128 + d];
        const int b = by >> 4;
        const size_t base = (((size_t)(b * HEADS + bx)) * HD + d) * SEQ
                          + (size_t)(by & 15) * 128 + sh * 64;
        #pragma unroll 8
        for (int s = 0; s < 64; s += 2) {
            float v0 = tb[(sh * 64 + s) * 132 + d] + bvv;
            float v1 = tb[(sh * 64 + s + 1) * 132 + d] + bvv;
            *(uint32_t*)(VTh + base + s) = hf2pack(v0, v1);
        }
        return;
    }

    __half* Ch = (bz == 0) ? Qh : Kh;
    #pragma unroll
    for (int mf = 0; mf < 2; mf++)
        #pragma unroll
        for (int nf = 0; nf < 8; nf++) {
            const int r = by * 128 + mrow0 + mf * 16;
            const int c = ncol0 + nf * 8;
            const float* a = acc[mf][nf];
            const int b = r >> 11, s = r & 2047;
            const float b0 = bias[bx * 128 + c], b1 = bias[bx * 128 + c + 1];
            const size_t base = (((size_t)(b * HEADS + bx)) * SEQ + s) * HD + c;
            *(uint32_t*)(Ch + base) =
                hf2pack((a[0] + b0) * alpha, (a[1] + b1) * alpha);
            *(uint32_t*)(Ch + base + (size_t)8 * HD) =
                hf2pack((a[2] + b0) * alpha, (a[3] + b1) * alpha);
        }
}

// ============================================================================
// Output projection GEMM (unchanged from R11)
// ============================================================================
__global__ void __launch_bounds__(256, 2)
gemm_out(const __half* __restrict__ Ah, const __half* __restrict__ Bh,
         float* __restrict__ Cf, const float* __restrict__ bias)
{
    extern __shared__ __align__(128) unsigned char smem[];
    const uint32_t sb = smem_u32(smem);
    const int tid = threadIdx.x, lane = tid & 31, wid = tid >> 5;
    const int wm = wid & 3, wn = wid >> 2;
    const int bx = blockIdx.x, by = blockIdx.y;

    const __half* pAh = Ah + (size_t)by * 128 * HID;
    const __half* pBh = Bh + (size_t)bx * 128 * HID;

    float acc[2][8][4];
    #pragma unroll
    for (int i = 0; i < 2; i++)
        #pragma unroll
        for (int j = 0; j < 8; j++)
            #pragma unroll
            for (int q = 0; q < 4; q++) acc[i][j][q] = 0.0f;

    mma_mainloop(sb, pAh, pBh, HID, HID, HID, tid, acc);

    const int mrow0 = wm * 32 + (lane >> 2);
    const int ncol0 = wn * 64 + (lane & 3) * 2;
    #pragma unroll
    for (int mf = 0; mf < 2; mf++)
        #pragma unroll
        for (int nf = 0; nf < 8; nf++) {
            const int r = by * 128 + mrow0 + mf * 16;
            const int c = ncol0 + nf * 8;
            const float* a = acc[mf][nf];
            const float b0 = bias[bx * 128 + c], b1 = bias[bx * 128 + c + 1];
            float* p0 = Cf + (size_t)r * HID + (size_t)bx * 128 + c;
            float2 w0; w0.x = a[0] + b0; w0.y = a[1] + b1;
            float2 w1; w1.x = a[2] + b0; w1.y = a[3] + b1;
            *(float2*)p0 = w0;
            *(float2*)(p0 + (size_t)8 * HID) = w1;
        }
}

// ============================================================================
// Fused flash attention, FA2 register-resident-P layout.
// 8 warps x (16 q-rows each, all 64 kv). Quad-local softmax reductions,
// P stays in registers as PV A-fragments, 1 syncthreads per iteration.
// Scores arrive in log2 domain (log2e folded into Q scale); P = ex2.f16x2.
// smem: Q 0..32K (2 panels), KV buf b @ 32K + b*32K: K p0 8K, K p1 8K, V 16K
// ============================================================================
constexpr int FL_KV0  = 32768;
constexpr int FL_SMEM = 98304;

__global__ void __launch_bounds__(256, 1)
flash_attn(const __half* __restrict__ Qh_, const __half* __restrict__ Kh_,
           const __half* __restrict__ Vh_, __half* __restrict__ Ah_)
{
    extern __shared__ __align__(128) unsigned char smem[];
    const uint32_t sb = smem_u32(smem);
    const int tid = threadIdx.x, lane = tid & 31, wid = tid >> 5;
    const int qt = blockIdx.x, bh = blockIdx.y;

    const size_t qoff = ((size_t)bh * SEQ + (size_t)qt * 128) * HD;
    const size_t koff = (size_t)bh * SEQ * HD;
    const size_t voff = (size_t)bh * HD * SEQ;

    {   // Q tile: 128 rows x 128 d (2 panels of 64 d)
        const int r = tid >> 1;
        const size_t gq = qoff + (size_t)r * HD;
        #pragma unroll
        for (int j = 0; j < 4; j++) {
            const uint32_t cb = (uint32_t)(tid & 1) * 64 + j * 16;
            const uint32_t off = swz((uint32_t)r * 128 + cb);
            cp_async16(sb + off,         (const char*)(Qh_ + gq)      + cb);
            cp_async16(sb + 16384 + off, (const char*)(Qh_ + gq + 64) + cb);
        }
    }

    auto fill_kv = [&](int it) {
        const uint32_t bufb = sb + FL_KV0 + (uint32_t)(it & 1) * 32768;
        {
            const int r = tid >> 2;
            const size_t gk = koff + ((size_t)it * 64 + r) * HD;
            #pragma unroll
            for (int j = 0; j < 2; j++) {
                const uint32_t cb = (uint32_t)(tid & 3) * 32 + j * 16;
                const uint32_t off = swz((uint32_t)r * 128 + cb);
                cp_async16(bufb + off,        (const char*)(Kh_ + gk)      + cb);
                cp_async16(bufb + 8192 + off, (const char*)(Kh_ + gk + 64) + cb);
            }
        }
        {
            const int r = tid >> 1;
            const size_t gv = voff + (size_t)r * SEQ + (size_t)it * 64;
            #pragma unroll
            for (int j = 0; j < 2; j++) {
                const uint32_t cb = (uint32_t)(tid & 1) * 64 + j * 32;
                const uint32_t off0 = swz((uint32_t)r * 128 + cb);
                const uint32_t off1 = swz((uint32_t)r * 128 + cb + 16);
                cp_async16(bufb + 16384 + off0, (const char*)(Vh_ + gv) + cb);
                cp_async16(bufb + 16384 + off1, (const char*)(Vh_ + gv) + cb + 16);
            }
        }
        CP_COMMIT();
    };

    fill_kv(0);

    const int nl = (lane & 7) + ((lane >> 4) & 1) * 8;
    const int kh = (lane >> 3) & 1;
    const uint32_t arow = (uint32_t)(wid * 16 + (lane & 15));   // warp's 16 q-rows
    const uint32_t acol16 = (uint32_t)(((lane >> 4) & 1) * 16);

    float O[16][4];     // 16 d-frags x c[4]; rows = arow quad rows
    #pragma unroll
    for (int j = 0; j < 16; j++)
        #pragma unroll
        for (int q = 0; q < 4; q++) O[j][q] = 0.0f;
    float mrun[2] = {-1e30f, -1e30f}, lrun[2] = {0.0f, 0.0f};

    for (int it = 0; it < SEQ / 64; ++it) {
        CP_WAIT(0);
        __syncthreads();
        if (it + 1 < SEQ / 64) fill_kv(it + 1);
        const uint32_t kb = sb + FL_KV0 + (uint32_t)(it & 1) * 32768;

        // ---- S (log2 domain) = Qs K^T : warp computes 16 q x 64 kv ----
        float S[8][4];
        #pragma unroll
        for (int nf = 0; nf < 8; nf++)
            #pragma unroll
            for (int q = 0; q < 4; q++) S[nf][q] = 0.0f;

        #pragma unroll
        for (int ks = 0; ks < 8; ++ks) {
            const uint32_t qp = sb + (uint32_t)(ks >> 2) * 16384;
            const uint32_t kp = kb + (uint32_t)(ks >> 2) * 8192;
            const uint32_t ac = acol16 + (uint32_t)(ks & 3) * 32;
            uint32_t qh[4];
            ldsm4(qh, qp + swz(arow * 128 + ac));
            uint32_t bh2[8][2];
            #pragma unroll
            for (int g = 0; g < 4; g++) {
                const uint32_t ro = (uint32_t)(nl + g * 16) * 128
                                  + kh * 16 + (ks & 3) * 32;
                uint32_t t[4];
                ldsm4(t, kp + swz(ro));
                bh2[2*g][0] = t[0]; bh2[2*g][1] = t[1];
                bh2[2*g+1][0] = t[2]; bh2[2*g+1][1] = t[3];
            }
            #pragma unroll
            for (int nf = 0; nf < 8; nf++)
                mma16816(S[nf], qh, bh2[nf][0], bh2[nf][1]);
        }

        // ---- online softmax: quad-local only ----
        float mx0 = -1e30f, mx1 = -1e30f;
        #pragma unroll
        for (int nf = 0; nf < 8; nf++) {
            mx0 = fmaxf(mx0, fmaxf(S[nf][0], S[nf][1]));
            mx1 = fmaxf(mx1, fmaxf(S[nf][2], S[nf][3]));
        }
        mx0 = fmaxf(mx0, __shfl_xor_sync(0xffffffffu, mx0, 1));
        mx0 = fmaxf(mx0, __shfl_xor_sync(0xffffffffu, mx0, 2));
        mx1 = fmaxf(mx1, __shfl_xor_sync(0xffffffffu, mx1, 1));
        mx1 = fmaxf(mx1, __shfl_xor_sync(0xffffffffu, mx1, 2));
        const float mn0 = fmaxf(mrun[0], mx0);
        const float mn1 = fmaxf(mrun[1], mx1);
        const float fac0 = exp2f(mrun[0] - mn0);
        const float fac1 = exp2f(mrun[1] - mn1);
        mrun[0] = mn0; mrun[1] = mn1;

        // P fragments (fp16x2, register-resident) + row sums
        uint32_t P[4][4];
        float rs0 = 0.0f, rs1 = 0.0f;
        #pragma unroll
        for (int ks = 0; ks < 4; ++ks) {
            #pragma unroll
            for (int j = 0; j < 2; j++) {
                const int nf = 2 * ks + j;
                const uint32_t p0 = ex2_f16x2(cvt_f16x2(S[nf][0] - mn0, S[nf][1] - mn0));
                const uint32_t p1 = ex2_f16x2(cvt_f16x2(S[nf][2] - mn1, S[nf][3] - mn1));
                P[ks][2 * j]     = p0;
                P[ks][2 * j + 1] = p1;
                rs0 += sum_f16x2(p0);
                rs1 += sum_f16x2(p1);
            }
        }
        rs0 += __shfl_xor_sync(0xffffffffu, rs0, 1);
        rs0 += __shfl_xor_sync(0xffffffffu, rs0, 2);
        rs1 += __shfl_xor_sync(0xffffffffu, rs1, 1);
        rs1 += __shfl_xor_sync(0xffffffffu, rs1, 2);
        lrun[0] = lrun[0] * fac0 + rs0;
        lrun[1] = lrun[1] * fac1 + rs1;

        #pragma unroll
        for (int nf = 0; nf < 16; nf++) {
            O[nf][0] *= fac0; O[nf][1] *= fac0;
            O[nf][2] *= fac1; O[nf][3] *= fac1;
        }

        // ---- O += P V : P in registers, V from smem ----
        #pragma unroll
        for (int ks = 0; ks < 4; ++ks) {
            uint32_t vh2[16][2];
            #pragma unroll
            for (int g = 0; g < 8; g++) {
                const uint32_t ro = (uint32_t)(nl + g * 16) * 128
                                  + kh * 16 + ks * 32;
                uint32_t t[4];
                ldsm4(t, kb + 16384 + swz(ro));
                vh2[2*g][0] = t[0]; vh2[2*g][1] = t[1];
                vh2[2*g+1][0] = t[2]; vh2[2*g+1][1] = t[3];
            }
            #pragma unroll
            for (int nf = 0; nf < 16; nf++)
                mma16816(O[nf], P[ks], vh2[nf][0], vh2[nf][1]);
        }
    }

    // ---- normalize and write (no cross-warp combine needed) ----
    const float linv0 = 1.0f / lrun[0];
    const float linv1 = 1.0f / lrun[1];
    const int b = bh >> 4, h = bh & 15;
    const int r = qt * 128 + wid * 16 + (lane >> 2);
    #pragma unroll
    for (int nf = 0; nf < 16; nf++) {
        const int c = nf * 8 + (lane & 3) * 2;
        const size_t base = ((size_t)b * SEQ + r) * HID + (size_t)h * 128 + c;
        *(uint32_t*)(Ah_ + base) = hf2pack(O[nf][0] * linv0, O[nf][1] * linv0);
        *(uint32_t*)(Ah_ + base + (size_t)8 * HID) =
            hf2pack(O[nf][2] * linv1, O[nf][3] * linv1);
    }
}

// ============================================================================
// Conversions
// ============================================================================
__global__ __launch_bounds__(256)
void conv_round_h(const float4* __restrict__ in, uint32_t* __restrict__ hi, int n4)
{
    int i = blockIdx.x * blockDim.x + threadIdx.x;
    if (i >= n4) return;
    float4 v = in[i];
    hi[2 * i]     = hf2pack(v.x, v.y);
    hi[2 * i + 1] = hf2pack(v.z, v.w);
}

__global__ __launch_bounds__(256)
void conv_round_h4(const float4* __restrict__ w0, const float4* __restrict__ w1,
                   const float4* __restrict__ w2, const float4* __restrict__ w3,
                   uint32_t* __restrict__ o0, uint32_t* __restrict__ o1,
                   uint32_t* __restrict__ o2, uint32_t* __restrict__ o3, int n4)
{
    int i = blockIdx.x * blockDim.x + threadIdx.x;
    if (i >= n4) return;
    const float4* in = (blockIdx.y == 0) ? w0 : (blockIdx.y == 1) ? w1
                     : (blockIdx.y == 2) ? w2 : w3;
    uint32_t* hi = (blockIdx.y == 0) ? o0 : (blockIdx.y == 1) ? o1
                 : (blockIdx.y == 2) ? o2 : o3;
    float4 v = in[i];
    hi[2 * i]     = hf2pack(v.x, v.y);
    hi[2 * i + 1] = hf2pack(v.z, v.w);
}

// ============================================================================
// kernel_launch
// ============================================================================
extern "C" void kernel_launch(void* const* d_in, const int* in_sizes, int n_in,
                              void* d_out, int out_size)
{
    const float* x  = (const float*)d_in[0];
    const float* Wq = (const float*)d_in[1];
    const float* bq = (const float*)d_in[2];
    const float* Wk = (const float*)d_in[3];
    const float* bk = (const float*)d_in[4];
    const float* Wv = (const float*)d_in[5];
    const float* bv = (const float*)d_in[6];
    const float* Wo = (const float*)d_in[7];
    const float* bo = (const float*)d_in[8];
    float* out = (float*)d_out;

    unsigned char* pool;
    cudaGetSymbolAddress((void**)&pool, g_pool);
    auto hfp = [&](size_t off) { return (__half*)(pool + off); };
    auto u32 = [&](size_t off) { return (uint32_t*)(pool + off); };

    cudaFuncSetAttribute(qkv_mma,    cudaFuncAttributeMaxDynamicSharedMemorySize, SMEM_BYTES);
    cudaFuncSetAttribute(gemm_out,   cudaFuncAttributeMaxDynamicSharedMemorySize, SMEM_BYTES);
    cudaFuncSetAttribute(flash_attn, cudaFuncAttributeMaxDynamicSharedMemorySize, FL_SMEM);

    // 1/sqrt(128) * log2(e): scores come out in log2 domain
    const float scale = 0.08838834764831845f * 1.44269504088896340736f;

    // 1) conversions
    conv_round_h<<<8192, 256>>>((const float4*)x, u32(OFF_XH), 2097152);
    dim3 gW(4096, 4, 1);
    conv_round_h4<<<gW, 256>>>((const float4*)Wq, (const float4*)Wk,
                               (const float4*)Wv, (const float4*)Wo,
                               u32(OFF_WQH), u32(OFF_WKH),
                               u32(OFF_WVH), u32(OFF_WOH), 1048576);

    // 2) fused QKV projections
    dim3 gQKV(16, 32, 3);
    qkv_mma<<<gQKV, 256, SMEM_BYTES>>>(
        hfp(OFF_XH),
        hfp(OFF_WQH), hfp(OFF_WKH), hfp(OFF_WVH),
        bq, bk, bv,
        hfp(OFF_QH), hfp(OFF_KH), hfp(OFF_VTH), scale);

    // 3) fused flash attention (register-resident P)
    dim3 gF(SEQ / 128, BATCH * HEADS, 1);
    flash_attn<<<gF, 256, FL_SMEM>>>(hfp(OFF_QH), hfp(OFF_KH),
                                     hfp(OFF_VTH), hfp(OFF_AH));

    // 4) output projection
    dim3 gO(16, 32, 1);
    gemm_out<<<gO, 256, SMEM_BYTES>>>(hfp(OFF_AH), hfp(OFF_WOH), out, bo);
}